// round 1
// baseline (speedup 1.0000x reference)
#include <cuda_runtime.h>
#include <cuda_bf16.h>
#include <math.h>

// Problem constants
#define BATCH 8
#define LSEQ  2048
#define DMODEL 512
#define NHEAD 8
#define NPNT  4
#define CHEAD 64   // DMODEL / NHEAD
#define MROWS (BATCH * LSEQ)   // 16384

// Scratch (device globals; no allocation allowed)
__device__ float g_v[MROWS * DMODEL];     // value projection   (B*L, 512)
__device__ float g_off[MROWS * NHEAD * NPNT * 2]; // offsets    (B*L, 64)
__device__ float g_aw[MROWS * NHEAD * NPNT];      // attn logits (B*L, 32)
__device__ float g_mid[MROWS * DMODEL];   // deform-attn output (B*L, 512)

// ---------------------------------------------------------------------------
// Generic tiled fp32 GEMM with bias: C[M,N] = A[M,K] @ B[K,N] + bias[N]
// 64x64 block tile, TK=16, 256 threads, 4x4 per-thread microtile.
// ---------------------------------------------------------------------------
#define TM 64
#define TN 64
#define TK 16

__global__ __launch_bounds__(256) void gemm_bias_kernel(
    const float* __restrict__ A, const float* __restrict__ B,
    const float* __restrict__ bias, float* __restrict__ C,
    int M, int N, int K)
{
    __shared__ float As[TK][TM + 1];   // padded: conflict-free transposed store
    __shared__ float Bs[TK][TN];

    const int tid = threadIdx.x;          // 0..255
    const int tx = tid & 15;              // 0..15 (col group)
    const int ty = tid >> 4;              // 0..15 (row group)

    const int m0 = blockIdx.y * TM;
    const int n0 = blockIdx.x * TN;

    float acc[4][4];
#pragma unroll
    for (int i = 0; i < 4; i++)
#pragma unroll
        for (int j = 0; j < 4; j++) acc[i][j] = 0.0f;

    for (int k0 = 0; k0 < K; k0 += TK) {
        // Load A tile (64 rows x 16 k) transposed into As[k][row]
#pragma unroll
        for (int e = 0; e < 4; e++) {
            int idx = tid + e * 256;       // 0..1023
            int r = idx >> 4;              // 0..63
            int c = idx & 15;              // 0..15
            As[c][r] = A[(size_t)(m0 + r) * K + (k0 + c)];
        }
        // Load B tile (16 k x 64 cols)
#pragma unroll
        for (int e = 0; e < 4; e++) {
            int idx = tid + e * 256;
            int r = idx >> 6;              // 0..15
            int c = idx & 63;              // 0..63
            int col = n0 + c;
            Bs[r][c] = (col < N) ? B[(size_t)(k0 + r) * N + col] : 0.0f;
        }
        __syncthreads();

#pragma unroll
        for (int kk = 0; kk < TK; kk++) {
            float a[4], b[4];
#pragma unroll
            for (int i = 0; i < 4; i++) a[i] = As[kk][ty * 4 + i];
#pragma unroll
            for (int j = 0; j < 4; j++) b[j] = Bs[kk][tx * 4 + j];
#pragma unroll
            for (int i = 0; i < 4; i++)
#pragma unroll
                for (int j = 0; j < 4; j++)
                    acc[i][j] = fmaf(a[i], b[j], acc[i][j]);
        }
        __syncthreads();
    }

#pragma unroll
    for (int i = 0; i < 4; i++) {
        int row = m0 + ty * 4 + i;
        if (row >= M) continue;
#pragma unroll
        for (int j = 0; j < 4; j++) {
            int col = n0 + tx * 4 + j;
            if (col < N)
                C[(size_t)row * N + col] = acc[i][j] + bias[col];
        }
    }
}

// ---------------------------------------------------------------------------
// Deformable sampling kernel. One block per (b,l). 512 threads = 8 heads x 64 ch.
// ---------------------------------------------------------------------------
__global__ __launch_bounds__(512) void deform_kernel(
    const float* __restrict__ v,      // (B*L, 512)
    const float* __restrict__ off,    // (B*L, 64)
    const float* __restrict__ awl,    // (B*L, 32)
    float* __restrict__ mid)          // (B*L, 512)
{
    __shared__ float s_w0[NHEAD][NPNT];
    __shared__ float s_w1[NHEAD][NPNT];
    __shared__ int   s_i0[NHEAD][NPNT];
    __shared__ int   s_i1[NHEAD][NPNT];

    const int blk = blockIdx.x;            // b*L + l
    const int b = blk / LSEQ;
    const int l = blk - b * LSEQ;
    const int t = threadIdx.x;

    if (t < NHEAD) {
        const int h = t;
        const float ref_y = (float)l / (float)(LSEQ - 1);

        // softmax over P=4 logits
        float lg[NPNT];
        float mx = -1e30f;
#pragma unroll
        for (int p = 0; p < NPNT; p++) {
            lg[p] = awl[(size_t)blk * (NHEAD * NPNT) + h * NPNT + p];
            mx = fmaxf(mx, lg[p]);
        }
        float sum = 0.0f;
#pragma unroll
        for (int p = 0; p < NPNT; p++) { lg[p] = __expf(lg[p] - mx); sum += lg[p]; }
        const float inv = 1.0f / sum;

#pragma unroll
        for (int p = 0; p < NPNT; p++) {
            const float a = lg[p] * inv;
            const float ox = off[(size_t)blk * 64 + (h * NPNT + p) * 2 + 0];
            const float oy = off[(size_t)blk * 64 + (h * NPNT + p) * 2 + 1];
            const float locx = fminf(fmaxf(ox, 0.0f), 1.0f);
            const float locy = fminf(fmaxf(oy + ref_y, 0.0f), 1.0f);

            const float ix = ((locx + 1.0f) * (float)LSEQ - 1.0f) * 0.5f;
            const float iy = locy * 0.5f;
            const float ix0 = floorf(ix);
            const float fx = ix - ix0;
            const float iy0 = floorf(iy);
            const float fy = iy - iy0;
            const float ywt = (1.0f - fy) * (iy0 == 0.0f ? 1.0f : 0.0f)
                            + fy * ((iy0 + 1.0f) == 0.0f ? 1.0f : 0.0f);

            const int i0 = (int)ix0;
            const int i1 = i0 + 1;
            const float w = a * ywt;
            const bool v0 = (i0 >= 0) && (i0 < LSEQ);
            const bool v1 = (i1 >= 0) && (i1 < LSEQ);
            s_w0[h][p] = v0 ? w * (1.0f - fx) : 0.0f;
            s_w1[h][p] = v1 ? w * fx : 0.0f;
            s_i0[h][p] = min(max(i0, 0), LSEQ - 1);
            s_i1[h][p] = min(max(i1, 0), LSEQ - 1);
        }
    }
    __syncthreads();

    const int h = t >> 6;       // 0..7
    const int c = t & 63;       // 0..63
    const float* vb = v + (size_t)b * LSEQ * DMODEL + h * CHEAD + c;

    float acc = 0.0f;
#pragma unroll
    for (int p = 0; p < NPNT; p++) {
        acc = fmaf(s_w0[h][p], vb[(size_t)s_i0[h][p] * DMODEL], acc);
        acc = fmaf(s_w1[h][p], vb[(size_t)s_i1[h][p] * DMODEL], acc);
    }
    mid[(size_t)blk * DMODEL + h * CHEAD + c] = acc;
}

// ---------------------------------------------------------------------------
// Host launch
// ---------------------------------------------------------------------------
extern "C" void kernel_launch(void* const* d_in, const int* in_sizes, int n_in,
                              void* d_out, int out_size)
{
    const float* query = (const float*)d_in[0];
    // d_in[1] = key_in (unused by the reference)
    const float* value = (const float*)d_in[2];
    const float* W_v   = (const float*)d_in[3];
    const float* b_v   = (const float*)d_in[4];
    const float* W_off = (const float*)d_in[5];
    const float* b_off = (const float*)d_in[6];
    const float* W_aw  = (const float*)d_in[7];
    const float* b_aw  = (const float*)d_in[8];
    const float* W_out = (const float*)d_in[9];
    const float* b_out = (const float*)d_in[10];
    float* out = (float*)d_out;

    float *pv, *poff, *paw, *pmid;
    cudaGetSymbolAddress((void**)&pv,  g_v);
    cudaGetSymbolAddress((void**)&poff, g_off);
    cudaGetSymbolAddress((void**)&paw, g_aw);
    cudaGetSymbolAddress((void**)&pmid, g_mid);

    // 1) v = value @ W_v + b_v     (16384 x 512 x 512)
    {
        dim3 grid((DMODEL + TN - 1) / TN, (MROWS + TM - 1) / TM);
        gemm_bias_kernel<<<grid, 256>>>(value, W_v, b_v, pv, MROWS, DMODEL, DMODEL);
    }
    // 2) off = query @ W_off + b_off  (16384 x 64 x 512)
    {
        dim3 grid((64 + TN - 1) / TN, (MROWS + TM - 1) / TM);
        gemm_bias_kernel<<<grid, 256>>>(query, W_off, b_off, poff, MROWS, 64, DMODEL);
    }
    // 3) aw logits = query @ W_aw + b_aw  (16384 x 32 x 512)
    {
        dim3 grid((32 + TN - 1) / TN, (MROWS + TM - 1) / TM);
        gemm_bias_kernel<<<grid, 256>>>(query, W_aw, b_aw, paw, MROWS, 32, DMODEL);
    }
    // 4) deformable sampling -> mid
    deform_kernel<<<MROWS, 512>>>(pv, poff, paw, pmid);

    // 5) out = mid @ W_out + b_out  (16384 x 512 x 512)
    {
        dim3 grid((DMODEL + TN - 1) / TN, (MROWS + TM - 1) / TM);
        gemm_bias_kernel<<<grid, 256>>>(pmid, W_out, b_out, out, MROWS, DMODEL, DMODEL);
    }
}

// round 3
// speedup vs baseline: 1.8867x; 1.8867x over previous
#include <cuda_runtime.h>
#include <cuda_bf16.h>
#include <math.h>
#include <stdint.h>

// Problem constants
#define BATCH 8
#define LSEQ  2048
#define DMODEL 512
#define NHEAD 8
#define NPNT  4
#define CHEAD 64
#define MROWS (BATCH * LSEQ)   // 16384

// Scratch (device globals; no allocation allowed)
__device__ float g_v[MROWS * DMODEL];
__device__ float g_off[MROWS * NHEAD * NPNT * 2];
__device__ float g_aw[MROWS * NHEAD * NPNT];
__device__ float g_mid[MROWS * DMODEL];

__device__ __forceinline__ uint32_t f2tf32(float x) {
    uint32_t u;
    asm("cvt.rna.tf32.f32 %0, %1;" : "=r"(u) : "f"(x));
    return u;
}

__device__ __forceinline__ void mma_tf32(float c[4],
                                         const uint32_t a[4],
                                         uint32_t b0, uint32_t b1) {
    asm volatile(
        "mma.sync.aligned.m16n8k8.row.col.f32.tf32.tf32.f32 "
        "{%0,%1,%2,%3}, {%4,%5,%6,%7}, {%8,%9}, {%0,%1,%2,%3};"
        : "+f"(c[0]), "+f"(c[1]), "+f"(c[2]), "+f"(c[3])
        : "r"(a[0]), "r"(a[1]), "r"(a[2]), "r"(a[3]), "r"(b0), "r"(b1));
}

// ===========================================================================
// tf32 mma.sync GEMM: C[M,N] = A[M,K] @ W[K,N] + bias[N]
// CTA: 128x128 tile, 256 threads (8 warps, 4 m-warps x 2 n-warps).
// K processed in chunks of 32, double-buffered SMEM, stride 36 (conflict-free
// fragment loads: bank = (4*group + tig) mod 32).
// Requires M%128==0, N%128==0, K%32==0.
// ===========================================================================
#define MM_TM 128
#define MM_TN 128
#define MM_KC 32
#define MM_STRIDE 36                          // floats per smem row
#define MM_TILE_FLOATS (128 * MM_STRIDE)      // 4608 floats = 18KB
#define MM_SMEM_FLOATS (4 * MM_TILE_FLOATS)   // A[2] + B[2]
#define MM_SMEM_BYTES (MM_SMEM_FLOATS * 4)    // 73728

__global__ __launch_bounds__(256)
void gemm_mma_kernel(const float* __restrict__ A, const float* __restrict__ W,
                     const float* __restrict__ bias, float* __restrict__ C,
                     int M, int N, int K)
{
    extern __shared__ float smem[];
    // layout: As[2][128][36], Bs[2][128][36] (Bs stored [n][k])
    float* SA[2] = { smem, smem + MM_TILE_FLOATS };
    float* SB[2] = { smem + 2 * MM_TILE_FLOATS, smem + 3 * MM_TILE_FLOATS };

    const int tid  = threadIdx.x;
    const int wid  = tid >> 5;
    const int lane = tid & 31;
    const int g    = lane >> 2;   // groupID 0..7
    const int tig  = lane & 3;    // thread-in-group 0..3

    const int wm = wid & 3;       // m-warp 0..3  (32 rows each)
    const int wn = wid >> 2;      // n-warp 0..1  (64 cols each)

    const int m0 = blockIdx.y * MM_TM;
    const int n0 = blockIdx.x * MM_TN;

    // A staging: slot i = tid + e*256; r = i>>3 (0..127), c4 = i&7 (float4 col)
    const int a_r  = tid >> 3;
    const int a_c4 = tid & 7;
    // B staging: n = tid&127 fixed; kq = tid>>7 + e*2
    const int b_n   = tid & 127;
    const int b_kq0 = tid >> 7;   // 0 or 1

    float4 ra[4];
    float  rb[4][4];

    float acc[2][8][4];
#pragma unroll
    for (int mt = 0; mt < 2; mt++)
#pragma unroll
        for (int nt = 0; nt < 8; nt++)
#pragma unroll
            for (int j = 0; j < 4; j++) acc[mt][nt][j] = 0.0f;

    const int nchunks = K / MM_KC;

    // ---- load helpers (macros keep addressing uniform) ----
#define LDG_CHUNK(k0)                                                          \
    do {                                                                       \
        _Pragma("unroll")                                                      \
        for (int e = 0; e < 4; e++) {                                          \
            const int r = a_r + e * 32;                                        \
            ra[e] = *reinterpret_cast<const float4*>(                          \
                &A[(size_t)(m0 + r) * K + (k0) + a_c4 * 4]);                   \
        }                                                                      \
        _Pragma("unroll")                                                      \
        for (int e = 0; e < 4; e++) {                                          \
            const int kq = b_kq0 + e * 2;                                      \
            _Pragma("unroll")                                                  \
            for (int j = 0; j < 4; j++)                                        \
                rb[e][j] = W[(size_t)((k0) + kq * 4 + j) * N + n0 + b_n];      \
        }                                                                      \
    } while (0)

#define STS_CHUNK(buf)                                                         \
    do {                                                                       \
        _Pragma("unroll")                                                      \
        for (int e = 0; e < 4; e++) {                                          \
            const int r = a_r + e * 32;                                        \
            float4 v = ra[e];                                                  \
            uint4 t;                                                           \
            t.x = f2tf32(v.x); t.y = f2tf32(v.y);                              \
            t.z = f2tf32(v.z); t.w = f2tf32(v.w);                              \
            *reinterpret_cast<uint4*>(&SA[buf][r * MM_STRIDE + a_c4 * 4]) = t; \
        }                                                                      \
        _Pragma("unroll")                                                      \
        for (int e = 0; e < 4; e++) {                                          \
            const int kq = b_kq0 + e * 2;                                      \
            uint4 t;                                                           \
            t.x = f2tf32(rb[e][0]); t.y = f2tf32(rb[e][1]);                    \
            t.z = f2tf32(rb[e][2]); t.w = f2tf32(rb[e][3]);                    \
            *reinterpret_cast<uint4*>(&SB[buf][b_n * MM_STRIDE + kq * 4]) = t; \
        }                                                                      \
    } while (0)

    // prologue
    LDG_CHUNK(0);
    STS_CHUNK(0);
    __syncthreads();

    for (int c = 0; c < nchunks; ++c) {
        const int s = c & 1;
        const bool more = (c + 1) < nchunks;
        if (more) LDG_CHUNK((c + 1) * MM_KC);

        // compute chunk c from buffer s
        const uint32_t* UA = reinterpret_cast<const uint32_t*>(SA[s]);
        const uint32_t* UB = reinterpret_cast<const uint32_t*>(SB[s]);
#pragma unroll
        for (int ks = 0; ks < 4; ks++) {
            const int kk = ks * 8 + tig;
            uint32_t afr[2][4];
#pragma unroll
            for (int mt = 0; mt < 2; mt++) {
                const int r = wm * 32 + mt * 16 + g;
                afr[mt][0] = UA[r * MM_STRIDE + kk];
                afr[mt][1] = UA[(r + 8) * MM_STRIDE + kk];
                afr[mt][2] = UA[r * MM_STRIDE + kk + 4];
                afr[mt][3] = UA[(r + 8) * MM_STRIDE + kk + 4];
            }
#pragma unroll
            for (int nt = 0; nt < 8; nt++) {
                const int n = wn * 64 + nt * 8 + g;
                const uint32_t b0 = UB[n * MM_STRIDE + kk];
                const uint32_t b1 = UB[n * MM_STRIDE + kk + 4];
                mma_tf32(acc[0][nt], afr[0], b0, b1);
                mma_tf32(acc[1][nt], afr[1], b0, b1);
            }
        }
        __syncthreads();
        if (more) {
            STS_CHUNK(1 - s);
            __syncthreads();
        }
    }

    // epilogue: C = acc + bias
#pragma unroll
    for (int mt = 0; mt < 2; mt++) {
        const int row0 = m0 + wm * 32 + mt * 16 + g;
#pragma unroll
        for (int nt = 0; nt < 8; nt++) {
            const int col = n0 + wn * 64 + nt * 8 + tig * 2;
            const float bx = bias[col];
            const float by = bias[col + 1];
            float2 lo, hi;
            lo.x = acc[mt][nt][0] + bx;  lo.y = acc[mt][nt][1] + by;
            hi.x = acc[mt][nt][2] + bx;  hi.y = acc[mt][nt][3] + by;
            *reinterpret_cast<float2*>(&C[(size_t)row0 * N + col]) = lo;
            *reinterpret_cast<float2*>(&C[(size_t)(row0 + 8) * N + col]) = hi;
        }
    }
#undef LDG_CHUNK
#undef STS_CHUNK
}

// ===========================================================================
// SIMT GEMM (small N=64 / N=32 projections)
// ===========================================================================
#define TM 64
#define TN 64
#define TK 16

__global__ __launch_bounds__(256) void gemm_bias_kernel(
    const float* __restrict__ A, const float* __restrict__ B,
    const float* __restrict__ bias, float* __restrict__ C,
    int M, int N, int K)
{
    __shared__ float As[TK][TM + 1];
    __shared__ float Bs[TK][TN];

    const int tid = threadIdx.x;
    const int tx = tid & 15;
    const int ty = tid >> 4;

    const int m0 = blockIdx.y * TM;
    const int n0 = blockIdx.x * TN;

    float acc[4][4];
#pragma unroll
    for (int i = 0; i < 4; i++)
#pragma unroll
        for (int j = 0; j < 4; j++) acc[i][j] = 0.0f;

    for (int k0 = 0; k0 < K; k0 += TK) {
#pragma unroll
        for (int e = 0; e < 4; e++) {
            int idx = tid + e * 256;
            int r = idx >> 4;
            int c = idx & 15;
            As[c][r] = A[(size_t)(m0 + r) * K + (k0 + c)];
        }
#pragma unroll
        for (int e = 0; e < 4; e++) {
            int idx = tid + e * 256;
            int r = idx >> 6;
            int c = idx & 63;
            int col = n0 + c;
            Bs[r][c] = (col < N) ? B[(size_t)(k0 + r) * N + col] : 0.0f;
        }
        __syncthreads();

#pragma unroll
        for (int kk = 0; kk < TK; kk++) {
            float a[4], b[4];
#pragma unroll
            for (int i = 0; i < 4; i++) a[i] = As[kk][ty * 4 + i];
#pragma unroll
            for (int j = 0; j < 4; j++) b[j] = Bs[kk][tx * 4 + j];
#pragma unroll
            for (int i = 0; i < 4; i++)
#pragma unroll
                for (int j = 0; j < 4; j++)
                    acc[i][j] = fmaf(a[i], b[j], acc[i][j]);
        }
        __syncthreads();
    }

#pragma unroll
    for (int i = 0; i < 4; i++) {
        int row = m0 + ty * 4 + i;
        if (row >= M) continue;
#pragma unroll
        for (int j = 0; j < 4; j++) {
            int col = n0 + tx * 4 + j;
            if (col < N)
                C[(size_t)row * N + col] = acc[i][j] + bias[col];
        }
    }
}

// ===========================================================================
// Deformable sampling kernel
// ===========================================================================
__global__ __launch_bounds__(512) void deform_kernel(
    const float* __restrict__ v,
    const float* __restrict__ off,
    const float* __restrict__ awl,
    float* __restrict__ mid)
{
    __shared__ float s_w0[NHEAD][NPNT];
    __shared__ float s_w1[NHEAD][NPNT];
    __shared__ int   s_i0[NHEAD][NPNT];
    __shared__ int   s_i1[NHEAD][NPNT];

    const int blk = blockIdx.x;
    const int b = blk / LSEQ;
    const int l = blk - b * LSEQ;
    const int t = threadIdx.x;

    if (t < NHEAD) {
        const int h = t;
        const float ref_y = (float)l / (float)(LSEQ - 1);

        float lg[NPNT];
        float mx = -1e30f;
#pragma unroll
        for (int p = 0; p < NPNT; p++) {
            lg[p] = awl[(size_t)blk * (NHEAD * NPNT) + h * NPNT + p];
            mx = fmaxf(mx, lg[p]);
        }
        float sum = 0.0f;
#pragma unroll
        for (int p = 0; p < NPNT; p++) { lg[p] = __expf(lg[p] - mx); sum += lg[p]; }
        const float inv = 1.0f / sum;

#pragma unroll
        for (int p = 0; p < NPNT; p++) {
            const float a = lg[p] * inv;
            const float ox = off[(size_t)blk * 64 + (h * NPNT + p) * 2 + 0];
            const float oy = off[(size_t)blk * 64 + (h * NPNT + p) * 2 + 1];
            const float locx = fminf(fmaxf(ox, 0.0f), 1.0f);
            const float locy = fminf(fmaxf(oy + ref_y, 0.0f), 1.0f);

            const float ix = ((locx + 1.0f) * (float)LSEQ - 1.0f) * 0.5f;
            const float iy = locy * 0.5f;
            const float ix0 = floorf(ix);
            const float fx = ix - ix0;
            const float iy0 = floorf(iy);
            const float fy = iy - iy0;
            const float ywt = (1.0f - fy) * (iy0 == 0.0f ? 1.0f : 0.0f)
                            + fy * ((iy0 + 1.0f) == 0.0f ? 1.0f : 0.0f);

            const int i0 = (int)ix0;
            const int i1 = i0 + 1;
            const float w = a * ywt;
            const bool v0 = (i0 >= 0) && (i0 < LSEQ);
            const bool v1 = (i1 >= 0) && (i1 < LSEQ);
            s_w0[h][p] = v0 ? w * (1.0f - fx) : 0.0f;
            s_w1[h][p] = v1 ? w * fx : 0.0f;
            s_i0[h][p] = min(max(i0, 0), LSEQ - 1);
            s_i1[h][p] = min(max(i1, 0), LSEQ - 1);
        }
    }
    __syncthreads();

    const int h = t >> 6;
    const int c = t & 63;
    const float* vb = v + (size_t)b * LSEQ * DMODEL + h * CHEAD + c;

    float acc = 0.0f;
#pragma unroll
    for (int p = 0; p < NPNT; p++) {
        acc = fmaf(s_w0[h][p], vb[(size_t)s_i0[h][p] * DMODEL], acc);
        acc = fmaf(s_w1[h][p], vb[(size_t)s_i1[h][p] * DMODEL], acc);
    }
    mid[(size_t)blk * DMODEL + h * CHEAD + c] = acc;
}

// ===========================================================================
// Host launch
// ===========================================================================
extern "C" void kernel_launch(void* const* d_in, const int* in_sizes, int n_in,
                              void* d_out, int out_size)
{
    const float* query = (const float*)d_in[0];
    const float* value = (const float*)d_in[2];
    const float* W_v   = (const float*)d_in[3];
    const float* b_v   = (const float*)d_in[4];
    const float* W_off = (const float*)d_in[5];
    const float* b_off = (const float*)d_in[6];
    const float* W_aw  = (const float*)d_in[7];
    const float* b_aw  = (const float*)d_in[8];
    const float* W_out = (const float*)d_in[9];
    const float* b_out = (const float*)d_in[10];
    float* out = (float*)d_out;

    float *pv, *poff, *paw, *pmid;
    cudaGetSymbolAddress((void**)&pv,  g_v);
    cudaGetSymbolAddress((void**)&poff, g_off);
    cudaGetSymbolAddress((void**)&paw, g_aw);
    cudaGetSymbolAddress((void**)&pmid, g_mid);

    cudaFuncSetAttribute(gemm_mma_kernel,
                         cudaFuncAttributeMaxDynamicSharedMemorySize, MM_SMEM_BYTES);

    // 1) v = value @ W_v + b_v  (tensor mma, tf32)
    {
        dim3 grid(DMODEL / MM_TN, MROWS / MM_TM);
        gemm_mma_kernel<<<grid, 256, MM_SMEM_BYTES>>>(value, W_v, b_v, pv,
                                                      MROWS, DMODEL, DMODEL);
    }
    // 2) off = query @ W_off + b_off  (16384 x 64 x 512, SIMT)
    {
        dim3 grid(1, MROWS / TM);
        gemm_bias_kernel<<<grid, 256>>>(query, W_off, b_off, poff, MROWS, 64, DMODEL);
    }
    // 3) aw logits = query @ W_aw + b_aw  (16384 x 32 x 512, SIMT)
    {
        dim3 grid(1, MROWS / TM);
        gemm_bias_kernel<<<grid, 256>>>(query, W_aw, b_aw, paw, MROWS, 32, DMODEL);
    }
    // 4) deformable sampling -> mid
    deform_kernel<<<MROWS, 512>>>(pv, poff, paw, pmid);

    // 5) out = mid @ W_out + b_out  (tensor mma, tf32)
    {
        dim3 grid(DMODEL / MM_TN, MROWS / MM_TM);
        gemm_mma_kernel<<<grid, 256, MM_SMEM_BYTES>>>(pmid, W_out, b_out, out,
                                                      MROWS, DMODEL, DMODEL);
    }
}

// round 5
// speedup vs baseline: 2.4645x; 1.3062x over previous
#include <cuda_runtime.h>
#include <cuda_bf16.h>
#include <math.h>
#include <stdint.h>

// Problem constants
#define BATCH 8
#define LSEQ  2048
#define DMODEL 512
#define NHEAD 8
#define NPNT  4
#define CHEAD 64
#define MROWS (BATCH * LSEQ)   // 16384

// Scratch (device globals; no allocation allowed)
__device__ __align__(16) float g_v[MROWS * DMODEL];       // value projection (fp32)
__device__ __align__(16) float g_va[MROWS * DMODEL];      // value, tf32-rounded
__device__ __align__(16) float g_mid[MROWS * DMODEL];     // deform output, tf32-rounded
__device__ __align__(16) float g_off[MROWS * 64];         // offsets (fp32!)
__device__ __align__(16) float g_aw[MROWS * 32];          // attn logits (fp32!)
__device__ __align__(16) float g_wvt[DMODEL * DMODEL];    // W_v^T, tf32-rounded
__device__ __align__(16) float g_wot[DMODEL * DMODEL];    // W_out^T, tf32-rounded

__device__ __forceinline__ uint32_t f2tf32(float x) {
    uint32_t u;
    asm("cvt.rna.tf32.f32 %0, %1;" : "=r"(u) : "f"(x));
    return u;
}

__device__ __forceinline__ uint32_t smem_u32(const void* p) {
    uint32_t a;
    asm("{ .reg .u64 t; cvta.to.shared.u64 t, %1; cvt.u32.u64 %0, t; }" : "=r"(a) : "l"(p));
    return a;
}

__device__ __forceinline__ void mma_tf32(float c[4],
                                         const uint32_t a[4],
                                         uint32_t b0, uint32_t b1) {
    asm volatile(
        "mma.sync.aligned.m16n8k8.row.col.f32.tf32.tf32.f32 "
        "{%0,%1,%2,%3}, {%4,%5,%6,%7}, {%8,%9}, {%0,%1,%2,%3};"
        : "+f"(c[0]), "+f"(c[1]), "+f"(c[2]), "+f"(c[3])
        : "r"(a[0]), "r"(a[1]), "r"(a[2]), "r"(a[3]), "r"(b0), "r"(b1));
}

#define CP_ASYNC16(dst, src) \
    asm volatile("cp.async.cg.shared.global [%0], [%1], 16;" :: "r"(dst), "l"(src) : "memory")
#define CP_COMMIT() asm volatile("cp.async.commit_group;" ::: "memory")
#define CP_WAIT1()  asm volatile("cp.async.wait_group 1;" ::: "memory")

// ===========================================================================
// Async tf32 GEMM: C[M,N] = A[M,K] @ Bt[N,K]^T + bias[N]
// A, Bt already tf32-rounded, K-contiguous. 128x128 tile, 256 thr, 3 stages.
// ===========================================================================
#define AG_KC 32
#define AG_TILE 16384
#define AG_STAGE (2 * AG_TILE)
#define AG_STAGES 3
#define AG_SMEM (AG_STAGES * AG_STAGE) // 96KB

__global__ __launch_bounds__(256, 2)
void gemm_async_kernel(const float* __restrict__ A, const float* __restrict__ Bt,
                       const float* __restrict__ bias, float* __restrict__ C,
                       int M, int N, int K)
{
    extern __shared__ char smem[];
    const uint32_t sbase = smem_u32(smem);

    const int tid  = threadIdx.x;
    const int wid  = tid >> 5;
    const int lane = tid & 31;
    const int g    = lane >> 2;
    const int tig  = lane & 3;
    const int wm   = wid & 3;
    const int wn   = wid >> 2;

    const int m0 = blockIdx.y * 128;
    const int n0 = blockIdx.x * 128;

    const int cp_r0 = tid >> 3;
    const int cp_c4 = tid & 7;

    float acc[2][8][4];
#pragma unroll
    for (int mt = 0; mt < 2; mt++)
#pragma unroll
        for (int nt = 0; nt < 8; nt++)
#pragma unroll
            for (int j = 0; j < 4; j++) acc[mt][nt][j] = 0.0f;

    const int nch = K / AG_KC;

#define COPY_STAGE(s, chunk)                                                   \
    do {                                                                       \
        const int _k0 = (chunk) * AG_KC;                                       \
        const uint32_t _dA = sbase + (s) * AG_STAGE;                           \
        const uint32_t _dB = _dA + AG_TILE;                                    \
        _Pragma("unroll")                                                      \
        for (int e = 0; e < 4; e++) {                                          \
            const int r = cp_r0 + e * 32;                                      \
            const uint32_t sw = (uint32_t)((cp_c4 ^ (r & 7)) << 4);            \
            CP_ASYNC16(_dA + r * 128 + sw,                                     \
                       &A[(size_t)(m0 + r) * K + _k0 + cp_c4 * 4]);            \
            CP_ASYNC16(_dB + r * 128 + sw,                                     \
                       &Bt[(size_t)(n0 + r) * K + _k0 + cp_c4 * 4]);           \
        }                                                                      \
    } while (0)

    COPY_STAGE(0, 0); CP_COMMIT();
    COPY_STAGE(1, 1); CP_COMMIT();

    for (int c = 0; c < nch; ++c) {
        CP_WAIT1();
        __syncthreads();

        if (c + 2 < nch) {
            COPY_STAGE((c + 2) % AG_STAGES, c + 2);
        }
        CP_COMMIT();

        const int s = c % AG_STAGES;
        const uint32_t* SA = reinterpret_cast<const uint32_t*>(smem + s * AG_STAGE);
        const uint32_t* SB = reinterpret_cast<const uint32_t*>(smem + s * AG_STAGE + AG_TILE);

#pragma unroll
        for (int ks = 0; ks < 4; ks++) {
            const int c4  = 2 * ks;
            const int x0  = ((c4 ^ g) << 2) + tig;
            const int x1  = (((c4 + 1) ^ g) << 2) + tig;

            uint32_t afr[2][4];
#pragma unroll
            for (int mt = 0; mt < 2; mt++) {
                const int r = wm * 32 + mt * 16 + g;
                afr[mt][0] = SA[r * 32 + x0];
                afr[mt][1] = SA[(r + 8) * 32 + x0];
                afr[mt][2] = SA[r * 32 + x1];
                afr[mt][3] = SA[(r + 8) * 32 + x1];
            }
#pragma unroll
            for (int nt = 0; nt < 8; nt++) {
                const int n = wn * 64 + nt * 8 + g;
                const uint32_t b0 = SB[n * 32 + x0];
                const uint32_t b1 = SB[n * 32 + x1];
                mma_tf32(acc[0][nt], afr[0], b0, b1);
                mma_tf32(acc[1][nt], afr[1], b0, b1);
            }
        }
        __syncthreads();
    }
#undef COPY_STAGE

#pragma unroll
    for (int mt = 0; mt < 2; mt++) {
        const int row0 = m0 + wm * 32 + mt * 16 + g;
#pragma unroll
        for (int nt = 0; nt < 8; nt++) {
            const int col = n0 + wn * 64 + nt * 8 + tig * 2;
            const float bx = bias[col];
            const float by = bias[col + 1];
            float2 lo, hi;
            lo.x = acc[mt][nt][0] + bx;  lo.y = acc[mt][nt][1] + by;
            hi.x = acc[mt][nt][2] + bx;  hi.y = acc[mt][nt][3] + by;
            *reinterpret_cast<float2*>(&C[(size_t)row0 * N + col]) = lo;
            *reinterpret_cast<float2*>(&C[(size_t)(row0 + 8) * N + col]) = hi;
        }
    }
}

// ===========================================================================
// SIMT fp32 GEMM with guards — offset/attn-weight projections (precision-
// critical: coordinate error is amplified x1024 by the sampling grid).
// ===========================================================================
#define TM 64
#define TN 64
#define TK 16

__global__ __launch_bounds__(256) void gemm_bias_kernel(
    const float* __restrict__ A, const float* __restrict__ B,
    const float* __restrict__ bias, float* __restrict__ C,
    int M, int N, int K)
{
    __shared__ float As[TK][TM + 1];
    __shared__ float Bs[TK][TN];

    const int tid = threadIdx.x;
    const int tx = tid & 15;
    const int ty = tid >> 4;

    const int m0 = blockIdx.y * TM;
    const int n0 = blockIdx.x * TN;

    float acc[4][4];
#pragma unroll
    for (int i = 0; i < 4; i++)
#pragma unroll
        for (int j = 0; j < 4; j++) acc[i][j] = 0.0f;

    for (int k0 = 0; k0 < K; k0 += TK) {
#pragma unroll
        for (int e = 0; e < 4; e++) {
            int idx = tid + e * 256;
            int r = idx >> 4;
            int c = idx & 15;
            As[c][r] = A[(size_t)(m0 + r) * K + (k0 + c)];
        }
#pragma unroll
        for (int e = 0; e < 4; e++) {
            int idx = tid + e * 256;
            int r = idx >> 6;
            int c = idx & 63;
            int col = n0 + c;
            Bs[r][c] = (col < N) ? B[(size_t)(k0 + r) * N + col] : 0.0f;
        }
        __syncthreads();

#pragma unroll
        for (int kk = 0; kk < TK; kk++) {
            float a[4], b[4];
#pragma unroll
            for (int i = 0; i < 4; i++) a[i] = As[kk][ty * 4 + i];
#pragma unroll
            for (int j = 0; j < 4; j++) b[j] = Bs[kk][tx * 4 + j];
#pragma unroll
            for (int i = 0; i < 4; i++)
#pragma unroll
                for (int j = 0; j < 4; j++)
                    acc[i][j] = fmaf(a[i], b[j], acc[i][j]);
        }
        __syncthreads();
    }

#pragma unroll
    for (int i = 0; i < 4; i++) {
        int row = m0 + ty * 4 + i;
        if (row >= M) continue;
#pragma unroll
        for (int j = 0; j < 4; j++) {
            int col = n0 + tx * 4 + j;
            if (col < N)
                C[(size_t)row * N + col] = acc[i][j] + bias[col];
        }
    }
}

// ===========================================================================
// Prep kernels
// ===========================================================================
__global__ void transpose_rna_kernel(const float* __restrict__ in,
                                     float* __restrict__ out, int R, int C)
{
    __shared__ float tile[32][33];
    const int bx = blockIdx.x * 32;
    const int by = blockIdx.y * 32;
#pragma unroll
    for (int j = 0; j < 32; j += 8)
        tile[threadIdx.y + j][threadIdx.x] =
            in[(size_t)(by + threadIdx.y + j) * C + bx + threadIdx.x];
    __syncthreads();
#pragma unroll
    for (int j = 0; j < 32; j += 8)
        out[(size_t)(bx + threadIdx.y + j) * R + by + threadIdx.x] =
            __uint_as_float(f2tf32(tile[threadIdx.x][threadIdx.y + j]));
}

__global__ void convert_rna_kernel(const float4* __restrict__ in,
                                   uint4* __restrict__ out, int n4)
{
    const int i = blockIdx.x * 256 + threadIdx.x;
    if (i < n4) {
        float4 v = in[i];
        uint4 t;
        t.x = f2tf32(v.x); t.y = f2tf32(v.y);
        t.z = f2tf32(v.z); t.w = f2tf32(v.w);
        out[i] = t;
    }
}

// ===========================================================================
// Deformable sampling: 256 threads, float2 per thread; writes tf32-rounded mid.
// ===========================================================================
__global__ __launch_bounds__(256) void deform_kernel(
    const float* __restrict__ v,
    const float* __restrict__ off,
    const float* __restrict__ awl,
    float* __restrict__ mid)
{
    __shared__ float s_w0[NHEAD][NPNT];
    __shared__ float s_w1[NHEAD][NPNT];
    __shared__ int   s_i0[NHEAD][NPNT];
    __shared__ int   s_i1[NHEAD][NPNT];

    const int blk = blockIdx.x;
    const int b = blk / LSEQ;
    const int l = blk - b * LSEQ;
    const int t = threadIdx.x;

    if (t < NHEAD) {
        const int h = t;
        const float ref_y = (float)l / (float)(LSEQ - 1);

        float lg[NPNT];
        float mx = -1e30f;
#pragma unroll
        for (int p = 0; p < NPNT; p++) {
            lg[p] = awl[(size_t)blk * 32 + h * NPNT + p];
            mx = fmaxf(mx, lg[p]);
        }
        float sum = 0.0f;
#pragma unroll
        for (int p = 0; p < NPNT; p++) { lg[p] = __expf(lg[p] - mx); sum += lg[p]; }
        const float inv = 1.0f / sum;

#pragma unroll
        for (int p = 0; p < NPNT; p++) {
            const float a = lg[p] * inv;
            const float ox = off[(size_t)blk * 64 + (h * NPNT + p) * 2 + 0];
            const float oy = off[(size_t)blk * 64 + (h * NPNT + p) * 2 + 1];
            const float locx = fminf(fmaxf(ox, 0.0f), 1.0f);
            const float locy = fminf(fmaxf(oy + ref_y, 0.0f), 1.0f);

            const float ix = ((locx + 1.0f) * (float)LSEQ - 1.0f) * 0.5f;
            const float iy = locy * 0.5f;
            const float ix0 = floorf(ix);
            const float fx = ix - ix0;
            const float iy0 = floorf(iy);
            const float fy = iy - iy0;
            const float ywt = (1.0f - fy) * (iy0 == 0.0f ? 1.0f : 0.0f)
                            + fy * ((iy0 + 1.0f) == 0.0f ? 1.0f : 0.0f);

            const int i0 = (int)ix0;
            const int i1 = i0 + 1;
            const float w = a * ywt;
            const bool v0 = (i0 >= 0) && (i0 < LSEQ);
            const bool v1 = (i1 >= 0) && (i1 < LSEQ);
            s_w0[h][p] = v0 ? w * (1.0f - fx) : 0.0f;
            s_w1[h][p] = v1 ? w * fx : 0.0f;
            s_i0[h][p] = min(max(i0, 0), LSEQ - 1);
            s_i1[h][p] = min(max(i1, 0), LSEQ - 1);
        }
    }
    __syncthreads();

    const int h  = t >> 5;
    const int c2 = t & 31;
    const float2* vb = reinterpret_cast<const float2*>(
        v + (size_t)b * LSEQ * DMODEL + h * CHEAD) + c2;

    float ax = 0.0f, ay = 0.0f;
#pragma unroll
    for (int p = 0; p < NPNT; p++) {
        const float w0 = s_w0[h][p];
        const float w1 = s_w1[h][p];
        const float2 x0 = vb[(size_t)s_i0[h][p] * (DMODEL / 2)];
        const float2 x1 = vb[(size_t)s_i1[h][p] * (DMODEL / 2)];
        ax = fmaf(w0, x0.x, ax); ay = fmaf(w0, x0.y, ay);
        ax = fmaf(w1, x1.x, ax); ay = fmaf(w1, x1.y, ay);
    }
    uint2 o;
    o.x = f2tf32(ax);
    o.y = f2tf32(ay);
    *reinterpret_cast<uint2*>(&mid[(size_t)blk * DMODEL + h * CHEAD + c2 * 2]) = o;
}

// ===========================================================================
// Host launch
// ===========================================================================
extern "C" void kernel_launch(void* const* d_in, const int* in_sizes, int n_in,
                              void* d_out, int out_size)
{
    const float* query = (const float*)d_in[0];
    const float* value = (const float*)d_in[2];
    const float* W_v   = (const float*)d_in[3];
    const float* b_v   = (const float*)d_in[4];
    const float* W_off = (const float*)d_in[5];
    const float* b_off = (const float*)d_in[6];
    const float* W_aw  = (const float*)d_in[7];
    const float* b_aw  = (const float*)d_in[8];
    const float* W_out = (const float*)d_in[9];
    const float* b_out = (const float*)d_in[10];
    float* out = (float*)d_out;

    float *pv, *pva, *pmid, *poff, *paw, *pwvt, *pwot;
    cudaGetSymbolAddress((void**)&pv,   g_v);
    cudaGetSymbolAddress((void**)&pva,  g_va);
    cudaGetSymbolAddress((void**)&pmid, g_mid);
    cudaGetSymbolAddress((void**)&poff, g_off);
    cudaGetSymbolAddress((void**)&paw,  g_aw);
    cudaGetSymbolAddress((void**)&pwvt, g_wvt);
    cudaGetSymbolAddress((void**)&pwot, g_wot);

    cudaFuncSetAttribute(gemm_async_kernel,
                         cudaFuncAttributeMaxDynamicSharedMemorySize, AG_SMEM);

    // --- prep: transpose+round weights, round value ---
    {
        dim3 tb(32, 8);
        dim3 tg(DMODEL / 32, DMODEL / 32);
        transpose_rna_kernel<<<tg, tb>>>(W_v,   pwvt, DMODEL, DMODEL);
        transpose_rna_kernel<<<tg, tb>>>(W_out, pwot, DMODEL, DMODEL);
    }
    convert_rna_kernel<<<(MROWS * DMODEL / 4 + 255) / 256, 256>>>(
        (const float4*)value, (uint4*)pva, MROWS * DMODEL / 4);

    // --- off/aw projections: fp32 SIMT (precision-critical path) ---
    {
        dim3 grid(1, MROWS / TM);
        gemm_bias_kernel<<<grid, 256>>>(query, W_off, b_off, poff, MROWS, 64, DMODEL);
        gemm_bias_kernel<<<grid, 256>>>(query, W_aw, b_aw, paw, MROWS, 32, DMODEL);
    }
    // --- v = value @ W_v + b_v (async tf32) ---
    {
        dim3 grid(DMODEL / 128, MROWS / 128);
        gemm_async_kernel<<<grid, 256, AG_SMEM>>>(pva, pwvt, b_v, pv,
                                                  MROWS, DMODEL, DMODEL);
    }
    // --- deformable sampling -> mid (tf32-rounded) ---
    deform_kernel<<<MROWS, 256>>>(pv, poff, paw, pmid);

    // --- out = mid @ W_out + b_out (async tf32) ---
    {
        dim3 grid(DMODEL / 128, MROWS / 128);
        gemm_async_kernel<<<grid, 256, AG_SMEM>>>(pmid, pwot, b_out, out,
                                                  MROWS, DMODEL, DMODEL);
    }
}

// round 6
// speedup vs baseline: 2.9464x; 1.1955x over previous
#include <cuda_runtime.h>
#include <cuda_bf16.h>
#include <math.h>
#include <stdint.h>

// Problem constants
#define BATCH 8
#define LSEQ  2048
#define DMODEL 512
#define NHEAD 8
#define NPNT  4
#define CHEAD 64
#define MROWS (BATCH * LSEQ)   // 16384

// Scratch (device globals; no allocation allowed)
__device__ __align__(16) float g_v[MROWS * DMODEL];       // value projection (fp32)
__device__ __align__(16) float g_va[MROWS * DMODEL];      // value, tf32-rounded
__device__ __align__(16) float g_mid[MROWS * DMODEL];     // deform output, tf32-rounded
__device__ __align__(16) float g_offaw[MROWS * 96];       // fused off(64)|aw(32), fp32
__device__ __align__(16) float g_wvt[DMODEL * DMODEL];    // W_v^T, tf32-rounded
__device__ __align__(16) float g_wot[DMODEL * DMODEL];    // W_out^T, tf32-rounded
__device__ __align__(16) float g_wq[DMODEL * 96];         // combined [K][96] W_off|W_aw
__device__ __align__(16) float g_bq[96];

// Streams/events for fork-join overlap (created once at module load; no
// device-memory allocation involved).
static cudaStream_t g_s1;
static cudaEvent_t g_ev0, g_ev1;
namespace {
struct StreamInit {
    StreamInit() {
        cudaStreamCreateWithFlags(&g_s1, cudaStreamNonBlocking);
        cudaEventCreateWithFlags(&g_ev0, cudaEventDisableTiming);
        cudaEventCreateWithFlags(&g_ev1, cudaEventDisableTiming);
    }
};
StreamInit g_stream_init;
}

__device__ __forceinline__ uint32_t f2tf32(float x) {
    uint32_t u;
    asm("cvt.rna.tf32.f32 %0, %1;" : "=r"(u) : "f"(x));
    return u;
}

__device__ __forceinline__ uint32_t smem_u32(const void* p) {
    uint32_t a;
    asm("{ .reg .u64 t; cvta.to.shared.u64 t, %1; cvt.u32.u64 %0, t; }" : "=r"(a) : "l"(p));
    return a;
}

__device__ __forceinline__ void mma_tf32(float c[4],
                                         const uint32_t a[4],
                                         uint32_t b0, uint32_t b1) {
    asm volatile(
        "mma.sync.aligned.m16n8k8.row.col.f32.tf32.tf32.f32 "
        "{%0,%1,%2,%3}, {%4,%5,%6,%7}, {%8,%9}, {%0,%1,%2,%3};"
        : "+f"(c[0]), "+f"(c[1]), "+f"(c[2]), "+f"(c[3])
        : "r"(a[0]), "r"(a[1]), "r"(a[2]), "r"(a[3]), "r"(b0), "r"(b1));
}

#define CP_ASYNC16(dst, src) \
    asm volatile("cp.async.cg.shared.global [%0], [%1], 16;" :: "r"(dst), "l"(src) : "memory")
#define CP_COMMIT() asm volatile("cp.async.commit_group;" ::: "memory")
#define CP_WAIT1()  asm volatile("cp.async.wait_group 1;" ::: "memory")

// ===========================================================================
// Async tf32 GEMM: C[M,N] = A[M,K] @ Bt[N,K]^T + bias[N]
// ===========================================================================
#define AG_KC 32
#define AG_TILE 16384
#define AG_STAGE (2 * AG_TILE)
#define AG_STAGES 3
#define AG_SMEM (AG_STAGES * AG_STAGE) // 96KB

__global__ __launch_bounds__(256, 2)
void gemm_async_kernel(const float* __restrict__ A, const float* __restrict__ Bt,
                       const float* __restrict__ bias, float* __restrict__ C,
                       int M, int N, int K)
{
    extern __shared__ char smem[];
    const uint32_t sbase = smem_u32(smem);

    const int tid  = threadIdx.x;
    const int wid  = tid >> 5;
    const int lane = tid & 31;
    const int g    = lane >> 2;
    const int tig  = lane & 3;
    const int wm   = wid & 3;
    const int wn   = wid >> 2;

    const int m0 = blockIdx.y * 128;
    const int n0 = blockIdx.x * 128;

    const int cp_r0 = tid >> 3;
    const int cp_c4 = tid & 7;

    float acc[2][8][4];
#pragma unroll
    for (int mt = 0; mt < 2; mt++)
#pragma unroll
        for (int nt = 0; nt < 8; nt++)
#pragma unroll
            for (int j = 0; j < 4; j++) acc[mt][nt][j] = 0.0f;

    const int nch = K / AG_KC;

#define COPY_STAGE(s, chunk)                                                   \
    do {                                                                       \
        const int _k0 = (chunk) * AG_KC;                                       \
        const uint32_t _dA = sbase + (s) * AG_STAGE;                           \
        const uint32_t _dB = _dA + AG_TILE;                                    \
        _Pragma("unroll")                                                      \
        for (int e = 0; e < 4; e++) {                                          \
            const int r = cp_r0 + e * 32;                                      \
            const uint32_t sw = (uint32_t)((cp_c4 ^ (r & 7)) << 4);            \
            CP_ASYNC16(_dA + r * 128 + sw,                                     \
                       &A[(size_t)(m0 + r) * K + _k0 + cp_c4 * 4]);            \
            CP_ASYNC16(_dB + r * 128 + sw,                                     \
                       &Bt[(size_t)(n0 + r) * K + _k0 + cp_c4 * 4]);           \
        }                                                                      \
    } while (0)

    COPY_STAGE(0, 0); CP_COMMIT();
    COPY_STAGE(1, 1); CP_COMMIT();

    for (int c = 0; c < nch; ++c) {
        CP_WAIT1();
        __syncthreads();

        if (c + 2 < nch) {
            COPY_STAGE((c + 2) % AG_STAGES, c + 2);
        }
        CP_COMMIT();

        const int s = c % AG_STAGES;
        const uint32_t* SA = reinterpret_cast<const uint32_t*>(smem + s * AG_STAGE);
        const uint32_t* SB = reinterpret_cast<const uint32_t*>(smem + s * AG_STAGE + AG_TILE);

#pragma unroll
        for (int ks = 0; ks < 4; ks++) {
            const int c4  = 2 * ks;
            const int x0  = ((c4 ^ g) << 2) + tig;
            const int x1  = (((c4 + 1) ^ g) << 2) + tig;

            uint32_t afr[2][4];
#pragma unroll
            for (int mt = 0; mt < 2; mt++) {
                const int r = wm * 32 + mt * 16 + g;
                afr[mt][0] = SA[r * 32 + x0];
                afr[mt][1] = SA[(r + 8) * 32 + x0];
                afr[mt][2] = SA[r * 32 + x1];
                afr[mt][3] = SA[(r + 8) * 32 + x1];
            }
#pragma unroll
            for (int nt = 0; nt < 8; nt++) {
                const int n = wn * 64 + nt * 8 + g;
                const uint32_t b0 = SB[n * 32 + x0];
                const uint32_t b1 = SB[n * 32 + x1];
                mma_tf32(acc[0][nt], afr[0], b0, b1);
                mma_tf32(acc[1][nt], afr[1], b0, b1);
            }
        }
        __syncthreads();
    }
#undef COPY_STAGE

#pragma unroll
    for (int mt = 0; mt < 2; mt++) {
        const int row0 = m0 + wm * 32 + mt * 16 + g;
#pragma unroll
        for (int nt = 0; nt < 8; nt++) {
            const int col = n0 + wn * 64 + nt * 8 + tig * 2;
            const float bx = bias[col];
            const float by = bias[col + 1];
            float2 lo, hi;
            lo.x = acc[mt][nt][0] + bx;  lo.y = acc[mt][nt][1] + by;
            hi.x = acc[mt][nt][2] + bx;  hi.y = acc[mt][nt][3] + by;
            *reinterpret_cast<float2*>(&C[(size_t)row0 * N + col]) = lo;
            *reinterpret_cast<float2*>(&C[(size_t)(row0 + 8) * N + col]) = hi;
        }
    }
}

// ===========================================================================
// Fused fp32 SIMT GEMM for off|aw: C[M,96] = A[M,512] @ Wq[512,96] + bq
// 64x96 tile, 384 threads, 4x4 per-thread microtile. Precision-critical path.
// ===========================================================================
#define FQ_TK 16

__global__ __launch_bounds__(384) void gemm_offaw_kernel(
    const float* __restrict__ A, const float* __restrict__ Wq,
    const float* __restrict__ bq, float* __restrict__ C, int M, int K)
{
    __shared__ float As[FQ_TK][68];   // 64 + pad4 (16B-aligned rows)
    __shared__ float Bs[FQ_TK][96];

    const int tid = threadIdx.x;      // 0..383
    const int ty = tid / 24;          // 0..15 (4 rows each)
    const int tx = tid % 24;          // 0..23 (4 cols each)

    const int m0 = blockIdx.x * 64;

    float acc[4][4];
#pragma unroll
    for (int i = 0; i < 4; i++)
#pragma unroll
        for (int j = 0; j < 4; j++) acc[i][j] = 0.0f;

    for (int k0 = 0; k0 < K; k0 += FQ_TK) {
        // A tile: 64 rows x 16 k, store transposed As[k][r]
#pragma unroll
        for (int e = 0; e < 3; e++) {
            const int idx = tid + e * 384;
            if (idx < 1024) {
                const int r = idx >> 4;
                const int c = idx & 15;
                As[c][r] = A[(size_t)(m0 + r) * K + k0 + c];
            }
        }
        // B tile: 16 k x 96 n
#pragma unroll
        for (int e = 0; e < 4; e++) {
            const int idx = tid + e * 384;
            const int r = idx / 96;
            const int c = idx % 96;
            Bs[r][c] = Wq[(size_t)(k0 + r) * 96 + c];
        }
        __syncthreads();

#pragma unroll
        for (int kk = 0; kk < FQ_TK; kk++) {
            float a[4], b[4];
#pragma unroll
            for (int i = 0; i < 4; i++) a[i] = As[kk][ty * 4 + i];
#pragma unroll
            for (int j = 0; j < 4; j++) b[j] = Bs[kk][tx * 4 + j];
#pragma unroll
            for (int i = 0; i < 4; i++)
#pragma unroll
                for (int j = 0; j < 4; j++)
                    acc[i][j] = fmaf(a[i], b[j], acc[i][j]);
        }
        __syncthreads();
    }

#pragma unroll
    for (int i = 0; i < 4; i++) {
        const int row = m0 + ty * 4 + i;
#pragma unroll
        for (int j = 0; j < 4; j++) {
            const int col = tx * 4 + j;
            C[(size_t)row * 96 + col] = acc[i][j] + bq[col];
        }
    }
}

// ===========================================================================
// Prep kernels
// ===========================================================================
__global__ void transpose_rna_kernel(const float* __restrict__ in,
                                     float* __restrict__ out, int R, int C)
{
    __shared__ float tile[32][33];
    const int bx = blockIdx.x * 32;
    const int by = blockIdx.y * 32;
#pragma unroll
    for (int j = 0; j < 32; j += 8)
        tile[threadIdx.y + j][threadIdx.x] =
            in[(size_t)(by + threadIdx.y + j) * C + bx + threadIdx.x];
    __syncthreads();
#pragma unroll
    for (int j = 0; j < 32; j += 8)
        out[(size_t)(bx + threadIdx.y + j) * R + by + threadIdx.x] =
            __uint_as_float(f2tf32(tile[threadIdx.x][threadIdx.y + j]));
}

__global__ void convert_rna_kernel(const float4* __restrict__ in,
                                   uint4* __restrict__ out, int n4)
{
    const int i = blockIdx.x * 256 + threadIdx.x;
    if (i < n4) {
        float4 v = in[i];
        uint4 t;
        t.x = f2tf32(v.x); t.y = f2tf32(v.y);
        t.z = f2tf32(v.z); t.w = f2tf32(v.w);
        out[i] = t;
    }
}

// Build combined [K=512][96] weight (off 64 | aw 32) and bias (fp32, no rounding)
__global__ void build_wq_kernel(const float* __restrict__ W_off,
                                const float* __restrict__ W_aw,
                                const float* __restrict__ b_off,
                                const float* __restrict__ b_aw,
                                float* __restrict__ wq, float* __restrict__ bq)
{
    const int i = blockIdx.x * 256 + threadIdx.x;  // 512*96 = 49152
    if (i < DMODEL * 96) {
        const int k = i / 96;
        const int n = i % 96;
        wq[i] = (n < 64) ? W_off[k * 64 + n] : W_aw[k * 32 + (n - 64)];
    }
    if (i < 96) {
        bq[i] = (i < 64) ? b_off[i] : b_aw[i - 64];
    }
}

// ===========================================================================
// Deformable sampling: 256 threads, float2 per thread; writes tf32-rounded mid.
// Reads fused offaw[row][96]: off pairs [0..63], logits [64..95].
// ===========================================================================
__global__ __launch_bounds__(256) void deform_kernel(
    const float* __restrict__ v,
    const float* __restrict__ offaw,
    float* __restrict__ mid)
{
    __shared__ float s_w0[NHEAD][NPNT];
    __shared__ float s_w1[NHEAD][NPNT];
    __shared__ int   s_i0[NHEAD][NPNT];
    __shared__ int   s_i1[NHEAD][NPNT];

    const int blk = blockIdx.x;
    const int b = blk / LSEQ;
    const int l = blk - b * LSEQ;
    const int t = threadIdx.x;

    if (t < NHEAD) {
        const int h = t;
        const float ref_y = (float)l / (float)(LSEQ - 1);
        const float* row = &offaw[(size_t)blk * 96];

        float lg[NPNT];
        float mx = -1e30f;
#pragma unroll
        for (int p = 0; p < NPNT; p++) {
            lg[p] = row[64 + h * NPNT + p];
            mx = fmaxf(mx, lg[p]);
        }
        float sum = 0.0f;
#pragma unroll
        for (int p = 0; p < NPNT; p++) { lg[p] = __expf(lg[p] - mx); sum += lg[p]; }
        const float inv = 1.0f / sum;

#pragma unroll
        for (int p = 0; p < NPNT; p++) {
            const float a = lg[p] * inv;
            const float ox = row[(h * NPNT + p) * 2 + 0];
            const float oy = row[(h * NPNT + p) * 2 + 1];
            const float locx = fminf(fmaxf(ox, 0.0f), 1.0f);
            const float locy = fminf(fmaxf(oy + ref_y, 0.0f), 1.0f);

            const float ix = ((locx + 1.0f) * (float)LSEQ - 1.0f) * 0.5f;
            const float iy = locy * 0.5f;
            const float ix0 = floorf(ix);
            const float fx = ix - ix0;
            const float iy0 = floorf(iy);
            const float fy = iy - iy0;
            const float ywt = (1.0f - fy) * (iy0 == 0.0f ? 1.0f : 0.0f)
                            + fy * ((iy0 + 1.0f) == 0.0f ? 1.0f : 0.0f);

            const int i0 = (int)ix0;
            const int i1 = i0 + 1;
            const float w = a * ywt;
            const bool v0 = (i0 >= 0) && (i0 < LSEQ);
            const bool v1 = (i1 >= 0) && (i1 < LSEQ);
            s_w0[h][p] = v0 ? w * (1.0f - fx) : 0.0f;
            s_w1[h][p] = v1 ? w * fx : 0.0f;
            s_i0[h][p] = min(max(i0, 0), LSEQ - 1);
            s_i1[h][p] = min(max(i1, 0), LSEQ - 1);
        }
    }
    __syncthreads();

    const int h  = t >> 5;
    const int c2 = t & 31;
    const float2* vb = reinterpret_cast<const float2*>(
        v + (size_t)b * LSEQ * DMODEL + h * CHEAD) + c2;

    float ax = 0.0f, ay = 0.0f;
#pragma unroll
    for (int p = 0; p < NPNT; p++) {
        const float w0 = s_w0[h][p];
        const float w1 = s_w1[h][p];
        const float2 x0 = vb[(size_t)s_i0[h][p] * (DMODEL / 2)];
        const float2 x1 = vb[(size_t)s_i1[h][p] * (DMODEL / 2)];
        ax = fmaf(w0, x0.x, ax); ay = fmaf(w0, x0.y, ay);
        ax = fmaf(w1, x1.x, ax); ay = fmaf(w1, x1.y, ay);
    }
    uint2 o;
    o.x = f2tf32(ax);
    o.y = f2tf32(ay);
    *reinterpret_cast<uint2*>(&mid[(size_t)blk * DMODEL + h * CHEAD + c2 * 2]) = o;
}

// ===========================================================================
// Host launch — fork/join across two streams (capture-safe pattern)
// ===========================================================================
extern "C" void kernel_launch(void* const* d_in, const int* in_sizes, int n_in,
                              void* d_out, int out_size)
{
    const float* query = (const float*)d_in[0];
    const float* value = (const float*)d_in[2];
    const float* W_v   = (const float*)d_in[3];
    const float* b_v   = (const float*)d_in[4];
    const float* W_off = (const float*)d_in[5];
    const float* b_off = (const float*)d_in[6];
    const float* W_aw  = (const float*)d_in[7];
    const float* b_aw  = (const float*)d_in[8];
    const float* W_out = (const float*)d_in[9];
    const float* b_out = (const float*)d_in[10];
    float* out = (float*)d_out;

    float *pv, *pva, *pmid, *poffaw, *pwvt, *pwot, *pwq, *pbq;
    cudaGetSymbolAddress((void**)&pv,     g_v);
    cudaGetSymbolAddress((void**)&pva,    g_va);
    cudaGetSymbolAddress((void**)&pmid,   g_mid);
    cudaGetSymbolAddress((void**)&poffaw, g_offaw);
    cudaGetSymbolAddress((void**)&pwvt,   g_wvt);
    cudaGetSymbolAddress((void**)&pwot,   g_wot);
    cudaGetSymbolAddress((void**)&pwq,    g_wq);
    cudaGetSymbolAddress((void**)&pbq,    g_bq);

    cudaFuncSetAttribute(gemm_async_kernel,
                         cudaFuncAttributeMaxDynamicSharedMemorySize, AG_SMEM);

    // Fork: side stream handles the offset/attention-weight chain.
    cudaEventRecord(g_ev0, 0);
    cudaStreamWaitEvent(g_s1, g_ev0, 0);

    // --- side stream: combined weights -> fused off/aw GEMM -> W_out^T ---
    build_wq_kernel<<<(DMODEL * 96 + 255) / 256, 256, 0, g_s1>>>(
        W_off, W_aw, b_off, b_aw, pwq, pbq);
    gemm_offaw_kernel<<<MROWS / 64, 384, 0, g_s1>>>(query, pwq, pbq, poffaw,
                                                    MROWS, DMODEL);
    {
        dim3 tb(32, 8);
        dim3 tg(DMODEL / 32, DMODEL / 32);
        transpose_rna_kernel<<<tg, tb, 0, g_s1>>>(W_out, pwot, DMODEL, DMODEL);
    }
    cudaEventRecord(g_ev1, g_s1);

    // --- default stream: value chain ---
    {
        dim3 tb(32, 8);
        dim3 tg(DMODEL / 32, DMODEL / 32);
        transpose_rna_kernel<<<tg, tb>>>(W_v, pwvt, DMODEL, DMODEL);
    }
    convert_rna_kernel<<<(MROWS * DMODEL / 4 + 255) / 256, 256>>>(
        (const float4*)value, (uint4*)pva, MROWS * DMODEL / 4);
    {
        dim3 grid(DMODEL / 128, MROWS / 128);
        gemm_async_kernel<<<grid, 256, AG_SMEM>>>(pva, pwvt, b_v, pv,
                                                  MROWS, DMODEL, DMODEL);
    }

    // Join: deform needs both chains.
    cudaStreamWaitEvent(0, g_ev1, 0);
    deform_kernel<<<MROWS, 256>>>(pv, poffaw, pmid);

    // --- out = mid @ W_out + b_out (async tf32) ---
    {
        dim3 grid(DMODEL / 128, MROWS / 128);
        gemm_async_kernel<<<grid, 256, AG_SMEM>>>(pmid, pwot, b_out, out,
                                                  MROWS, DMODEL, DMODEL);
    }
}

// round 7
// speedup vs baseline: 3.0296x; 1.0282x over previous
#include <cuda_runtime.h>
#include <cuda_bf16.h>
#include <math.h>
#include <stdint.h>

// Problem constants
#define BATCH 8
#define LSEQ  2048
#define DMODEL 512
#define NHEAD 8
#define NPNT  4
#define CHEAD 64
#define MROWS (BATCH * LSEQ)   // 16384

// Scratch (device globals; no allocation allowed)
__device__ __align__(16) float g_v[MROWS * DMODEL];       // value projection (fp32)
__device__ __align__(16) float g_va[MROWS * DMODEL];      // value, tf32-rounded
__device__ __align__(16) float g_mid[MROWS * DMODEL];     // deform output, tf32-rounded
__device__ __align__(16) float g_offaw[MROWS * 96];       // fused off(64)|aw(32), fp32
__device__ __align__(16) float g_wvt[DMODEL * DMODEL];    // W_v^T, tf32-rounded
__device__ __align__(16) float g_wot[DMODEL * DMODEL];    // W_out^T, tf32-rounded
__device__ __align__(16) float g_wq[DMODEL * 96];         // combined [K][96] W_off|W_aw
__device__ __align__(16) float g_bq[96];

// Streams/events for fork-join overlap (created once at module load).
static cudaStream_t g_s1, g_s2;
static cudaEvent_t g_ev0, g_ev1, g_ev2;
namespace {
struct StreamInit {
    StreamInit() {
        cudaStreamCreateWithFlags(&g_s1, cudaStreamNonBlocking);
        cudaStreamCreateWithFlags(&g_s2, cudaStreamNonBlocking);
        cudaEventCreateWithFlags(&g_ev0, cudaEventDisableTiming);
        cudaEventCreateWithFlags(&g_ev1, cudaEventDisableTiming);
        cudaEventCreateWithFlags(&g_ev2, cudaEventDisableTiming);
    }
};
StreamInit g_stream_init;
}

__device__ __forceinline__ uint32_t f2tf32(float x) {
    uint32_t u;
    asm("cvt.rna.tf32.f32 %0, %1;" : "=r"(u) : "f"(x));
    return u;
}

__device__ __forceinline__ uint32_t smem_u32(const void* p) {
    uint32_t a;
    asm("{ .reg .u64 t; cvta.to.shared.u64 t, %1; cvt.u32.u64 %0, t; }" : "=r"(a) : "l"(p));
    return a;
}

__device__ __forceinline__ void mma_tf32(float c[4],
                                         const uint32_t a[4],
                                         uint32_t b0, uint32_t b1) {
    asm volatile(
        "mma.sync.aligned.m16n8k8.row.col.f32.tf32.tf32.f32 "
        "{%0,%1,%2,%3}, {%4,%5,%6,%7}, {%8,%9}, {%0,%1,%2,%3};"
        : "+f"(c[0]), "+f"(c[1]), "+f"(c[2]), "+f"(c[3])
        : "r"(a[0]), "r"(a[1]), "r"(a[2]), "r"(a[3]), "r"(b0), "r"(b1));
}

#define CP_ASYNC16(dst, src) \
    asm volatile("cp.async.cg.shared.global [%0], [%1], 16;" :: "r"(dst), "l"(src) : "memory")
#define CP_COMMIT() asm volatile("cp.async.commit_group;" ::: "memory")
#define CP_WAIT1()  asm volatile("cp.async.wait_group 1;" ::: "memory")

// ===========================================================================
// Async tf32 GEMM: C[M,N] = A[M,K] @ Bt[N,K]^T + bias[N]
// ===========================================================================
#define AG_KC 32
#define AG_TILE 16384
#define AG_STAGE (2 * AG_TILE)
#define AG_STAGES 3
#define AG_SMEM (AG_STAGES * AG_STAGE) // 96KB

__global__ __launch_bounds__(256, 2)
void gemm_async_kernel(const float* __restrict__ A, const float* __restrict__ Bt,
                       const float* __restrict__ bias, float* __restrict__ C,
                       int M, int N, int K)
{
    extern __shared__ char smem[];
    const uint32_t sbase = smem_u32(smem);

    const int tid  = threadIdx.x;
    const int wid  = tid >> 5;
    const int lane = tid & 31;
    const int g    = lane >> 2;
    const int tig  = lane & 3;
    const int wm   = wid & 3;
    const int wn   = wid >> 2;

    const int m0 = blockIdx.y * 128;
    const int n0 = blockIdx.x * 128;

    const int cp_r0 = tid >> 3;
    const int cp_c4 = tid & 7;

    float acc[2][8][4];
#pragma unroll
    for (int mt = 0; mt < 2; mt++)
#pragma unroll
        for (int nt = 0; nt < 8; nt++)
#pragma unroll
            for (int j = 0; j < 4; j++) acc[mt][nt][j] = 0.0f;

    const int nch = K / AG_KC;

#define COPY_STAGE(s, chunk)                                                   \
    do {                                                                       \
        const int _k0 = (chunk) * AG_KC;                                       \
        const uint32_t _dA = sbase + (s) * AG_STAGE;                           \
        const uint32_t _dB = _dA + AG_TILE;                                    \
        _Pragma("unroll")                                                      \
        for (int e = 0; e < 4; e++) {                                          \
            const int r = cp_r0 + e * 32;                                      \
            const uint32_t sw = (uint32_t)((cp_c4 ^ (r & 7)) << 4);            \
            CP_ASYNC16(_dA + r * 128 + sw,                                     \
                       &A[(size_t)(m0 + r) * K + _k0 + cp_c4 * 4]);            \
            CP_ASYNC16(_dB + r * 128 + sw,                                     \
                       &Bt[(size_t)(n0 + r) * K + _k0 + cp_c4 * 4]);           \
        }                                                                      \
    } while (0)

    COPY_STAGE(0, 0); CP_COMMIT();
    COPY_STAGE(1, 1); CP_COMMIT();

    for (int c = 0; c < nch; ++c) {
        CP_WAIT1();
        __syncthreads();

        if (c + 2 < nch) {
            COPY_STAGE((c + 2) % AG_STAGES, c + 2);
        }
        CP_COMMIT();

        const int s = c % AG_STAGES;
        const uint32_t* SA = reinterpret_cast<const uint32_t*>(smem + s * AG_STAGE);
        const uint32_t* SB = reinterpret_cast<const uint32_t*>(smem + s * AG_STAGE + AG_TILE);

#pragma unroll
        for (int ks = 0; ks < 4; ks++) {
            const int c4  = 2 * ks;
            const int x0  = ((c4 ^ g) << 2) + tig;
            const int x1  = (((c4 + 1) ^ g) << 2) + tig;

            uint32_t afr[2][4];
#pragma unroll
            for (int mt = 0; mt < 2; mt++) {
                const int r = wm * 32 + mt * 16 + g;
                afr[mt][0] = SA[r * 32 + x0];
                afr[mt][1] = SA[(r + 8) * 32 + x0];
                afr[mt][2] = SA[r * 32 + x1];
                afr[mt][3] = SA[(r + 8) * 32 + x1];
            }
#pragma unroll
            for (int nt = 0; nt < 8; nt++) {
                const int n = wn * 64 + nt * 8 + g;
                const uint32_t b0 = SB[n * 32 + x0];
                const uint32_t b1 = SB[n * 32 + x1];
                mma_tf32(acc[0][nt], afr[0], b0, b1);
                mma_tf32(acc[1][nt], afr[1], b0, b1);
            }
        }
        __syncthreads();
    }
#undef COPY_STAGE

#pragma unroll
    for (int mt = 0; mt < 2; mt++) {
        const int row0 = m0 + wm * 32 + mt * 16 + g;
#pragma unroll
        for (int nt = 0; nt < 8; nt++) {
            const int col = n0 + wn * 64 + nt * 8 + tig * 2;
            const float bx = bias[col];
            const float by = bias[col + 1];
            float2 lo, hi;
            lo.x = acc[mt][nt][0] + bx;  lo.y = acc[mt][nt][1] + by;
            hi.x = acc[mt][nt][2] + bx;  hi.y = acc[mt][nt][3] + by;
            *reinterpret_cast<float2*>(&C[(size_t)row0 * N + col]) = lo;
            *reinterpret_cast<float2*>(&C[(size_t)(row0 + 8) * N + col]) = hi;
        }
    }
}

// ===========================================================================
// Fused fp32 SIMT GEMM for off|aw: C[M,96] = A[M,512] @ Wq[512,96] + bq
// ===========================================================================
#define FQ_TK 16

__global__ __launch_bounds__(384) void gemm_offaw_kernel(
    const float* __restrict__ A, const float* __restrict__ Wq,
    const float* __restrict__ bq, float* __restrict__ C, int M, int K)
{
    __shared__ float As[FQ_TK][68];
    __shared__ float Bs[FQ_TK][96];

    const int tid = threadIdx.x;
    const int ty = tid / 24;
    const int tx = tid % 24;

    const int m0 = blockIdx.x * 64;

    float acc[4][4];
#pragma unroll
    for (int i = 0; i < 4; i++)
#pragma unroll
        for (int j = 0; j < 4; j++) acc[i][j] = 0.0f;

    for (int k0 = 0; k0 < K; k0 += FQ_TK) {
#pragma unroll
        for (int e = 0; e < 3; e++) {
            const int idx = tid + e * 384;
            if (idx < 1024) {
                const int r = idx >> 4;
                const int c = idx & 15;
                As[c][r] = A[(size_t)(m0 + r) * K + k0 + c];
            }
        }
#pragma unroll
        for (int e = 0; e < 4; e++) {
            const int idx = tid + e * 384;
            const int r = idx / 96;
            const int c = idx % 96;
            Bs[r][c] = Wq[(size_t)(k0 + r) * 96 + c];
        }
        __syncthreads();

#pragma unroll
        for (int kk = 0; kk < FQ_TK; kk++) {
            float a[4], b[4];
#pragma unroll
            for (int i = 0; i < 4; i++) a[i] = As[kk][ty * 4 + i];
#pragma unroll
            for (int j = 0; j < 4; j++) b[j] = Bs[kk][tx * 4 + j];
#pragma unroll
            for (int i = 0; i < 4; i++)
#pragma unroll
                for (int j = 0; j < 4; j++)
                    acc[i][j] = fmaf(a[i], b[j], acc[i][j]);
        }
        __syncthreads();
    }

#pragma unroll
    for (int i = 0; i < 4; i++) {
        const int row = m0 + ty * 4 + i;
#pragma unroll
        for (int j = 0; j < 4; j++) {
            const int col = tx * 4 + j;
            C[(size_t)row * 96 + col] = acc[i][j] + bq[col];
        }
    }
}

// ===========================================================================
// Prep kernels
// ===========================================================================
__global__ void transpose_rna_kernel(const float* __restrict__ in,
                                     float* __restrict__ out, int R, int C)
{
    __shared__ float tile[32][33];
    const int bx = blockIdx.x * 32;
    const int by = blockIdx.y * 32;
#pragma unroll
    for (int j = 0; j < 32; j += 8)
        tile[threadIdx.y + j][threadIdx.x] =
            in[(size_t)(by + threadIdx.y + j) * C + bx + threadIdx.x];
    __syncthreads();
#pragma unroll
    for (int j = 0; j < 32; j += 8)
        out[(size_t)(bx + threadIdx.y + j) * R + by + threadIdx.x] =
            __uint_as_float(f2tf32(tile[threadIdx.x][threadIdx.y + j]));
}

__global__ void convert_rna_kernel(const float4* __restrict__ in,
                                   uint4* __restrict__ out, int n4)
{
    const int i = blockIdx.x * 256 + threadIdx.x;
    if (i < n4) {
        float4 v = in[i];
        uint4 t;
        t.x = f2tf32(v.x); t.y = f2tf32(v.y);
        t.z = f2tf32(v.z); t.w = f2tf32(v.w);
        out[i] = t;
    }
}

__global__ void build_wq_kernel(const float* __restrict__ W_off,
                                const float* __restrict__ W_aw,
                                const float* __restrict__ b_off,
                                const float* __restrict__ b_aw,
                                float* __restrict__ wq, float* __restrict__ bq)
{
    const int i = blockIdx.x * 256 + threadIdx.x;
    if (i < DMODEL * 96) {
        const int k = i / 96;
        const int n = i % 96;
        wq[i] = (n < 64) ? W_off[k * 64 + n] : W_aw[k * 32 + (n - 64)];
    }
    if (i < 96) {
        bq[i] = (i < 64) ? b_off[i] : b_aw[i - 64];
    }
}

// ===========================================================================
// Deformable sampling: 128 threads, float4 per thread; writes tf32-rounded mid.
// Reads fused offaw[row][96]: off pairs [0..63], logits [64..95].
// ===========================================================================
__global__ __launch_bounds__(128) void deform_kernel(
    const float* __restrict__ v,
    const float* __restrict__ offaw,
    float* __restrict__ mid)
{
    __shared__ float s_w0[NHEAD][NPNT];
    __shared__ float s_w1[NHEAD][NPNT];
    __shared__ int   s_i0[NHEAD][NPNT];
    __shared__ int   s_i1[NHEAD][NPNT];

    const int blk = blockIdx.x;
    const int b = blk / LSEQ;
    const int l = blk - b * LSEQ;
    const int t = threadIdx.x;

    if (t < NHEAD) {
        const int h = t;
        const float ref_y = (float)l / (float)(LSEQ - 1);
        const float* row = &offaw[(size_t)blk * 96];

        float lg[NPNT];
        float mx = -1e30f;
#pragma unroll
        for (int p = 0; p < NPNT; p++) {
            lg[p] = row[64 + h * NPNT + p];
            mx = fmaxf(mx, lg[p]);
        }
        float sum = 0.0f;
#pragma unroll
        for (int p = 0; p < NPNT; p++) { lg[p] = __expf(lg[p] - mx); sum += lg[p]; }
        const float inv = 1.0f / sum;

#pragma unroll
        for (int p = 0; p < NPNT; p++) {
            const float a = lg[p] * inv;
            const float ox = row[(h * NPNT + p) * 2 + 0];
            const float oy = row[(h * NPNT + p) * 2 + 1];
            const float locx = fminf(fmaxf(ox, 0.0f), 1.0f);
            const float locy = fminf(fmaxf(oy + ref_y, 0.0f), 1.0f);

            const float ix = ((locx + 1.0f) * (float)LSEQ - 1.0f) * 0.5f;
            const float iy = locy * 0.5f;
            const float ix0 = floorf(ix);
            const float fx = ix - ix0;
            const float iy0 = floorf(iy);
            const float fy = iy - iy0;
            const float ywt = (1.0f - fy) * (iy0 == 0.0f ? 1.0f : 0.0f)
                            + fy * ((iy0 + 1.0f) == 0.0f ? 1.0f : 0.0f);

            const int i0 = (int)ix0;
            const int i1 = i0 + 1;
            const float w = a * ywt;
            const bool v0 = (i0 >= 0) && (i0 < LSEQ);
            const bool v1 = (i1 >= 0) && (i1 < LSEQ);
            s_w0[h][p] = v0 ? w * (1.0f - fx) : 0.0f;
            s_w1[h][p] = v1 ? w * fx : 0.0f;
            s_i0[h][p] = min(max(i0, 0), LSEQ - 1);
            s_i1[h][p] = min(max(i1, 0), LSEQ - 1);
        }
    }
    __syncthreads();

    const int h  = t >> 4;       // 0..7
    const int c4 = t & 15;       // float4 index within head (16 per head)
    const float4* vb = reinterpret_cast<const float4*>(
        v + (size_t)b * LSEQ * DMODEL + h * CHEAD) + c4;

    float ax = 0.0f, ay = 0.0f, az = 0.0f, aw = 0.0f;
#pragma unroll
    for (int p = 0; p < NPNT; p++) {
        const float w0 = s_w0[h][p];
        const float w1 = s_w1[h][p];
        const float4 x0 = vb[(size_t)s_i0[h][p] * (DMODEL / 4)];
        const float4 x1 = vb[(size_t)s_i1[h][p] * (DMODEL / 4)];
        ax = fmaf(w0, x0.x, ax); ay = fmaf(w0, x0.y, ay);
        az = fmaf(w0, x0.z, az); aw = fmaf(w0, x0.w, aw);
        ax = fmaf(w1, x1.x, ax); ay = fmaf(w1, x1.y, ay);
        az = fmaf(w1, x1.z, az); aw = fmaf(w1, x1.w, aw);
    }
    uint4 o;
    o.x = f2tf32(ax);
    o.y = f2tf32(ay);
    o.z = f2tf32(az);
    o.w = f2tf32(aw);
    *reinterpret_cast<uint4*>(&mid[(size_t)blk * DMODEL + h * CHEAD + c4 * 4]) = o;
}

// ===========================================================================
// Host launch — three-way fork/join (capture-safe pattern)
// ===========================================================================
extern "C" void kernel_launch(void* const* d_in, const int* in_sizes, int n_in,
                              void* d_out, int out_size)
{
    const float* query = (const float*)d_in[0];
    const float* value = (const float*)d_in[2];
    const float* W_v   = (const float*)d_in[3];
    const float* b_v   = (const float*)d_in[4];
    const float* W_off = (const float*)d_in[5];
    const float* b_off = (const float*)d_in[6];
    const float* W_aw  = (const float*)d_in[7];
    const float* b_aw  = (const float*)d_in[8];
    const float* W_out = (const float*)d_in[9];
    const float* b_out = (const float*)d_in[10];
    float* out = (float*)d_out;

    float *pv, *pva, *pmid, *poffaw, *pwvt, *pwot, *pwq, *pbq;
    cudaGetSymbolAddress((void**)&pv,     g_v);
    cudaGetSymbolAddress((void**)&pva,    g_va);
    cudaGetSymbolAddress((void**)&pmid,   g_mid);
    cudaGetSymbolAddress((void**)&poffaw, g_offaw);
    cudaGetSymbolAddress((void**)&pwvt,   g_wvt);
    cudaGetSymbolAddress((void**)&pwot,   g_wot);
    cudaGetSymbolAddress((void**)&pwq,    g_wq);
    cudaGetSymbolAddress((void**)&pbq,    g_bq);

    cudaFuncSetAttribute(gemm_async_kernel,
                         cudaFuncAttributeMaxDynamicSharedMemorySize, AG_SMEM);

    // Fork.
    cudaEventRecord(g_ev0, 0);
    cudaStreamWaitEvent(g_s1, g_ev0, 0);
    cudaStreamWaitEvent(g_s2, g_ev0, 0);

    // --- s1: off/aw chain + W_out transpose ---
    build_wq_kernel<<<(DMODEL * 96 + 255) / 256, 256, 0, g_s1>>>(
        W_off, W_aw, b_off, b_aw, pwq, pbq);
    gemm_offaw_kernel<<<MROWS / 64, 384, 0, g_s1>>>(query, pwq, pbq, poffaw,
                                                    MROWS, DMODEL);
    {
        dim3 tb(32, 8);
        dim3 tg(DMODEL / 32, DMODEL / 32);
        transpose_rna_kernel<<<tg, tb, 0, g_s1>>>(W_out, pwot, DMODEL, DMODEL);
    }
    cudaEventRecord(g_ev1, g_s1);

    // --- s2: RNA-convert value (concurrent with W_v transpose on s0) ---
    convert_rna_kernel<<<(MROWS * DMODEL / 4 + 255) / 256, 256, 0, g_s2>>>(
        (const float4*)value, (uint4*)pva, MROWS * DMODEL / 4);
    cudaEventRecord(g_ev2, g_s2);

    // --- s0 (origin): W_v transpose, then v-GEMM once convert is done ---
    {
        dim3 tb(32, 8);
        dim3 tg(DMODEL / 32, DMODEL / 32);
        transpose_rna_kernel<<<tg, tb>>>(W_v, pwvt, DMODEL, DMODEL);
    }
    cudaStreamWaitEvent(0, g_ev2, 0);
    {
        dim3 grid(DMODEL / 128, MROWS / 128);
        gemm_async_kernel<<<grid, 256, AG_SMEM>>>(pva, pwvt, b_v, pv,
                                                  MROWS, DMODEL, DMODEL);
    }

    // Join: deform needs the off/aw chain too.
    cudaStreamWaitEvent(0, g_ev1, 0);
    deform_kernel<<<MROWS, 128>>>(pv, poffaw, pmid);

    // --- out = mid @ W_out + b_out (async tf32) ---
    {
        dim3 grid(DMODEL / 128, MROWS / 128);
        gemm_async_kernel<<<grid, 256, AG_SMEM>>>(pmid, pwot, b_out, out,
                                                  MROWS, DMODEL, DMODEL);
    }
}

// round 8
// speedup vs baseline: 3.8534x; 1.2719x over previous
#include <cuda_runtime.h>
#include <cuda_fp16.h>
#include <math.h>
#include <stdint.h>

// Problem constants
#define BATCH 8
#define LSEQ  2048
#define DMODEL 512
#define NHEAD 8
#define NPNT  4
#define CHEAD 64
#define MROWS (BATCH * LSEQ)   // 16384

// Scratch (device globals; no allocation allowed)
__device__ __align__(16) __half g_v[MROWS * DMODEL];      // value projection (fp16)
__device__ __align__(16) __half g_va[MROWS * DMODEL];     // value, fp16
__device__ __align__(16) __half g_mid[MROWS * DMODEL];    // deform output (fp16)
__device__ __align__(16) float  g_offaw[MROWS * 96];      // fused off|aw (fp32!)
__device__ __align__(16) __half g_wvt[DMODEL * DMODEL];   // W_v^T   fp16 [N][K]
__device__ __align__(16) __half g_wot[DMODEL * DMODEL];   // W_out^T fp16 [N][K]
__device__ __align__(16) float  g_wq[DMODEL * 96];        // combined W_off|W_aw (fp32)
__device__ __align__(16) float  g_bq[96];

// Streams/events for fork-join overlap (created once at module load).
static cudaStream_t g_s1, g_s2;
static cudaEvent_t g_ev0, g_ev1, g_ev2;
namespace {
struct StreamInit {
    StreamInit() {
        cudaStreamCreateWithFlags(&g_s1, cudaStreamNonBlocking);
        cudaStreamCreateWithFlags(&g_s2, cudaStreamNonBlocking);
        cudaEventCreateWithFlags(&g_ev0, cudaEventDisableTiming);
        cudaEventCreateWithFlags(&g_ev1, cudaEventDisableTiming);
        cudaEventCreateWithFlags(&g_ev2, cudaEventDisableTiming);
    }
};
StreamInit g_stream_init;
}

__device__ __forceinline__ uint32_t smem_u32(const void* p) {
    uint32_t a;
    asm("{ .reg .u64 t; cvta.to.shared.u64 t, %1; cvt.u32.u64 %0, t; }" : "=r"(a) : "l"(p));
    return a;
}

__device__ __forceinline__ void mma_f16(float c[4],
                                        const uint32_t a[4],
                                        uint32_t b0, uint32_t b1) {
    asm volatile(
        "mma.sync.aligned.m16n8k16.row.col.f32.f16.f16.f32 "
        "{%0,%1,%2,%3}, {%4,%5,%6,%7}, {%8,%9}, {%0,%1,%2,%3};"
        : "+f"(c[0]), "+f"(c[1]), "+f"(c[2]), "+f"(c[3])
        : "r"(a[0]), "r"(a[1]), "r"(a[2]), "r"(a[3]), "r"(b0), "r"(b1));
}

#define CP_ASYNC16(dst, src) \
    asm volatile("cp.async.cg.shared.global [%0], [%1], 16;" :: "r"(dst), "l"(src) : "memory")
#define CP_COMMIT() asm volatile("cp.async.commit_group;" ::: "memory")
#define CP_WAIT2()  asm volatile("cp.async.wait_group 2;" ::: "memory")

// ===========================================================================
// Async fp16 GEMM: C[M,N] = A[M,K] @ Bt[N,K]^T + bias[N]
// A, Bt fp16 K-contiguous. 128x128 tile, 256 thr, KC=32, 4 stages.
// SMEM row stride 80B (64B data + 16B pad) -> conflict-free fragment LDS:
// word bank = (20*g + tig) mod 32 covers all 32 banks exactly.
// OutT: __half (packed half2 stores) or float (float2 stores).
// ===========================================================================
#define HG_KC 32
#define HG_ROWB 80                      // bytes per smem row
#define HG_TILE (128 * HG_ROWB)         // 10240 B per operand
#define HG_STAGE (2 * HG_TILE)          // 20480 B
#define HG_STAGES 4
#define HG_SMEM (HG_STAGES * HG_STAGE)  // 81920 B

template <typename OutT>
__global__ __launch_bounds__(256, 2)
void gemm_async_h_kernel(const __half* __restrict__ A, const __half* __restrict__ Bt,
                         const float* __restrict__ bias, OutT* __restrict__ C,
                         int M, int N, int K)
{
    extern __shared__ char smem[];
    const uint32_t sbase = smem_u32(smem);

    const int tid  = threadIdx.x;
    const int wid  = tid >> 5;
    const int lane = tid & 31;
    const int g    = lane >> 2;
    const int tig  = lane & 3;
    const int wm   = wid & 3;      // 32 rows each
    const int wn   = wid >> 2;     // 64 cols each

    const int m0 = blockIdx.y * 128;
    const int n0 = blockIdx.x * 128;

    float acc[2][8][4];
#pragma unroll
    for (int mt = 0; mt < 2; mt++)
#pragma unroll
        for (int nt = 0; nt < 8; nt++)
#pragma unroll
            for (int j = 0; j < 4; j++) acc[mt][nt][j] = 0.0f;

    const int nch = K / HG_KC;   // 16

#define HCOPY_STAGE(s, chunk)                                                  \
    do {                                                                       \
        const int _k0 = (chunk) * HG_KC;                                       \
        const uint32_t _dA = sbase + (s) * HG_STAGE;                           \
        const uint32_t _dB = _dA + HG_TILE;                                    \
        _Pragma("unroll")                                                      \
        for (int e = 0; e < 2; e++) {                                          \
            const int cc = tid + e * 256;      /* 0..511 */                    \
            const int r = cc >> 2;             /* 0..127 */                    \
            const int q = cc & 3;              /* 16B chunk in row */          \
            CP_ASYNC16(_dA + r * HG_ROWB + q * 16,                             \
                       &A[(size_t)(m0 + r) * K + _k0 + q * 8]);                \
            CP_ASYNC16(_dB + r * HG_ROWB + q * 16,                             \
                       &Bt[(size_t)(n0 + r) * K + _k0 + q * 8]);               \
        }                                                                      \
    } while (0)

    // prologue: 3 stages in flight
    HCOPY_STAGE(0, 0); CP_COMMIT();
    HCOPY_STAGE(1, 1); CP_COMMIT();
    HCOPY_STAGE(2, 2); CP_COMMIT();

    for (int c = 0; c < nch; ++c) {
        CP_WAIT2();
        __syncthreads();

        if (c + 3 < nch) {
            HCOPY_STAGE((c + 3) % HG_STAGES, c + 3);
        }
        CP_COMMIT();

        const int s = c % HG_STAGES;
        const uint32_t* SA = reinterpret_cast<const uint32_t*>(smem + s * HG_STAGE);
        const uint32_t* SB = reinterpret_cast<const uint32_t*>(smem + s * HG_STAGE + HG_TILE);

#pragma unroll
        for (int ks = 0; ks < 2; ks++) {          // two K=16 steps per chunk
            const int kw = ks * 8 + tig;          // word offset within row

            uint32_t afr[2][4];
#pragma unroll
            for (int mt = 0; mt < 2; mt++) {
                const int r = wm * 32 + mt * 16 + g;
                afr[mt][0] = SA[r * 20 + kw];
                afr[mt][1] = SA[(r + 8) * 20 + kw];
                afr[mt][2] = SA[r * 20 + kw + 4];
                afr[mt][3] = SA[(r + 8) * 20 + kw + 4];
            }
#pragma unroll
            for (int nt = 0; nt < 8; nt++) {
                const int n = wn * 64 + nt * 8 + g;
                const uint32_t b0 = SB[n * 20 + kw];
                const uint32_t b1 = SB[n * 20 + kw + 4];
                mma_f16(acc[0][nt], afr[0], b0, b1);
                mma_f16(acc[1][nt], afr[1], b0, b1);
            }
        }
        __syncthreads();
    }
#undef HCOPY_STAGE

    // epilogue: C = acc + bias
#pragma unroll
    for (int mt = 0; mt < 2; mt++) {
        const int row0 = m0 + wm * 32 + mt * 16 + g;
#pragma unroll
        for (int nt = 0; nt < 8; nt++) {
            const int col = n0 + wn * 64 + nt * 8 + tig * 2;
            const float bx = bias[col];
            const float by = bias[col + 1];
            const float l0 = acc[mt][nt][0] + bx;
            const float l1 = acc[mt][nt][1] + by;
            const float h0 = acc[mt][nt][2] + bx;
            const float h1 = acc[mt][nt][3] + by;
            if constexpr (sizeof(OutT) == 2) {
                __half2* p0 = reinterpret_cast<__half2*>(
                    &C[(size_t)row0 * N + col]);
                __half2* p1 = reinterpret_cast<__half2*>(
                    &C[(size_t)(row0 + 8) * N + col]);
                *p0 = __floats2half2_rn(l0, l1);
                *p1 = __floats2half2_rn(h0, h1);
            } else {
                float2 lo, hi;
                lo.x = l0; lo.y = l1; hi.x = h0; hi.y = h1;
                *reinterpret_cast<float2*>(&C[(size_t)row0 * N + col]) = lo;
                *reinterpret_cast<float2*>(&C[(size_t)(row0 + 8) * N + col]) = hi;
            }
        }
    }
}

// ===========================================================================
// Fused fp32 SIMT GEMM for off|aw: C[M,96] = A[M,512] @ Wq[512,96] + bq
// (precision-critical: coordinate error amplified x1024 by the sampling grid)
// ===========================================================================
#define FQ_TK 16

__global__ __launch_bounds__(384) void gemm_offaw_kernel(
    const float* __restrict__ A, const float* __restrict__ Wq,
    const float* __restrict__ bq, float* __restrict__ C, int M, int K)
{
    __shared__ float As[FQ_TK][68];
    __shared__ float Bs[FQ_TK][96];

    const int tid = threadIdx.x;
    const int ty = tid / 24;
    const int tx = tid % 24;

    const int m0 = blockIdx.x * 64;

    float acc[4][4];
#pragma unroll
    for (int i = 0; i < 4; i++)
#pragma unroll
        for (int j = 0; j < 4; j++) acc[i][j] = 0.0f;

    for (int k0 = 0; k0 < K; k0 += FQ_TK) {
#pragma unroll
        for (int e = 0; e < 3; e++) {
            const int idx = tid + e * 384;
            if (idx < 1024) {
                const int r = idx >> 4;
                const int c = idx & 15;
                As[c][r] = A[(size_t)(m0 + r) * K + k0 + c];
            }
        }
#pragma unroll
        for (int e = 0; e < 4; e++) {
            const int idx = tid + e * 384;
            const int r = idx / 96;
            const int c = idx % 96;
            Bs[r][c] = Wq[(size_t)(k0 + r) * 96 + c];
        }
        __syncthreads();

#pragma unroll
        for (int kk = 0; kk < FQ_TK; kk++) {
            float a[4], b[4];
#pragma unroll
            for (int i = 0; i < 4; i++) a[i] = As[kk][ty * 4 + i];
#pragma unroll
            for (int j = 0; j < 4; j++) b[j] = Bs[kk][tx * 4 + j];
#pragma unroll
            for (int i = 0; i < 4; i++)
#pragma unroll
                for (int j = 0; j < 4; j++)
                    acc[i][j] = fmaf(a[i], b[j], acc[i][j]);
        }
        __syncthreads();
    }

#pragma unroll
    for (int i = 0; i < 4; i++) {
        const int row = m0 + ty * 4 + i;
#pragma unroll
        for (int j = 0; j < 4; j++) {
            const int col = tx * 4 + j;
            C[(size_t)row * 96 + col] = acc[i][j] + bq[col];
        }
    }
}

// ===========================================================================
// Prep kernels
// ===========================================================================
// W^T to fp16: out[n*R + k] = (half)in[k*C + n]
__global__ void transpose_h_kernel(const float* __restrict__ in,
                                   __half* __restrict__ out, int R, int C)
{
    __shared__ float tile[32][33];
    const int bx = blockIdx.x * 32;
    const int by = blockIdx.y * 32;
#pragma unroll
    for (int j = 0; j < 32; j += 8)
        tile[threadIdx.y + j][threadIdx.x] =
            in[(size_t)(by + threadIdx.y + j) * C + bx + threadIdx.x];
    __syncthreads();
#pragma unroll
    for (int j = 0; j < 32; j += 8)
        out[(size_t)(bx + threadIdx.y + j) * R + by + threadIdx.x] =
            __float2half_rn(tile[threadIdx.x][threadIdx.y + j]);
}

// fp32 -> fp16 (8 elements per thread)
__global__ void convert_h_kernel(const float4* __restrict__ in,
                                 uint2* __restrict__ out, int n8)
{
    const int i = blockIdx.x * 256 + threadIdx.x;
    if (i < n8) {
        const float4 a = in[2 * i];
        const float4 b = in[2 * i + 1];
        uint2 o;
        __half2 p0 = __floats2half2_rn(a.x, a.y);
        __half2 p1 = __floats2half2_rn(a.z, a.w);
        __half2 p2 = __floats2half2_rn(b.x, b.y);
        __half2 p3 = __floats2half2_rn(b.z, b.w);
        o.x = (*(uint16_t*)&p0.x) | ((uint32_t)(*(uint16_t*)&p0.y) << 16);
        o.x = *reinterpret_cast<uint32_t*>(&p0);
        o.y = *reinterpret_cast<uint32_t*>(&p1);
        out[2 * i] = o;
        uint2 o2;
        o2.x = *reinterpret_cast<uint32_t*>(&p2);
        o2.y = *reinterpret_cast<uint32_t*>(&p3);
        out[2 * i + 1] = o2;
    }
}

__global__ void build_wq_kernel(const float* __restrict__ W_off,
                                const float* __restrict__ W_aw,
                                const float* __restrict__ b_off,
                                const float* __restrict__ b_aw,
                                float* __restrict__ wq, float* __restrict__ bq)
{
    const int i = blockIdx.x * 256 + threadIdx.x;
    if (i < DMODEL * 96) {
        const int k = i / 96;
        const int n = i % 96;
        wq[i] = (n < 64) ? W_off[k * 64 + n] : W_aw[k * 32 + (n - 64)];
    }
    if (i < 96) {
        bq[i] = (i < 64) ? b_off[i] : b_aw[i - 64];
    }
}

// ===========================================================================
// Deformable sampling: 128 threads; v and mid are fp16, math fp32.
// Reads fused offaw[row][96] fp32: off pairs [0..63], logits [64..95].
// ===========================================================================
__global__ __launch_bounds__(128) void deform_kernel(
    const __half* __restrict__ v,
    const float* __restrict__ offaw,
    __half* __restrict__ mid)
{
    __shared__ float s_w0[NHEAD][NPNT];
    __shared__ float s_w1[NHEAD][NPNT];
    __shared__ int   s_i0[NHEAD][NPNT];
    __shared__ int   s_i1[NHEAD][NPNT];

    const int blk = blockIdx.x;
    const int b = blk / LSEQ;
    const int l = blk - b * LSEQ;
    const int t = threadIdx.x;

    if (t < NHEAD) {
        const int h = t;
        const float ref_y = (float)l / (float)(LSEQ - 1);
        const float* row = &offaw[(size_t)blk * 96];

        float lg[NPNT];
        float mx = -1e30f;
#pragma unroll
        for (int p = 0; p < NPNT; p++) {
            lg[p] = row[64 + h * NPNT + p];
            mx = fmaxf(mx, lg[p]);
        }
        float sum = 0.0f;
#pragma unroll
        for (int p = 0; p < NPNT; p++) { lg[p] = __expf(lg[p] - mx); sum += lg[p]; }
        const float inv = 1.0f / sum;

#pragma unroll
        for (int p = 0; p < NPNT; p++) {
            const float a = lg[p] * inv;
            const float ox = row[(h * NPNT + p) * 2 + 0];
            const float oy = row[(h * NPNT + p) * 2 + 1];
            const float locx = fminf(fmaxf(ox, 0.0f), 1.0f);
            const float locy = fminf(fmaxf(oy + ref_y, 0.0f), 1.0f);

            const float ix = ((locx + 1.0f) * (float)LSEQ - 1.0f) * 0.5f;
            const float iy = locy * 0.5f;
            const float ix0 = floorf(ix);
            const float fx = ix - ix0;
            const float iy0 = floorf(iy);
            const float fy = iy - iy0;
            const float ywt = (1.0f - fy) * (iy0 == 0.0f ? 1.0f : 0.0f)
                            + fy * ((iy0 + 1.0f) == 0.0f ? 1.0f : 0.0f);

            const int i0 = (int)ix0;
            const int i1 = i0 + 1;
            const float w = a * ywt;
            const bool v0 = (i0 >= 0) && (i0 < LSEQ);
            const bool v1 = (i1 >= 0) && (i1 < LSEQ);
            s_w0[h][p] = v0 ? w * (1.0f - fx) : 0.0f;
            s_w1[h][p] = v1 ? w * fx : 0.0f;
            s_i0[h][p] = min(max(i0, 0), LSEQ - 1);
            s_i1[h][p] = min(max(i1, 0), LSEQ - 1);
        }
    }
    __syncthreads();

    const int h  = t >> 4;       // 0..7
    const int c4 = t & 15;       // 4-half group within head (16 per head)
    const uint2* vb = reinterpret_cast<const uint2*>(
        v + (size_t)b * LSEQ * DMODEL + h * CHEAD) + c4;

    float ax = 0.0f, ay = 0.0f, az = 0.0f, aw = 0.0f;
#pragma unroll
    for (int p = 0; p < NPNT; p++) {
        const float w0 = s_w0[h][p];
        const float w1 = s_w1[h][p];
        const uint2 u0 = vb[(size_t)s_i0[h][p] * (DMODEL / 4)];
        const uint2 u1 = vb[(size_t)s_i1[h][p] * (DMODEL / 4)];
        const float2 f00 = __half22float2(*reinterpret_cast<const __half2*>(&u0.x));
        const float2 f01 = __half22float2(*reinterpret_cast<const __half2*>(&u0.y));
        const float2 f10 = __half22float2(*reinterpret_cast<const __half2*>(&u1.x));
        const float2 f11 = __half22float2(*reinterpret_cast<const __half2*>(&u1.y));
        ax = fmaf(w0, f00.x, ax); ay = fmaf(w0, f00.y, ay);
        az = fmaf(w0, f01.x, az); aw = fmaf(w0, f01.y, aw);
        ax = fmaf(w1, f10.x, ax); ay = fmaf(w1, f10.y, ay);
        az = fmaf(w1, f11.x, az); aw = fmaf(w1, f11.y, aw);
    }
    __half2 o0 = __floats2half2_rn(ax, ay);
    __half2 o1 = __floats2half2_rn(az, aw);
    uint2 o;
    o.x = *reinterpret_cast<uint32_t*>(&o0);
    o.y = *reinterpret_cast<uint32_t*>(&o1);
    *reinterpret_cast<uint2*>(&mid[(size_t)blk * DMODEL + h * CHEAD + c4 * 4]) = o;
}

// ===========================================================================
// Host launch — three-way fork/join (capture-safe pattern)
// ===========================================================================
extern "C" void kernel_launch(void* const* d_in, const int* in_sizes, int n_in,
                              void* d_out, int out_size)
{
    const float* query = (const float*)d_in[0];
    const float* value = (const float*)d_in[2];
    const float* W_v   = (const float*)d_in[3];
    const float* b_v   = (const float*)d_in[4];
    const float* W_off = (const float*)d_in[5];
    const float* b_off = (const float*)d_in[6];
    const float* W_aw  = (const float*)d_in[7];
    const float* b_aw  = (const float*)d_in[8];
    const float* W_out = (const float*)d_in[9];
    const float* b_out = (const float*)d_in[10];
    float* out = (float*)d_out;

    __half *pv, *pva, *pmid, *pwvt, *pwot;
    float *poffaw, *pwq, *pbq;
    cudaGetSymbolAddress((void**)&pv,     g_v);
    cudaGetSymbolAddress((void**)&pva,    g_va);
    cudaGetSymbolAddress((void**)&pmid,   g_mid);
    cudaGetSymbolAddress((void**)&poffaw, g_offaw);
    cudaGetSymbolAddress((void**)&pwvt,   g_wvt);
    cudaGetSymbolAddress((void**)&pwot,   g_wot);
    cudaGetSymbolAddress((void**)&pwq,    g_wq);
    cudaGetSymbolAddress((void**)&pbq,    g_bq);

    cudaFuncSetAttribute(gemm_async_h_kernel<__half>,
                         cudaFuncAttributeMaxDynamicSharedMemorySize, HG_SMEM);
    cudaFuncSetAttribute(gemm_async_h_kernel<float>,
                         cudaFuncAttributeMaxDynamicSharedMemorySize, HG_SMEM);

    // Fork.
    cudaEventRecord(g_ev0, 0);
    cudaStreamWaitEvent(g_s1, g_ev0, 0);
    cudaStreamWaitEvent(g_s2, g_ev0, 0);

    // --- s1: off/aw chain (fp32) + W_out transpose ---
    build_wq_kernel<<<(DMODEL * 96 + 255) / 256, 256, 0, g_s1>>>(
        W_off, W_aw, b_off, b_aw, pwq, pbq);
    gemm_offaw_kernel<<<MROWS / 64, 384, 0, g_s1>>>(query, pwq, pbq, poffaw,
                                                    MROWS, DMODEL);
    {
        dim3 tb(32, 8);
        dim3 tg(DMODEL / 32, DMODEL / 32);
        transpose_h_kernel<<<tg, tb, 0, g_s1>>>(W_out, pwot, DMODEL, DMODEL);
    }
    cudaEventRecord(g_ev1, g_s1);

    // --- s2: convert value to fp16 (concurrent with W_v transpose on s0) ---
    convert_h_kernel<<<(MROWS * DMODEL / 8 + 255) / 256, 256, 0, g_s2>>>(
        (const float4*)value, (uint2*)pva, MROWS * DMODEL / 8);
    cudaEventRecord(g_ev2, g_s2);

    // --- s0 (origin): W_v transpose, then v-GEMM once convert is done ---
    {
        dim3 tb(32, 8);
        dim3 tg(DMODEL / 32, DMODEL / 32);
        transpose_h_kernel<<<tg, tb>>>(W_v, pwvt, DMODEL, DMODEL);
    }
    cudaStreamWaitEvent(0, g_ev2, 0);
    {
        dim3 grid(DMODEL / 128, MROWS / 128);
        gemm_async_h_kernel<__half><<<grid, 256, HG_SMEM>>>(pva, pwvt, b_v, pv,
                                                            MROWS, DMODEL, DMODEL);
    }

    // Join: deform needs the off/aw chain too.
    cudaStreamWaitEvent(0, g_ev1, 0);
    deform_kernel<<<MROWS, 128>>>(pv, poffaw, pmid);

    // --- out = mid @ W_out + b_out (fp16 mma, fp32 out) ---
    {
        dim3 grid(DMODEL / 128, MROWS / 128);
        gemm_async_h_kernel<float><<<grid, 256, HG_SMEM>>>(pmid, pwot, b_out, out,
                                                           MROWS, DMODEL, DMODEL);
    }
}

// round 9
// speedup vs baseline: 3.9014x; 1.0125x over previous
#include <cuda_runtime.h>
#include <cuda_fp16.h>
#include <math.h>
#include <stdint.h>

// Problem constants
#define BATCH 8
#define LSEQ  2048
#define DMODEL 512
#define NHEAD 8
#define NPNT  4
#define CHEAD 64
#define MROWS (BATCH * LSEQ)   // 16384

// Scratch (device globals; no allocation allowed)
__device__ __align__(16) __half g_v[MROWS * DMODEL];      // value projection (fp16)
__device__ __align__(16) __half g_va[MROWS * DMODEL];     // value, fp16
__device__ __align__(16) __half g_mid[MROWS * DMODEL];    // deform output (fp16)
__device__ __align__(16) float  g_offaw[MROWS * 128];     // off(64)|aw(32)|pad, fp32
__device__ __align__(16) __half g_wvt[DMODEL * DMODEL];   // W_v^T   fp16 [N][K]
__device__ __align__(16) __half g_wot[DMODEL * DMODEL];   // W_out^T fp16 [N][K]
__device__ __align__(16) __half g_qhi[MROWS * DMODEL];    // query hi fp16
__device__ __align__(16) __half g_qlo[MROWS * DMODEL];    // query lo fp16 (residual)
__device__ __align__(16) __half g_wqt_hi[128 * DMODEL];   // Wq^T hi fp16 [128][512]
__device__ __align__(16) __half g_wqt_lo[128 * DMODEL];   // Wq^T lo fp16
__device__ __align__(16) float  g_bq[128];

// Streams/events for fork-join overlap (created once at module load).
static cudaStream_t g_s1, g_s2;
static cudaEvent_t g_ev0, g_ev1, g_ev2;
namespace {
struct StreamInit {
    StreamInit() {
        cudaStreamCreateWithFlags(&g_s1, cudaStreamNonBlocking);
        cudaStreamCreateWithFlags(&g_s2, cudaStreamNonBlocking);
        cudaEventCreateWithFlags(&g_ev0, cudaEventDisableTiming);
        cudaEventCreateWithFlags(&g_ev1, cudaEventDisableTiming);
        cudaEventCreateWithFlags(&g_ev2, cudaEventDisableTiming);
    }
};
StreamInit g_stream_init;
}

__device__ __forceinline__ uint32_t smem_u32(const void* p) {
    uint32_t a;
    asm("{ .reg .u64 t; cvta.to.shared.u64 t, %1; cvt.u32.u64 %0, t; }" : "=r"(a) : "l"(p));
    return a;
}

__device__ __forceinline__ void mma_f16(float c[4],
                                        const uint32_t a[4],
                                        uint32_t b0, uint32_t b1) {
    asm volatile(
        "mma.sync.aligned.m16n8k16.row.col.f32.f16.f16.f32 "
        "{%0,%1,%2,%3}, {%4,%5,%6,%7}, {%8,%9}, {%0,%1,%2,%3};"
        : "+f"(c[0]), "+f"(c[1]), "+f"(c[2]), "+f"(c[3])
        : "r"(a[0]), "r"(a[1]), "r"(a[2]), "r"(a[3]), "r"(b0), "r"(b1));
}

#define CP_ASYNC16(dst, src) \
    asm volatile("cp.async.cg.shared.global [%0], [%1], 16;" :: "r"(dst), "l"(src) : "memory")
#define CP_COMMIT() asm volatile("cp.async.commit_group;" ::: "memory")
#define CP_WAIT2()  asm volatile("cp.async.wait_group 2;" ::: "memory")

// ===========================================================================
// Async fp16 GEMM: C[M,N] = A[M,K] @ Bt[N,K]^T + (ACC ? C : bias)
// A, Bt fp16 K-contiguous. 128x128 tile, 256 thr, KC=32, 4 stages.
// SMEM row stride 80B: fragment LDS word bank = (20g+tig) mod 32 -> conflict-free.
// ===========================================================================
#define HG_KC 32
#define HG_ROWB 80
#define HG_TILE (128 * HG_ROWB)
#define HG_STAGE (2 * HG_TILE)
#define HG_STAGES 4
#define HG_SMEM (HG_STAGES * HG_STAGE)  // 81920 B

template <typename OutT, bool ACC>
__global__ __launch_bounds__(256, 2)
void gemm_async_h_kernel(const __half* __restrict__ A, const __half* __restrict__ Bt,
                         const float* __restrict__ bias, OutT* __restrict__ C,
                         int M, int N, int K)
{
    extern __shared__ char smem[];
    const uint32_t sbase = smem_u32(smem);

    const int tid  = threadIdx.x;
    const int wid  = tid >> 5;
    const int lane = tid & 31;
    const int g    = lane >> 2;
    const int tig  = lane & 3;
    const int wm   = wid & 3;
    const int wn   = wid >> 2;

    const int m0 = blockIdx.y * 128;
    const int n0 = blockIdx.x * 128;

    float acc[2][8][4];
#pragma unroll
    for (int mt = 0; mt < 2; mt++)
#pragma unroll
        for (int nt = 0; nt < 8; nt++)
#pragma unroll
            for (int j = 0; j < 4; j++) acc[mt][nt][j] = 0.0f;

    const int nch = K / HG_KC;

#define HCOPY_STAGE(s, chunk)                                                  \
    do {                                                                       \
        const int _k0 = (chunk) * HG_KC;                                       \
        const uint32_t _dA = sbase + (s) * HG_STAGE;                           \
        const uint32_t _dB = _dA + HG_TILE;                                    \
        _Pragma("unroll")                                                      \
        for (int e = 0; e < 2; e++) {                                          \
            const int cc = tid + e * 256;                                      \
            const int r = cc >> 2;                                             \
            const int q = cc & 3;                                              \
            CP_ASYNC16(_dA + r * HG_ROWB + q * 16,                             \
                       &A[(size_t)(m0 + r) * K + _k0 + q * 8]);                \
            CP_ASYNC16(_dB + r * HG_ROWB + q * 16,                             \
                       &Bt[(size_t)(n0 + r) * K + _k0 + q * 8]);               \
        }                                                                      \
    } while (0)

    HCOPY_STAGE(0, 0); CP_COMMIT();
    HCOPY_STAGE(1, 1); CP_COMMIT();
    HCOPY_STAGE(2, 2); CP_COMMIT();

    for (int c = 0; c < nch; ++c) {
        CP_WAIT2();
        __syncthreads();

        if (c + 3 < nch) {
            HCOPY_STAGE((c + 3) % HG_STAGES, c + 3);
        }
        CP_COMMIT();

        const int s = c % HG_STAGES;
        const uint32_t* SA = reinterpret_cast<const uint32_t*>(smem + s * HG_STAGE);
        const uint32_t* SB = reinterpret_cast<const uint32_t*>(smem + s * HG_STAGE + HG_TILE);

#pragma unroll
        for (int ks = 0; ks < 2; ks++) {
            const int kw = ks * 8 + tig;

            uint32_t afr[2][4];
#pragma unroll
            for (int mt = 0; mt < 2; mt++) {
                const int r = wm * 32 + mt * 16 + g;
                afr[mt][0] = SA[r * 20 + kw];
                afr[mt][1] = SA[(r + 8) * 20 + kw];
                afr[mt][2] = SA[r * 20 + kw + 4];
                afr[mt][3] = SA[(r + 8) * 20 + kw + 4];
            }
#pragma unroll
            for (int nt = 0; nt < 8; nt++) {
                const int n = wn * 64 + nt * 8 + g;
                const uint32_t b0 = SB[n * 20 + kw];
                const uint32_t b1 = SB[n * 20 + kw + 4];
                mma_f16(acc[0][nt], afr[0], b0, b1);
                mma_f16(acc[1][nt], afr[1], b0, b1);
            }
        }
        __syncthreads();
    }
#undef HCOPY_STAGE

#pragma unroll
    for (int mt = 0; mt < 2; mt++) {
        const int row0 = m0 + wm * 32 + mt * 16 + g;
#pragma unroll
        for (int nt = 0; nt < 8; nt++) {
            const int col = n0 + wn * 64 + nt * 8 + tig * 2;
            float l0 = acc[mt][nt][0];
            float l1 = acc[mt][nt][1];
            float h0 = acc[mt][nt][2];
            float h1 = acc[mt][nt][3];
            if constexpr (ACC) {
                // accumulate into existing fp32 C
                float2 cl = *reinterpret_cast<float2*>(&C[(size_t)row0 * N + col]);
                float2 ch = *reinterpret_cast<float2*>(&C[(size_t)(row0 + 8) * N + col]);
                cl.x += l0; cl.y += l1; ch.x += h0; ch.y += h1;
                *reinterpret_cast<float2*>(&C[(size_t)row0 * N + col]) = cl;
                *reinterpret_cast<float2*>(&C[(size_t)(row0 + 8) * N + col]) = ch;
            } else {
                const float bx = bias[col];
                const float by = bias[col + 1];
                l0 += bx; l1 += by; h0 += bx; h1 += by;
                if constexpr (sizeof(OutT) == 2) {
                    __half2* p0 = reinterpret_cast<__half2*>(&C[(size_t)row0 * N + col]);
                    __half2* p1 = reinterpret_cast<__half2*>(&C[(size_t)(row0 + 8) * N + col]);
                    *p0 = __floats2half2_rn(l0, l1);
                    *p1 = __floats2half2_rn(h0, h1);
                } else {
                    float2 lo, hi;
                    lo.x = l0; lo.y = l1; hi.x = h0; hi.y = h1;
                    *reinterpret_cast<float2*>(&C[(size_t)row0 * N + col]) = lo;
                    *reinterpret_cast<float2*>(&C[(size_t)(row0 + 8) * N + col]) = hi;
                }
            }
        }
    }
}

// ===========================================================================
// Prep kernels
// ===========================================================================
// W^T to fp16: out[n*R + k] = (half)in[k*C + n]
__global__ void transpose_h_kernel(const float* __restrict__ in,
                                   __half* __restrict__ out, int R, int C)
{
    __shared__ float tile[32][33];
    const int bx = blockIdx.x * 32;
    const int by = blockIdx.y * 32;
#pragma unroll
    for (int j = 0; j < 32; j += 8)
        tile[threadIdx.y + j][threadIdx.x] =
            in[(size_t)(by + threadIdx.y + j) * C + bx + threadIdx.x];
    __syncthreads();
#pragma unroll
    for (int j = 0; j < 32; j += 8)
        out[(size_t)(bx + threadIdx.y + j) * R + by + threadIdx.x] =
            __float2half_rn(tile[threadIdx.x][threadIdx.y + j]);
}

// fp32 -> fp16 (8 elements per thread)
__global__ void convert_h_kernel(const float4* __restrict__ in,
                                 uint2* __restrict__ out, int n8)
{
    const int i = blockIdx.x * 256 + threadIdx.x;
    if (i < n8) {
        const float4 a = in[2 * i];
        const float4 b = in[2 * i + 1];
        __half2 p0 = __floats2half2_rn(a.x, a.y);
        __half2 p1 = __floats2half2_rn(a.z, a.w);
        __half2 p2 = __floats2half2_rn(b.x, b.y);
        __half2 p3 = __floats2half2_rn(b.z, b.w);
        uint2 o;
        o.x = *reinterpret_cast<uint32_t*>(&p0);
        o.y = *reinterpret_cast<uint32_t*>(&p1);
        out[2 * i] = o;
        uint2 o2;
        o2.x = *reinterpret_cast<uint32_t*>(&p2);
        o2.y = *reinterpret_cast<uint32_t*>(&p3);
        out[2 * i + 1] = o2;
    }
}

// fp32 -> (hi fp16, lo fp16 residual), 4 elements per thread
__global__ void split_h_kernel(const float4* __restrict__ in,
                               uint2* __restrict__ hi, uint2* __restrict__ lo,
                               int n4)
{
    const int i = blockIdx.x * 256 + threadIdx.x;
    if (i < n4) {
        const float4 a = in[i];
        const __half hx = __float2half_rn(a.x), hy = __float2half_rn(a.y);
        const __half hz = __float2half_rn(a.z), hw = __float2half_rn(a.w);
        const __half lx = __float2half_rn(a.x - __half2float(hx));
        const __half ly = __float2half_rn(a.y - __half2float(hy));
        const __half lz = __float2half_rn(a.z - __half2float(hz));
        const __half lw = __float2half_rn(a.w - __half2float(hw));
        __half2 h0 = __halves2half2(hx, hy), h1 = __halves2half2(hz, hw);
        __half2 l0 = __halves2half2(lx, ly), l1 = __halves2half2(lz, lw);
        uint2 oh, ol;
        oh.x = *reinterpret_cast<uint32_t*>(&h0);
        oh.y = *reinterpret_cast<uint32_t*>(&h1);
        ol.x = *reinterpret_cast<uint32_t*>(&l0);
        ol.y = *reinterpret_cast<uint32_t*>(&l1);
        hi[i] = oh;
        lo[i] = ol;
    }
}

// Build split-transposed combined weight: wqt_{hi,lo}[n*512 + k] from
// Wq[k][n] = (n<64 ? W_off[k,n] : n<96 ? W_aw[k,n-64] : 0), plus bias.
__global__ void build_wq_split_kernel(const float* __restrict__ W_off,
                                      const float* __restrict__ W_aw,
                                      const float* __restrict__ b_off,
                                      const float* __restrict__ b_aw,
                                      __half* __restrict__ wqt_hi,
                                      __half* __restrict__ wqt_lo,
                                      float* __restrict__ bq)
{
    const int i = blockIdx.x * 256 + threadIdx.x;  // 128*512 = 65536
    if (i < 128 * DMODEL) {
        const int n = i / DMODEL;
        const int k = i - n * DMODEL;
        float w = 0.0f;
        if (n < 64)      w = W_off[k * 64 + n];
        else if (n < 96) w = W_aw[k * 32 + (n - 64)];
        const __half h = __float2half_rn(w);
        const __half l = __float2half_rn(w - __half2float(h));
        wqt_hi[i] = h;
        wqt_lo[i] = l;
    }
    if (i < 128) {
        float bv = 0.0f;
        if (i < 64)      bv = b_off[i];
        else if (i < 96) bv = b_aw[i - 64];
        bq[i] = bv;
    }
}

// ===========================================================================
// Deformable sampling: 128 threads; v and mid fp16, math fp32.
// Reads offaw[row][128] fp32: off pairs [0..63], logits [64..95].
// ===========================================================================
__global__ __launch_bounds__(128) void deform_kernel(
    const __half* __restrict__ v,
    const float* __restrict__ offaw,
    __half* __restrict__ mid)
{
    __shared__ float s_w0[NHEAD][NPNT];
    __shared__ float s_w1[NHEAD][NPNT];
    __shared__ int   s_i0[NHEAD][NPNT];
    __shared__ int   s_i1[NHEAD][NPNT];

    const int blk = blockIdx.x;
    const int b = blk / LSEQ;
    const int l = blk - b * LSEQ;
    const int t = threadIdx.x;

    if (t < NHEAD) {
        const int h = t;
        const float ref_y = (float)l / (float)(LSEQ - 1);
        const float* row = &offaw[(size_t)blk * 128];

        float lg[NPNT];
        float mx = -1e30f;
#pragma unroll
        for (int p = 0; p < NPNT; p++) {
            lg[p] = row[64 + h * NPNT + p];
            mx = fmaxf(mx, lg[p]);
        }
        float sum = 0.0f;
#pragma unroll
        for (int p = 0; p < NPNT; p++) { lg[p] = __expf(lg[p] - mx); sum += lg[p]; }
        const float inv = 1.0f / sum;

#pragma unroll
        for (int p = 0; p < NPNT; p++) {
            const float a = lg[p] * inv;
            const float ox = row[(h * NPNT + p) * 2 + 0];
            const float oy = row[(h * NPNT + p) * 2 + 1];
            const float locx = fminf(fmaxf(ox, 0.0f), 1.0f);
            const float locy = fminf(fmaxf(oy + ref_y, 0.0f), 1.0f);

            const float ix = ((locx + 1.0f) * (float)LSEQ - 1.0f) * 0.5f;
            const float iy = locy * 0.5f;
            const float ix0 = floorf(ix);
            const float fx = ix - ix0;
            const float iy0 = floorf(iy);
            const float fy = iy - iy0;
            const float ywt = (1.0f - fy) * (iy0 == 0.0f ? 1.0f : 0.0f)
                            + fy * ((iy0 + 1.0f) == 0.0f ? 1.0f : 0.0f);

            const int i0 = (int)ix0;
            const int i1 = i0 + 1;
            const float w = a * ywt;
            const bool v0 = (i0 >= 0) && (i0 < LSEQ);
            const bool v1 = (i1 >= 0) && (i1 < LSEQ);
            s_w0[h][p] = v0 ? w * (1.0f - fx) : 0.0f;
            s_w1[h][p] = v1 ? w * fx : 0.0f;
            s_i0[h][p] = min(max(i0, 0), LSEQ - 1);
            s_i1[h][p] = min(max(i1, 0), LSEQ - 1);
        }
    }
    __syncthreads();

    const int h  = t >> 4;
    const int c4 = t & 15;
    const uint2* vb = reinterpret_cast<const uint2*>(
        v + (size_t)b * LSEQ * DMODEL + h * CHEAD) + c4;

    float ax = 0.0f, ay = 0.0f, az = 0.0f, aw = 0.0f;
#pragma unroll
    for (int p = 0; p < NPNT; p++) {
        const float w0 = s_w0[h][p];
        const float w1 = s_w1[h][p];
        const uint2 u0 = vb[(size_t)s_i0[h][p] * (DMODEL / 4)];
        const uint2 u1 = vb[(size_t)s_i1[h][p] * (DMODEL / 4)];
        const float2 f00 = __half22float2(*reinterpret_cast<const __half2*>(&u0.x));
        const float2 f01 = __half22float2(*reinterpret_cast<const __half2*>(&u0.y));
        const float2 f10 = __half22float2(*reinterpret_cast<const __half2*>(&u1.x));
        const float2 f11 = __half22float2(*reinterpret_cast<const __half2*>(&u1.y));
        ax = fmaf(w0, f00.x, ax); ay = fmaf(w0, f00.y, ay);
        az = fmaf(w0, f01.x, az); aw = fmaf(w0, f01.y, aw);
        ax = fmaf(w1, f10.x, ax); ay = fmaf(w1, f10.y, ay);
        az = fmaf(w1, f11.x, az); aw = fmaf(w1, f11.y, aw);
    }
    __half2 o0 = __floats2half2_rn(ax, ay);
    __half2 o1 = __floats2half2_rn(az, aw);
    uint2 o;
    o.x = *reinterpret_cast<uint32_t*>(&o0);
    o.y = *reinterpret_cast<uint32_t*>(&o1);
    *reinterpret_cast<uint2*>(&mid[(size_t)blk * DMODEL + h * CHEAD + c4 * 4]) = o;
}

// ===========================================================================
// Host launch — fork/join; off/aw via 3-pass split-fp16 tensor GEMM
// ===========================================================================
extern "C" void kernel_launch(void* const* d_in, const int* in_sizes, int n_in,
                              void* d_out, int out_size)
{
    const float* query = (const float*)d_in[0];
    const float* value = (const float*)d_in[2];
    const float* W_v   = (const float*)d_in[3];
    const float* b_v   = (const float*)d_in[4];
    const float* W_off = (const float*)d_in[5];
    const float* b_off = (const float*)d_in[6];
    const float* W_aw  = (const float*)d_in[7];
    const float* b_aw  = (const float*)d_in[8];
    const float* W_out = (const float*)d_in[9];
    const float* b_out = (const float*)d_in[10];
    float* out = (float*)d_out;

    __half *pv, *pva, *pmid, *pwvt, *pwot, *pqhi, *pqlo, *pwqh, *pwql;
    float *poffaw, *pbq;
    cudaGetSymbolAddress((void**)&pv,     g_v);
    cudaGetSymbolAddress((void**)&pva,    g_va);
    cudaGetSymbolAddress((void**)&pmid,   g_mid);
    cudaGetSymbolAddress((void**)&poffaw, g_offaw);
    cudaGetSymbolAddress((void**)&pwvt,   g_wvt);
    cudaGetSymbolAddress((void**)&pwot,   g_wot);
    cudaGetSymbolAddress((void**)&pqhi,   g_qhi);
    cudaGetSymbolAddress((void**)&pqlo,   g_qlo);
    cudaGetSymbolAddress((void**)&pwqh,   g_wqt_hi);
    cudaGetSymbolAddress((void**)&pwql,   g_wqt_lo);
    cudaGetSymbolAddress((void**)&pbq,    g_bq);

    cudaFuncSetAttribute((const void*)gemm_async_h_kernel<__half, false>,
                         cudaFuncAttributeMaxDynamicSharedMemorySize, HG_SMEM);
    cudaFuncSetAttribute((const void*)gemm_async_h_kernel<float, false>,
                         cudaFuncAttributeMaxDynamicSharedMemorySize, HG_SMEM);
    cudaFuncSetAttribute((const void*)gemm_async_h_kernel<float, true>,
                         cudaFuncAttributeMaxDynamicSharedMemorySize, HG_SMEM);

    // Fork.
    cudaEventRecord(g_ev0, 0);
    cudaStreamWaitEvent(g_s1, g_ev0, 0);
    cudaStreamWaitEvent(g_s2, g_ev0, 0);

    // --- s1: off/aw chain via split-fp16 tensor GEMM + W_out transpose ---
    build_wq_split_kernel<<<(128 * DMODEL + 255) / 256, 256, 0, g_s1>>>(
        W_off, W_aw, b_off, b_aw, pwqh, pwql, pbq);
    split_h_kernel<<<(MROWS * DMODEL / 4 + 255) / 256, 256, 0, g_s1>>>(
        (const float4*)query, (uint2*)pqhi, (uint2*)pqlo, MROWS * DMODEL / 4);
    {
        dim3 grid(1, MROWS / 128);
        // pass 1: q_hi @ Wq_hi + bq
        gemm_async_h_kernel<float, false><<<grid, 256, HG_SMEM, g_s1>>>(
            pqhi, pwqh, pbq, poffaw, MROWS, 128, DMODEL);
        // pass 2: += q_hi @ Wq_lo
        gemm_async_h_kernel<float, true><<<grid, 256, HG_SMEM, g_s1>>>(
            pqhi, pwql, pbq, poffaw, MROWS, 128, DMODEL);
        // pass 3: += q_lo @ Wq_hi
        gemm_async_h_kernel<float, true><<<grid, 256, HG_SMEM, g_s1>>>(
            pqlo, pwqh, pbq, poffaw, MROWS, 128, DMODEL);
    }
    {
        dim3 tb(32, 8);
        dim3 tg(DMODEL / 32, DMODEL / 32);
        transpose_h_kernel<<<tg, tb, 0, g_s1>>>(W_out, pwot, DMODEL, DMODEL);
    }
    cudaEventRecord(g_ev1, g_s1);

    // --- s2: convert value to fp16 ---
    convert_h_kernel<<<(MROWS * DMODEL / 8 + 255) / 256, 256, 0, g_s2>>>(
        (const float4*)value, (uint2*)pva, MROWS * DMODEL / 8);
    cudaEventRecord(g_ev2, g_s2);

    // --- s0 (origin): W_v transpose, then v-GEMM once convert is done ---
    {
        dim3 tb(32, 8);
        dim3 tg(DMODEL / 32, DMODEL / 32);
        transpose_h_kernel<<<tg, tb>>>(W_v, pwvt, DMODEL, DMODEL);
    }
    cudaStreamWaitEvent(0, g_ev2, 0);
    {
        dim3 grid(DMODEL / 128, MROWS / 128);
        gemm_async_h_kernel<__half, false><<<grid, 256, HG_SMEM>>>(
            pva, pwvt, b_v, pv, MROWS, DMODEL, DMODEL);
    }

    // Join: deform needs the off/aw chain too.
    cudaStreamWaitEvent(0, g_ev1, 0);
    deform_kernel<<<MROWS, 128>>>(pv, poffaw, pmid);

    // --- out = mid @ W_out + b_out (fp16 mma, fp32 out) ---
    {
        dim3 grid(DMODEL / 128, MROWS / 128);
        gemm_async_h_kernel<float, false><<<grid, 256, HG_SMEM>>>(
            pmid, pwot, b_out, out, MROWS, DMODEL, DMODEL);
    }
}

// round 10
// speedup vs baseline: 4.3435x; 1.1133x over previous
#include <cuda_runtime.h>
#include <cuda_fp16.h>
#include <math.h>
#include <stdint.h>

// Problem constants
#define BATCH 8
#define LSEQ  2048
#define DMODEL 512
#define NHEAD 8
#define NPNT  4
#define CHEAD 64
#define MROWS (BATCH * LSEQ)   // 16384

// Scratch (device globals; no allocation allowed)
__device__ __align__(16) __half g_v[MROWS * DMODEL];      // value projection (fp16)
__device__ __align__(16) __half g_va[MROWS * DMODEL];     // value, fp16
__device__ __align__(16) __half g_mid[MROWS * DMODEL];    // deform output (fp16)
__device__ __align__(16) float  g_offaw[MROWS * 128];     // off(64)|aw(32)|pad, fp32
__device__ __align__(16) __half g_wvt[DMODEL * DMODEL];   // W_v^T   fp16 [N][K]
__device__ __align__(16) __half g_wot[DMODEL * DMODEL];   // W_out^T fp16 [N][K]
__device__ __align__(16) __half g_qhi[MROWS * DMODEL];    // query hi fp16
__device__ __align__(16) __half g_qlo[MROWS * DMODEL];    // query lo fp16 (residual)
__device__ __align__(16) __half g_wqt_hi[128 * DMODEL];   // Wq^T hi fp16 [128][512]
__device__ __align__(16) __half g_wqt_lo[128 * DMODEL];   // Wq^T lo fp16
__device__ __align__(16) float  g_bq[128];

// Streams/events for fork-join overlap (created once at module load).
static cudaStream_t g_s1, g_s2;
static cudaEvent_t g_ev0, g_ev1, g_ev2;
namespace {
struct StreamInit {
    StreamInit() {
        cudaStreamCreateWithFlags(&g_s1, cudaStreamNonBlocking);
        cudaStreamCreateWithFlags(&g_s2, cudaStreamNonBlocking);
        cudaEventCreateWithFlags(&g_ev0, cudaEventDisableTiming);
        cudaEventCreateWithFlags(&g_ev1, cudaEventDisableTiming);
        cudaEventCreateWithFlags(&g_ev2, cudaEventDisableTiming);
    }
};
StreamInit g_stream_init;
}

__device__ __forceinline__ uint32_t smem_u32(const void* p) {
    uint32_t a;
    asm("{ .reg .u64 t; cvta.to.shared.u64 t, %1; cvt.u32.u64 %0, t; }" : "=r"(a) : "l"(p));
    return a;
}

__device__ __forceinline__ void mma_f16(float c[4],
                                        const uint32_t a[4],
                                        uint32_t b0, uint32_t b1) {
    asm volatile(
        "mma.sync.aligned.m16n8k16.row.col.f32.f16.f16.f32 "
        "{%0,%1,%2,%3}, {%4,%5,%6,%7}, {%8,%9}, {%0,%1,%2,%3};"
        : "+f"(c[0]), "+f"(c[1]), "+f"(c[2]), "+f"(c[3])
        : "r"(a[0]), "r"(a[1]), "r"(a[2]), "r"(a[3]), "r"(b0), "r"(b1));
}

#define CP_ASYNC16(dst, src) \
    asm volatile("cp.async.cg.shared.global [%0], [%1], 16;" :: "r"(dst), "l"(src) : "memory")
#define CP_COMMIT() asm volatile("cp.async.commit_group;" ::: "memory")
#define CP_WAIT1()  asm volatile("cp.async.wait_group 1;" ::: "memory")
#define CP_WAIT2()  asm volatile("cp.async.wait_group 2;" ::: "memory")

// ===========================================================================
// Async fp16 GEMM: C[M,N] = A[M,K] @ Bt[N,K]^T + bias[N]
// 128x128 tile, 256 thr, KC=32, 4 stages; smem row stride 80B (conflict-free).
// ===========================================================================
#define HG_KC 32
#define HG_ROWB 80
#define HG_TILE (128 * HG_ROWB)
#define HG_STAGE (2 * HG_TILE)
#define HG_STAGES 4
#define HG_SMEM (HG_STAGES * HG_STAGE)  // 81920 B

template <typename OutT>
__global__ __launch_bounds__(256, 2)
void gemm_async_h_kernel(const __half* __restrict__ A, const __half* __restrict__ Bt,
                         const float* __restrict__ bias, OutT* __restrict__ C,
                         int M, int N, int K)
{
    extern __shared__ char smem[];
    const uint32_t sbase = smem_u32(smem);

    const int tid  = threadIdx.x;
    const int wid  = tid >> 5;
    const int lane = tid & 31;
    const int g    = lane >> 2;
    const int tig  = lane & 3;
    const int wm   = wid & 3;
    const int wn   = wid >> 2;

    const int m0 = blockIdx.y * 128;
    const int n0 = blockIdx.x * 128;

    float acc[2][8][4];
#pragma unroll
    for (int mt = 0; mt < 2; mt++)
#pragma unroll
        for (int nt = 0; nt < 8; nt++)
#pragma unroll
            for (int j = 0; j < 4; j++) acc[mt][nt][j] = 0.0f;

    const int nch = K / HG_KC;

#define HCOPY_STAGE(s, chunk)                                                  \
    do {                                                                       \
        const int _k0 = (chunk) * HG_KC;                                       \
        const uint32_t _dA = sbase + (s) * HG_STAGE;                           \
        const uint32_t _dB = _dA + HG_TILE;                                    \
        _Pragma("unroll")                                                      \
        for (int e = 0; e < 2; e++) {                                          \
            const int cc = tid + e * 256;                                      \
            const int r = cc >> 2;                                             \
            const int q = cc & 3;                                              \
            CP_ASYNC16(_dA + r * HG_ROWB + q * 16,                             \
                       &A[(size_t)(m0 + r) * K + _k0 + q * 8]);                \
            CP_ASYNC16(_dB + r * HG_ROWB + q * 16,                             \
                       &Bt[(size_t)(n0 + r) * K + _k0 + q * 8]);               \
        }                                                                      \
    } while (0)

    HCOPY_STAGE(0, 0); CP_COMMIT();
    HCOPY_STAGE(1, 1); CP_COMMIT();
    HCOPY_STAGE(2, 2); CP_COMMIT();

    for (int c = 0; c < nch; ++c) {
        CP_WAIT2();
        __syncthreads();

        if (c + 3 < nch) {
            HCOPY_STAGE((c + 3) % HG_STAGES, c + 3);
        }
        CP_COMMIT();

        const int s = c % HG_STAGES;
        const uint32_t* SA = reinterpret_cast<const uint32_t*>(smem + s * HG_STAGE);
        const uint32_t* SB = reinterpret_cast<const uint32_t*>(smem + s * HG_STAGE + HG_TILE);

#pragma unroll
        for (int ks = 0; ks < 2; ks++) {
            const int kw = ks * 8 + tig;

            uint32_t afr[2][4];
#pragma unroll
            for (int mt = 0; mt < 2; mt++) {
                const int r = wm * 32 + mt * 16 + g;
                afr[mt][0] = SA[r * 20 + kw];
                afr[mt][1] = SA[(r + 8) * 20 + kw];
                afr[mt][2] = SA[r * 20 + kw + 4];
                afr[mt][3] = SA[(r + 8) * 20 + kw + 4];
            }
#pragma unroll
            for (int nt = 0; nt < 8; nt++) {
                const int n = wn * 64 + nt * 8 + g;
                const uint32_t b0 = SB[n * 20 + kw];
                const uint32_t b1 = SB[n * 20 + kw + 4];
                mma_f16(acc[0][nt], afr[0], b0, b1);
                mma_f16(acc[1][nt], afr[1], b0, b1);
            }
        }
        __syncthreads();
    }
#undef HCOPY_STAGE

#pragma unroll
    for (int mt = 0; mt < 2; mt++) {
        const int row0 = m0 + wm * 32 + mt * 16 + g;
#pragma unroll
        for (int nt = 0; nt < 8; nt++) {
            const int col = n0 + wn * 64 + nt * 8 + tig * 2;
            const float bx = bias[col];
            const float by = bias[col + 1];
            const float l0 = acc[mt][nt][0] + bx;
            const float l1 = acc[mt][nt][1] + by;
            const float h0 = acc[mt][nt][2] + bx;
            const float h1 = acc[mt][nt][3] + by;
            if constexpr (sizeof(OutT) == 2) {
                __half2* p0 = reinterpret_cast<__half2*>(&C[(size_t)row0 * N + col]);
                __half2* p1 = reinterpret_cast<__half2*>(&C[(size_t)(row0 + 8) * N + col]);
                *p0 = __floats2half2_rn(l0, l1);
                *p1 = __floats2half2_rn(h0, h1);
            } else {
                float2 lo, hi;
                lo.x = l0; lo.y = l1; hi.x = h0; hi.y = h1;
                *reinterpret_cast<float2*>(&C[(size_t)row0 * N + col]) = lo;
                *reinterpret_cast<float2*>(&C[(size_t)(row0 + 8) * N + col]) = hi;
            }
        }
    }
}

// ===========================================================================
// Fused split-fp16 off/aw GEMM:
// C[M,128] = (Ah+Al)[M,512] @ (Bh+Bl)[128,512]^T + bias  (drops al@bl term)
// Stages Ah, Al, Bh, Bl per chunk; 3 MMAs per fragment pair into one fp32 acc.
// 3 stages x 40KB = 120KB smem, 1 CTA/SM, grid (1, M/128).
// ===========================================================================
#define FG_TILE HG_TILE                  // 10240 B per tensor tile
#define FG_STAGE (4 * FG_TILE)           // 40960 B
#define FG_STAGES 3
#define FG_SMEM (FG_STAGES * FG_STAGE)   // 122880 B

__global__ __launch_bounds__(256, 1)
void gemm_offaw_fused_kernel(const __half* __restrict__ Ah, const __half* __restrict__ Al,
                             const __half* __restrict__ Bh, const __half* __restrict__ Bl,
                             const float* __restrict__ bias, float* __restrict__ C,
                             int M, int K)
{
    extern __shared__ char smem[];
    const uint32_t sbase = smem_u32(smem);
    const int N = 128;

    const int tid  = threadIdx.x;
    const int wid  = tid >> 5;
    const int lane = tid & 31;
    const int g    = lane >> 2;
    const int tig  = lane & 3;
    const int wm   = wid & 3;
    const int wn   = wid >> 2;

    const int m0 = blockIdx.y * 128;

    float acc[2][8][4];
#pragma unroll
    for (int mt = 0; mt < 2; mt++)
#pragma unroll
        for (int nt = 0; nt < 8; nt++)
#pragma unroll
            for (int j = 0; j < 4; j++) acc[mt][nt][j] = 0.0f;

    const int nch = K / HG_KC;   // 16

#define FCOPY_STAGE(s, chunk)                                                  \
    do {                                                                       \
        const int _k0 = (chunk) * HG_KC;                                       \
        const uint32_t _d0 = sbase + (s) * FG_STAGE;                           \
        _Pragma("unroll")                                                      \
        for (int e = 0; e < 2; e++) {                                          \
            const int cc = tid + e * 256;                                      \
            const int r = cc >> 2;                                             \
            const int q = cc & 3;                                              \
            const uint32_t od = r * HG_ROWB + q * 16;                          \
            const size_t oa = (size_t)(m0 + r) * K + _k0 + q * 8;              \
            const size_t ob = (size_t)r * K + _k0 + q * 8;                     \
            CP_ASYNC16(_d0 + od,                 &Ah[oa]);                     \
            CP_ASYNC16(_d0 + FG_TILE + od,       &Al[oa]);                     \
            CP_ASYNC16(_d0 + 2 * FG_TILE + od,   &Bh[ob]);                     \
            CP_ASYNC16(_d0 + 3 * FG_TILE + od,   &Bl[ob]);                     \
        }                                                                      \
    } while (0)

    FCOPY_STAGE(0, 0); CP_COMMIT();
    FCOPY_STAGE(1, 1); CP_COMMIT();

    for (int c = 0; c < nch; ++c) {
        CP_WAIT1();
        __syncthreads();

        if (c + 2 < nch) {
            FCOPY_STAGE((c + 2) % FG_STAGES, c + 2);
        }
        CP_COMMIT();

        const int s = c % FG_STAGES;
        const uint32_t* SAh = reinterpret_cast<const uint32_t*>(smem + s * FG_STAGE);
        const uint32_t* SAl = SAh + FG_TILE / 4;
        const uint32_t* SBh = SAh + 2 * (FG_TILE / 4);
        const uint32_t* SBl = SAh + 3 * (FG_TILE / 4);

#pragma unroll
        for (int ks = 0; ks < 2; ks++) {
            const int kw = ks * 8 + tig;

            uint32_t ah[2][4], al[2][4];
#pragma unroll
            for (int mt = 0; mt < 2; mt++) {
                const int r = wm * 32 + mt * 16 + g;
                ah[mt][0] = SAh[r * 20 + kw];
                ah[mt][1] = SAh[(r + 8) * 20 + kw];
                ah[mt][2] = SAh[r * 20 + kw + 4];
                ah[mt][3] = SAh[(r + 8) * 20 + kw + 4];
                al[mt][0] = SAl[r * 20 + kw];
                al[mt][1] = SAl[(r + 8) * 20 + kw];
                al[mt][2] = SAl[r * 20 + kw + 4];
                al[mt][3] = SAl[(r + 8) * 20 + kw + 4];
            }
#pragma unroll
            for (int nt = 0; nt < 8; nt++) {
                const int n = wn * 64 + nt * 8 + g;
                const uint32_t bh0 = SBh[n * 20 + kw];
                const uint32_t bh1 = SBh[n * 20 + kw + 4];
                const uint32_t bl0 = SBl[n * 20 + kw];
                const uint32_t bl1 = SBl[n * 20 + kw + 4];
#pragma unroll
                for (int mt = 0; mt < 2; mt++) {
                    mma_f16(acc[mt][nt], ah[mt], bh0, bh1);   // hi@hi
                    mma_f16(acc[mt][nt], ah[mt], bl0, bl1);   // hi@lo
                    mma_f16(acc[mt][nt], al[mt], bh0, bh1);   // lo@hi
                }
            }
        }
        __syncthreads();
    }
#undef FCOPY_STAGE

#pragma unroll
    for (int mt = 0; mt < 2; mt++) {
        const int row0 = m0 + wm * 32 + mt * 16 + g;
#pragma unroll
        for (int nt = 0; nt < 8; nt++) {
            const int col = wn * 64 + nt * 8 + tig * 2;
            const float bx = bias[col];
            const float by = bias[col + 1];
            float2 lo, hi;
            lo.x = acc[mt][nt][0] + bx;  lo.y = acc[mt][nt][1] + by;
            hi.x = acc[mt][nt][2] + bx;  hi.y = acc[mt][nt][3] + by;
            *reinterpret_cast<float2*>(&C[(size_t)row0 * N + col]) = lo;
            *reinterpret_cast<float2*>(&C[(size_t)(row0 + 8) * N + col]) = hi;
        }
    }
}

// ===========================================================================
// Prep kernels
// ===========================================================================
__global__ void transpose_h_kernel(const float* __restrict__ in,
                                   __half* __restrict__ out, int R, int C)
{
    __shared__ float tile[32][33];
    const int bx = blockIdx.x * 32;
    const int by = blockIdx.y * 32;
#pragma unroll
    for (int j = 0; j < 32; j += 8)
        tile[threadIdx.y + j][threadIdx.x] =
            in[(size_t)(by + threadIdx.y + j) * C + bx + threadIdx.x];
    __syncthreads();
#pragma unroll
    for (int j = 0; j < 32; j += 8)
        out[(size_t)(bx + threadIdx.y + j) * R + by + threadIdx.x] =
            __float2half_rn(tile[threadIdx.x][threadIdx.y + j]);
}

__global__ void convert_h_kernel(const float4* __restrict__ in,
                                 uint2* __restrict__ out, int n8)
{
    const int i = blockIdx.x * 256 + threadIdx.x;
    if (i < n8) {
        const float4 a = in[2 * i];
        const float4 b = in[2 * i + 1];
        __half2 p0 = __floats2half2_rn(a.x, a.y);
        __half2 p1 = __floats2half2_rn(a.z, a.w);
        __half2 p2 = __floats2half2_rn(b.x, b.y);
        __half2 p3 = __floats2half2_rn(b.z, b.w);
        uint2 o;
        o.x = *reinterpret_cast<uint32_t*>(&p0);
        o.y = *reinterpret_cast<uint32_t*>(&p1);
        out[2 * i] = o;
        uint2 o2;
        o2.x = *reinterpret_cast<uint32_t*>(&p2);
        o2.y = *reinterpret_cast<uint32_t*>(&p3);
        out[2 * i + 1] = o2;
    }
}

__global__ void split_h_kernel(const float4* __restrict__ in,
                               uint2* __restrict__ hi, uint2* __restrict__ lo,
                               int n4)
{
    const int i = blockIdx.x * 256 + threadIdx.x;
    if (i < n4) {
        const float4 a = in[i];
        const __half hx = __float2half_rn(a.x), hy = __float2half_rn(a.y);
        const __half hz = __float2half_rn(a.z), hw = __float2half_rn(a.w);
        const __half lx = __float2half_rn(a.x - __half2float(hx));
        const __half ly = __float2half_rn(a.y - __half2float(hy));
        const __half lz = __float2half_rn(a.z - __half2float(hz));
        const __half lw = __float2half_rn(a.w - __half2float(hw));
        __half2 h0 = __halves2half2(hx, hy), h1 = __halves2half2(hz, hw);
        __half2 l0 = __halves2half2(lx, ly), l1 = __halves2half2(lz, lw);
        uint2 oh, ol;
        oh.x = *reinterpret_cast<uint32_t*>(&h0);
        oh.y = *reinterpret_cast<uint32_t*>(&h1);
        ol.x = *reinterpret_cast<uint32_t*>(&l0);
        ol.y = *reinterpret_cast<uint32_t*>(&l1);
        hi[i] = oh;
        lo[i] = ol;
    }
}

__global__ void build_wq_split_kernel(const float* __restrict__ W_off,
                                      const float* __restrict__ W_aw,
                                      const float* __restrict__ b_off,
                                      const float* __restrict__ b_aw,
                                      __half* __restrict__ wqt_hi,
                                      __half* __restrict__ wqt_lo,
                                      float* __restrict__ bq)
{
    const int i = blockIdx.x * 256 + threadIdx.x;
    if (i < 128 * DMODEL) {
        const int n = i / DMODEL;
        const int k = i - n * DMODEL;
        float w = 0.0f;
        if (n < 64)      w = W_off[k * 64 + n];
        else if (n < 96) w = W_aw[k * 32 + (n - 64)];
        const __half h = __float2half_rn(w);
        const __half l = __float2half_rn(w - __half2float(h));
        wqt_hi[i] = h;
        wqt_lo[i] = l;
    }
    if (i < 128) {
        float bv = 0.0f;
        if (i < 64)      bv = b_off[i];
        else if (i < 96) bv = b_aw[i - 64];
        bq[i] = bv;
    }
}

// ===========================================================================
// Deformable sampling: 128 threads; v and mid fp16, math fp32.
// ===========================================================================
__global__ __launch_bounds__(128) void deform_kernel(
    const __half* __restrict__ v,
    const float* __restrict__ offaw,
    __half* __restrict__ mid)
{
    __shared__ float s_w0[NHEAD][NPNT];
    __shared__ float s_w1[NHEAD][NPNT];
    __shared__ int   s_i0[NHEAD][NPNT];
    __shared__ int   s_i1[NHEAD][NPNT];

    const int blk = blockIdx.x;
    const int b = blk / LSEQ;
    const int l = blk - b * LSEQ;
    const int t = threadIdx.x;

    if (t < NHEAD) {
        const int h = t;
        const float ref_y = (float)l / (float)(LSEQ - 1);
        const float* row = &offaw[(size_t)blk * 128];

        float lg[NPNT];
        float mx = -1e30f;
#pragma unroll
        for (int p = 0; p < NPNT; p++) {
            lg[p] = row[64 + h * NPNT + p];
            mx = fmaxf(mx, lg[p]);
        }
        float sum = 0.0f;
#pragma unroll
        for (int p = 0; p < NPNT; p++) { lg[p] = __expf(lg[p] - mx); sum += lg[p]; }
        const float inv = 1.0f / sum;

#pragma unroll
        for (int p = 0; p < NPNT; p++) {
            const float a = lg[p] * inv;
            const float ox = row[(h * NPNT + p) * 2 + 0];
            const float oy = row[(h * NPNT + p) * 2 + 1];
            const float locx = fminf(fmaxf(ox, 0.0f), 1.0f);
            const float locy = fminf(fmaxf(oy + ref_y, 0.0f), 1.0f);

            const float ix = ((locx + 1.0f) * (float)LSEQ - 1.0f) * 0.5f;
            const float iy = locy * 0.5f;
            const float ix0 = floorf(ix);
            const float fx = ix - ix0;
            const float iy0 = floorf(iy);
            const float fy = iy - iy0;
            const float ywt = (1.0f - fy) * (iy0 == 0.0f ? 1.0f : 0.0f)
                            + fy * ((iy0 + 1.0f) == 0.0f ? 1.0f : 0.0f);

            const int i0 = (int)ix0;
            const int i1 = i0 + 1;
            const float w = a * ywt;
            const bool v0 = (i0 >= 0) && (i0 < LSEQ);
            const bool v1 = (i1 >= 0) && (i1 < LSEQ);
            s_w0[h][p] = v0 ? w * (1.0f - fx) : 0.0f;
            s_w1[h][p] = v1 ? w * fx : 0.0f;
            s_i0[h][p] = min(max(i0, 0), LSEQ - 1);
            s_i1[h][p] = min(max(i1, 0), LSEQ - 1);
        }
    }
    __syncthreads();

    const int h  = t >> 4;
    const int c4 = t & 15;
    const uint2* vb = reinterpret_cast<const uint2*>(
        v + (size_t)b * LSEQ * DMODEL + h * CHEAD) + c4;

    float ax = 0.0f, ay = 0.0f, az = 0.0f, aw = 0.0f;
#pragma unroll
    for (int p = 0; p < NPNT; p++) {
        const float w0 = s_w0[h][p];
        const float w1 = s_w1[h][p];
        const uint2 u0 = vb[(size_t)s_i0[h][p] * (DMODEL / 4)];
        const uint2 u1 = vb[(size_t)s_i1[h][p] * (DMODEL / 4)];
        const float2 f00 = __half22float2(*reinterpret_cast<const __half2*>(&u0.x));
        const float2 f01 = __half22float2(*reinterpret_cast<const __half2*>(&u0.y));
        const float2 f10 = __half22float2(*reinterpret_cast<const __half2*>(&u1.x));
        const float2 f11 = __half22float2(*reinterpret_cast<const __half2*>(&u1.y));
        ax = fmaf(w0, f00.x, ax); ay = fmaf(w0, f00.y, ay);
        az = fmaf(w0, f01.x, az); aw = fmaf(w0, f01.y, aw);
        ax = fmaf(w1, f10.x, ax); ay = fmaf(w1, f10.y, ay);
        az = fmaf(w1, f11.x, az); aw = fmaf(w1, f11.y, aw);
    }
    __half2 o0 = __floats2half2_rn(ax, ay);
    __half2 o1 = __floats2half2_rn(az, aw);
    uint2 o;
    o.x = *reinterpret_cast<uint32_t*>(&o0);
    o.y = *reinterpret_cast<uint32_t*>(&o1);
    *reinterpret_cast<uint2*>(&mid[(size_t)blk * DMODEL + h * CHEAD + c4 * 4]) = o;
}

// ===========================================================================
// Host launch — fork/join; off/aw via fused split-fp16 tensor GEMM
// ===========================================================================
extern "C" void kernel_launch(void* const* d_in, const int* in_sizes, int n_in,
                              void* d_out, int out_size)
{
    const float* query = (const float*)d_in[0];
    const float* value = (const float*)d_in[2];
    const float* W_v   = (const float*)d_in[3];
    const float* b_v   = (const float*)d_in[4];
    const float* W_off = (const float*)d_in[5];
    const float* b_off = (const float*)d_in[6];
    const float* W_aw  = (const float*)d_in[7];
    const float* b_aw  = (const float*)d_in[8];
    const float* W_out = (const float*)d_in[9];
    const float* b_out = (const float*)d_in[10];
    float* out = (float*)d_out;

    __half *pv, *pva, *pmid, *pwvt, *pwot, *pqhi, *pqlo, *pwqh, *pwql;
    float *poffaw, *pbq;
    cudaGetSymbolAddress((void**)&pv,     g_v);
    cudaGetSymbolAddress((void**)&pva,    g_va);
    cudaGetSymbolAddress((void**)&pmid,   g_mid);
    cudaGetSymbolAddress((void**)&poffaw, g_offaw);
    cudaGetSymbolAddress((void**)&pwvt,   g_wvt);
    cudaGetSymbolAddress((void**)&pwot,   g_wot);
    cudaGetSymbolAddress((void**)&pqhi,   g_qhi);
    cudaGetSymbolAddress((void**)&pqlo,   g_qlo);
    cudaGetSymbolAddress((void**)&pwqh,   g_wqt_hi);
    cudaGetSymbolAddress((void**)&pwql,   g_wqt_lo);
    cudaGetSymbolAddress((void**)&pbq,    g_bq);

    cudaFuncSetAttribute((const void*)gemm_async_h_kernel<__half>,
                         cudaFuncAttributeMaxDynamicSharedMemorySize, HG_SMEM);
    cudaFuncSetAttribute((const void*)gemm_async_h_kernel<float>,
                         cudaFuncAttributeMaxDynamicSharedMemorySize, HG_SMEM);
    cudaFuncSetAttribute((const void*)gemm_offaw_fused_kernel,
                         cudaFuncAttributeMaxDynamicSharedMemorySize, FG_SMEM);

    // Fork.
    cudaEventRecord(g_ev0, 0);
    cudaStreamWaitEvent(g_s1, g_ev0, 0);
    cudaStreamWaitEvent(g_s2, g_ev0, 0);

    // --- s1: off/aw chain via fused split-fp16 tensor GEMM + W_out transpose ---
    build_wq_split_kernel<<<(128 * DMODEL + 255) / 256, 256, 0, g_s1>>>(
        W_off, W_aw, b_off, b_aw, pwqh, pwql, pbq);
    split_h_kernel<<<(MROWS * DMODEL / 4 + 255) / 256, 256, 0, g_s1>>>(
        (const float4*)query, (uint2*)pqhi, (uint2*)pqlo, MROWS * DMODEL / 4);
    {
        dim3 grid(1, MROWS / 128);
        gemm_offaw_fused_kernel<<<grid, 256, FG_SMEM, g_s1>>>(
            pqhi, pqlo, pwqh, pwql, pbq, poffaw, MROWS, DMODEL);
    }
    {
        dim3 tb(32, 8);
        dim3 tg(DMODEL / 32, DMODEL / 32);
        transpose_h_kernel<<<tg, tb, 0, g_s1>>>(W_out, pwot, DMODEL, DMODEL);
    }
    cudaEventRecord(g_ev1, g_s1);

    // --- s2: convert value to fp16 ---
    convert_h_kernel<<<(MROWS * DMODEL / 8 + 255) / 256, 256, 0, g_s2>>>(
        (const float4*)value, (uint2*)pva, MROWS * DMODEL / 8);
    cudaEventRecord(g_ev2, g_s2);

    // --- s0 (origin): W_v transpose, then v-GEMM once convert is done ---
    {
        dim3 tb(32, 8);
        dim3 tg(DMODEL / 32, DMODEL / 32);
        transpose_h_kernel<<<tg, tb>>>(W_v, pwvt, DMODEL, DMODEL);
    }
    cudaStreamWaitEvent(0, g_ev2, 0);
    {
        dim3 grid(DMODEL / 128, MROWS / 128);
        gemm_async_h_kernel<__half><<<grid, 256, HG_SMEM>>>(
            pva, pwvt, b_v, pv, MROWS, DMODEL, DMODEL);
    }

    // Join: deform needs the off/aw chain too.
    cudaStreamWaitEvent(0, g_ev1, 0);
    deform_kernel<<<MROWS, 128>>>(pv, poffaw, pmid);

    // --- out = mid @ W_out + b_out (fp16 mma, fp32 out) ---
    {
        dim3 grid(DMODEL / 128, MROWS / 128);
        gemm_async_h_kernel<float><<<grid, 256, HG_SMEM>>>(
            pmid, pwot, b_out, out, MROWS, DMODEL, DMODEL);
    }
}

// round 11
// speedup vs baseline: 4.7432x; 1.0920x over previous
#include <cuda_runtime.h>
#include <cuda_fp16.h>
#include <math.h>
#include <stdint.h>

// Problem constants
#define BATCH 8
#define LSEQ  2048
#define DMODEL 512
#define NHEAD 8
#define NPNT  4
#define CHEAD 64
#define MROWS (BATCH * LSEQ)   // 16384

// Scratch (device globals; no allocation allowed)
__device__ __align__(16) __half g_v[MROWS * DMODEL];      // value projection (fp16)
__device__ __align__(16) __half g_va[MROWS * DMODEL];     // value, fp16
__device__ __align__(16) __half g_mid[MROWS * DMODEL];    // deform output (fp16)
__device__ __align__(16) float  g_offaw[MROWS * 128];     // off(64)|aw(32)|pad, fp32
__device__ __align__(16) __half g_wvt[DMODEL * DMODEL];   // W_v^T   fp16 [N][K]
__device__ __align__(16) __half g_wot[DMODEL * DMODEL];   // W_out^T fp16 [N][K]
__device__ __align__(16) __half g_qhi[MROWS * DMODEL];    // query hi fp16
__device__ __align__(16) __half g_qlo[MROWS * DMODEL];    // query lo fp16 (residual)
__device__ __align__(16) __half g_wqt_hi[128 * DMODEL];   // Wq^T hi fp16 [128][512]
__device__ __align__(16) __half g_wqt_lo[128 * DMODEL];   // Wq^T lo fp16
__device__ __align__(16) float  g_bq[128];

// Streams/events for fork-join overlap (created once at module load).
static cudaStream_t g_s1, g_s2;
static cudaEvent_t g_ev0, g_ev1, g_ev2;
namespace {
struct StreamInit {
    StreamInit() {
        cudaStreamCreateWithFlags(&g_s1, cudaStreamNonBlocking);
        cudaStreamCreateWithFlags(&g_s2, cudaStreamNonBlocking);
        cudaEventCreateWithFlags(&g_ev0, cudaEventDisableTiming);
        cudaEventCreateWithFlags(&g_ev1, cudaEventDisableTiming);
        cudaEventCreateWithFlags(&g_ev2, cudaEventDisableTiming);
    }
};
StreamInit g_stream_init;
}

__device__ __forceinline__ uint32_t smem_u32(const void* p) {
    uint32_t a;
    asm("{ .reg .u64 t; cvta.to.shared.u64 t, %1; cvt.u32.u64 %0, t; }" : "=r"(a) : "l"(p));
    return a;
}

__device__ __forceinline__ void mma_f16(float c[4],
                                        const uint32_t a[4],
                                        uint32_t b0, uint32_t b1) {
    asm volatile(
        "mma.sync.aligned.m16n8k16.row.col.f32.f16.f16.f32 "
        "{%0,%1,%2,%3}, {%4,%5,%6,%7}, {%8,%9}, {%0,%1,%2,%3};"
        : "+f"(c[0]), "+f"(c[1]), "+f"(c[2]), "+f"(c[3])
        : "r"(a[0]), "r"(a[1]), "r"(a[2]), "r"(a[3]), "r"(b0), "r"(b1));
}

__device__ __forceinline__ void ldsm_x4(uint32_t r[4], uint32_t addr) {
    asm volatile(
        "ldmatrix.sync.aligned.m8n8.x4.shared.b16 {%0,%1,%2,%3}, [%4];"
        : "=r"(r[0]), "=r"(r[1]), "=r"(r[2]), "=r"(r[3]) : "r"(addr));
}

#define CP_ASYNC16(dst, src) \
    asm volatile("cp.async.cg.shared.global [%0], [%1], 16;" :: "r"(dst), "l"(src) : "memory")
#define CP_COMMIT() asm volatile("cp.async.commit_group;" ::: "memory")
#define CP_WAIT1()  asm volatile("cp.async.wait_group 1;" ::: "memory")
#define CP_WAIT2()  asm volatile("cp.async.wait_group 2;" ::: "memory")

// ===========================================================================
// Async fp16 GEMM: C[M,N] = A[M,K] @ Bt[N,K]^T + bias[N]
// 128x128 tile, 256 thr, KC=32, 4 stages; smem row stride 80B.
// Fragment loads via ldmatrix.x4 (conflict-free with the 80B stride).
// ===========================================================================
#define HG_KC 32
#define HG_ROWB 80
#define HG_TILE (128 * HG_ROWB)
#define HG_STAGE (2 * HG_TILE)
#define HG_STAGES 4
#define HG_SMEM (HG_STAGES * HG_STAGE)  // 81920 B

template <typename OutT>
__global__ __launch_bounds__(256, 2)
void gemm_async_h_kernel(const __half* __restrict__ A, const __half* __restrict__ Bt,
                         const float* __restrict__ bias, OutT* __restrict__ C,
                         int M, int N, int K)
{
    extern __shared__ char smem[];
    const uint32_t sbase = smem_u32(smem);

    const int tid  = threadIdx.x;
    const int wid  = tid >> 5;
    const int lane = tid & 31;
    const int g    = lane >> 2;
    const int tig  = lane & 3;
    const int wm   = wid & 3;
    const int wn   = wid >> 2;

    const int m0 = blockIdx.y * 128;
    const int n0 = blockIdx.x * 128;

    // ldmatrix lane-address offsets (within a stage)
    // A (x4 per mt): row = wm*32 + mt*16 + (lane&15); kbyte = (lane>>4)*16 + ks*32
    const uint32_t aOff = (uint32_t)((wm * 32 + (lane & 15)) * HG_ROWB + (lane >> 4) * 16);
    // B (x4 per nt-pair j): row = wn*64 + j*16 + (lane&7) + (lane>>4)*8;
    //                       kbyte = ((lane>>3)&1)*16 + ks*32
    const uint32_t bOff = (uint32_t)(HG_TILE +
        (wn * 64 + (lane & 7) + (lane >> 4) * 8) * HG_ROWB + ((lane >> 3) & 1) * 16);

    float acc[2][8][4];
#pragma unroll
    for (int mt = 0; mt < 2; mt++)
#pragma unroll
        for (int nt = 0; nt < 8; nt++)
#pragma unroll
            for (int j = 0; j < 4; j++) acc[mt][nt][j] = 0.0f;

    const int nch = K / HG_KC;

#define HCOPY_STAGE(s, chunk)                                                  \
    do {                                                                       \
        const int _k0 = (chunk) * HG_KC;                                       \
        const uint32_t _dA = sbase + (s) * HG_STAGE;                           \
        const uint32_t _dB = _dA + HG_TILE;                                    \
        _Pragma("unroll")                                                      \
        for (int e = 0; e < 2; e++) {                                          \
            const int cc = tid + e * 256;                                      \
            const int r = cc >> 2;                                             \
            const int q = cc & 3;                                              \
            CP_ASYNC16(_dA + r * HG_ROWB + q * 16,                             \
                       &A[(size_t)(m0 + r) * K + _k0 + q * 8]);                \
            CP_ASYNC16(_dB + r * HG_ROWB + q * 16,                             \
                       &Bt[(size_t)(n0 + r) * K + _k0 + q * 8]);               \
        }                                                                      \
    } while (0)

    HCOPY_STAGE(0, 0); CP_COMMIT();
    HCOPY_STAGE(1, 1); CP_COMMIT();
    HCOPY_STAGE(2, 2); CP_COMMIT();

    for (int c = 0; c < nch; ++c) {
        CP_WAIT2();
        __syncthreads();

        if (c + 3 < nch) {
            HCOPY_STAGE((c + 3) % HG_STAGES, c + 3);
        }
        CP_COMMIT();

        const int s = c % HG_STAGES;
        const uint32_t stageBase = sbase + s * HG_STAGE;
        const uint32_t aBase = stageBase + aOff;
        const uint32_t bBase = stageBase + bOff;

#pragma unroll
        for (int ks = 0; ks < 2; ks++) {
            uint32_t a0[4], a1[4];
            ldsm_x4(a0, aBase + ks * 32);
            ldsm_x4(a1, aBase + 16 * HG_ROWB + ks * 32);
#pragma unroll
            for (int j = 0; j < 4; j++) {
                uint32_t b[4];
                ldsm_x4(b, bBase + j * 16 * HG_ROWB + ks * 32);
                mma_f16(acc[0][2 * j],     a0, b[0], b[1]);
                mma_f16(acc[1][2 * j],     a1, b[0], b[1]);
                mma_f16(acc[0][2 * j + 1], a0, b[2], b[3]);
                mma_f16(acc[1][2 * j + 1], a1, b[2], b[3]);
            }
        }
        __syncthreads();
    }
#undef HCOPY_STAGE

#pragma unroll
    for (int mt = 0; mt < 2; mt++) {
        const int row0 = m0 + wm * 32 + mt * 16 + g;
#pragma unroll
        for (int nt = 0; nt < 8; nt++) {
            const int col = n0 + wn * 64 + nt * 8 + tig * 2;
            const float bx = bias[col];
            const float by = bias[col + 1];
            const float l0 = acc[mt][nt][0] + bx;
            const float l1 = acc[mt][nt][1] + by;
            const float h0 = acc[mt][nt][2] + bx;
            const float h1 = acc[mt][nt][3] + by;
            if constexpr (sizeof(OutT) == 2) {
                __half2* p0 = reinterpret_cast<__half2*>(&C[(size_t)row0 * N + col]);
                __half2* p1 = reinterpret_cast<__half2*>(&C[(size_t)(row0 + 8) * N + col]);
                *p0 = __floats2half2_rn(l0, l1);
                *p1 = __floats2half2_rn(h0, h1);
            } else {
                float2 lo, hi;
                lo.x = l0; lo.y = l1; hi.x = h0; hi.y = h1;
                *reinterpret_cast<float2*>(&C[(size_t)row0 * N + col]) = lo;
                *reinterpret_cast<float2*>(&C[(size_t)(row0 + 8) * N + col]) = hi;
            }
        }
    }
}

// ===========================================================================
// Fused split-fp16 off/aw GEMM (off critical path — unchanged from round 10):
// C[M,128] = (Ah+Al)[M,512] @ (Bh+Bl)[128,512]^T + bias  (drops al@bl term)
// ===========================================================================
#define FG_TILE HG_TILE
#define FG_STAGE (4 * FG_TILE)
#define FG_STAGES 3
#define FG_SMEM (FG_STAGES * FG_STAGE)   // 122880 B

__global__ __launch_bounds__(256, 1)
void gemm_offaw_fused_kernel(const __half* __restrict__ Ah, const __half* __restrict__ Al,
                             const __half* __restrict__ Bh, const __half* __restrict__ Bl,
                             const float* __restrict__ bias, float* __restrict__ C,
                             int M, int K)
{
    extern __shared__ char smem[];
    const uint32_t sbase = smem_u32(smem);
    const int N = 128;

    const int tid  = threadIdx.x;
    const int wid  = tid >> 5;
    const int lane = tid & 31;
    const int g    = lane >> 2;
    const int tig  = lane & 3;
    const int wm   = wid & 3;
    const int wn   = wid >> 2;

    const int m0 = blockIdx.y * 128;

    float acc[2][8][4];
#pragma unroll
    for (int mt = 0; mt < 2; mt++)
#pragma unroll
        for (int nt = 0; nt < 8; nt++)
#pragma unroll
            for (int j = 0; j < 4; j++) acc[mt][nt][j] = 0.0f;

    const int nch = K / HG_KC;

#define FCOPY_STAGE(s, chunk)                                                  \
    do {                                                                       \
        const int _k0 = (chunk) * HG_KC;                                       \
        const uint32_t _d0 = sbase + (s) * FG_STAGE;                           \
        _Pragma("unroll")                                                      \
        for (int e = 0; e < 2; e++) {                                          \
            const int cc = tid + e * 256;                                      \
            const int r = cc >> 2;                                             \
            const int q = cc & 3;                                              \
            const uint32_t od = r * HG_ROWB + q * 16;                          \
            const size_t oa = (size_t)(m0 + r) * K + _k0 + q * 8;              \
            const size_t ob = (size_t)r * K + _k0 + q * 8;                     \
            CP_ASYNC16(_d0 + od,                 &Ah[oa]);                     \
            CP_ASYNC16(_d0 + FG_TILE + od,       &Al[oa]);                     \
            CP_ASYNC16(_d0 + 2 * FG_TILE + od,   &Bh[ob]);                     \
            CP_ASYNC16(_d0 + 3 * FG_TILE + od,   &Bl[ob]);                     \
        }                                                                      \
    } while (0)

    FCOPY_STAGE(0, 0); CP_COMMIT();
    FCOPY_STAGE(1, 1); CP_COMMIT();

    for (int c = 0; c < nch; ++c) {
        CP_WAIT1();
        __syncthreads();

        if (c + 2 < nch) {
            FCOPY_STAGE((c + 2) % FG_STAGES, c + 2);
        }
        CP_COMMIT();

        const int s = c % FG_STAGES;
        const uint32_t* SAh = reinterpret_cast<const uint32_t*>(smem + s * FG_STAGE);
        const uint32_t* SAl = SAh + FG_TILE / 4;
        const uint32_t* SBh = SAh + 2 * (FG_TILE / 4);
        const uint32_t* SBl = SAh + 3 * (FG_TILE / 4);

#pragma unroll
        for (int ks = 0; ks < 2; ks++) {
            const int kw = ks * 8 + tig;

            uint32_t ah[2][4], al[2][4];
#pragma unroll
            for (int mt = 0; mt < 2; mt++) {
                const int r = wm * 32 + mt * 16 + g;
                ah[mt][0] = SAh[r * 20 + kw];
                ah[mt][1] = SAh[(r + 8) * 20 + kw];
                ah[mt][2] = SAh[r * 20 + kw + 4];
                ah[mt][3] = SAh[(r + 8) * 20 + kw + 4];
                al[mt][0] = SAl[r * 20 + kw];
                al[mt][1] = SAl[(r + 8) * 20 + kw];
                al[mt][2] = SAl[r * 20 + kw + 4];
                al[mt][3] = SAl[(r + 8) * 20 + kw + 4];
            }
#pragma unroll
            for (int nt = 0; nt < 8; nt++) {
                const int n = wn * 64 + nt * 8 + g;
                const uint32_t bh0 = SBh[n * 20 + kw];
                const uint32_t bh1 = SBh[n * 20 + kw + 4];
                const uint32_t bl0 = SBl[n * 20 + kw];
                const uint32_t bl1 = SBl[n * 20 + kw + 4];
#pragma unroll
                for (int mt = 0; mt < 2; mt++) {
                    mma_f16(acc[mt][nt], ah[mt], bh0, bh1);   // hi@hi
                    mma_f16(acc[mt][nt], ah[mt], bl0, bl1);   // hi@lo
                    mma_f16(acc[mt][nt], al[mt], bh0, bh1);   // lo@hi
                }
            }
        }
        __syncthreads();
    }
#undef FCOPY_STAGE

#pragma unroll
    for (int mt = 0; mt < 2; mt++) {
        const int row0 = m0 + wm * 32 + mt * 16 + g;
#pragma unroll
        for (int nt = 0; nt < 8; nt++) {
            const int col = wn * 64 + nt * 8 + tig * 2;
            const float bx = bias[col];
            const float by = bias[col + 1];
            float2 lo, hi;
            lo.x = acc[mt][nt][0] + bx;  lo.y = acc[mt][nt][1] + by;
            hi.x = acc[mt][nt][2] + bx;  hi.y = acc[mt][nt][3] + by;
            *reinterpret_cast<float2*>(&C[(size_t)row0 * N + col]) = lo;
            *reinterpret_cast<float2*>(&C[(size_t)(row0 + 8) * N + col]) = hi;
        }
    }
}

// ===========================================================================
// Prep kernels
// ===========================================================================
__global__ void transpose_h_kernel(const float* __restrict__ in,
                                   __half* __restrict__ out, int R, int C)
{
    __shared__ float tile[32][33];
    const int bx = blockIdx.x * 32;
    const int by = blockIdx.y * 32;
#pragma unroll
    for (int j = 0; j < 32; j += 8)
        tile[threadIdx.y + j][threadIdx.x] =
            in[(size_t)(by + threadIdx.y + j) * C + bx + threadIdx.x];
    __syncthreads();
#pragma unroll
    for (int j = 0; j < 32; j += 8)
        out[(size_t)(bx + threadIdx.y + j) * R + by + threadIdx.x] =
            __float2half_rn(tile[threadIdx.x][threadIdx.y + j]);
}

__global__ void convert_h_kernel(const float4* __restrict__ in,
                                 uint2* __restrict__ out, int n8)
{
    const int i = blockIdx.x * 256 + threadIdx.x;
    if (i < n8) {
        const float4 a = in[2 * i];
        const float4 b = in[2 * i + 1];
        __half2 p0 = __floats2half2_rn(a.x, a.y);
        __half2 p1 = __floats2half2_rn(a.z, a.w);
        __half2 p2 = __floats2half2_rn(b.x, b.y);
        __half2 p3 = __floats2half2_rn(b.z, b.w);
        uint2 o;
        o.x = *reinterpret_cast<uint32_t*>(&p0);
        o.y = *reinterpret_cast<uint32_t*>(&p1);
        out[2 * i] = o;
        uint2 o2;
        o2.x = *reinterpret_cast<uint32_t*>(&p2);
        o2.y = *reinterpret_cast<uint32_t*>(&p3);
        out[2 * i + 1] = o2;
    }
}

__global__ void split_h_kernel(const float4* __restrict__ in,
                               uint2* __restrict__ hi, uint2* __restrict__ lo,
                               int n4)
{
    const int i = blockIdx.x * 256 + threadIdx.x;
    if (i < n4) {
        const float4 a = in[i];
        const __half hx = __float2half_rn(a.x), hy = __float2half_rn(a.y);
        const __half hz = __float2half_rn(a.z), hw = __float2half_rn(a.w);
        const __half lx = __float2half_rn(a.x - __half2float(hx));
        const __half ly = __float2half_rn(a.y - __half2float(hy));
        const __half lz = __float2half_rn(a.z - __half2float(hz));
        const __half lw = __float2half_rn(a.w - __half2float(hw));
        __half2 h0 = __halves2half2(hx, hy), h1 = __halves2half2(hz, hw);
        __half2 l0 = __halves2half2(lx, ly), l1 = __halves2half2(lz, lw);
        uint2 oh, ol;
        oh.x = *reinterpret_cast<uint32_t*>(&h0);
        oh.y = *reinterpret_cast<uint32_t*>(&h1);
        ol.x = *reinterpret_cast<uint32_t*>(&l0);
        ol.y = *reinterpret_cast<uint32_t*>(&l1);
        hi[i] = oh;
        lo[i] = ol;
    }
}

__global__ void build_wq_split_kernel(const float* __restrict__ W_off,
                                      const float* __restrict__ W_aw,
                                      const float* __restrict__ b_off,
                                      const float* __restrict__ b_aw,
                                      __half* __restrict__ wqt_hi,
                                      __half* __restrict__ wqt_lo,
                                      float* __restrict__ bq)
{
    const int i = blockIdx.x * 256 + threadIdx.x;
    if (i < 128 * DMODEL) {
        const int n = i / DMODEL;
        const int k = i - n * DMODEL;
        float w = 0.0f;
        if (n < 64)      w = W_off[k * 64 + n];
        else if (n < 96) w = W_aw[k * 32 + (n - 64)];
        const __half h = __float2half_rn(w);
        const __half l = __float2half_rn(w - __half2float(h));
        wqt_hi[i] = h;
        wqt_lo[i] = l;
    }
    if (i < 128) {
        float bv = 0.0f;
        if (i < 64)      bv = b_off[i];
        else if (i < 96) bv = b_aw[i - 64];
        bq[i] = bv;
    }
}

// ===========================================================================
// Deformable sampling: 128 threads; v and mid fp16, math fp32.
// ===========================================================================
__global__ __launch_bounds__(128) void deform_kernel(
    const __half* __restrict__ v,
    const float* __restrict__ offaw,
    __half* __restrict__ mid)
{
    __shared__ float s_w0[NHEAD][NPNT];
    __shared__ float s_w1[NHEAD][NPNT];
    __shared__ int   s_i0[NHEAD][NPNT];
    __shared__ int   s_i1[NHEAD][NPNT];

    const int blk = blockIdx.x;
    const int b = blk / LSEQ;
    const int l = blk - b * LSEQ;
    const int t = threadIdx.x;

    if (t < NHEAD) {
        const int h = t;
        const float ref_y = (float)l / (float)(LSEQ - 1);
        const float* row = &offaw[(size_t)blk * 128];

        float lg[NPNT];
        float mx = -1e30f;
#pragma unroll
        for (int p = 0; p < NPNT; p++) {
            lg[p] = row[64 + h * NPNT + p];
            mx = fmaxf(mx, lg[p]);
        }
        float sum = 0.0f;
#pragma unroll
        for (int p = 0; p < NPNT; p++) { lg[p] = __expf(lg[p] - mx); sum += lg[p]; }
        const float inv = 1.0f / sum;

#pragma unroll
        for (int p = 0; p < NPNT; p++) {
            const float a = lg[p] * inv;
            const float ox = row[(h * NPNT + p) * 2 + 0];
            const float oy = row[(h * NPNT + p) * 2 + 1];
            const float locx = fminf(fmaxf(ox, 0.0f), 1.0f);
            const float locy = fminf(fmaxf(oy + ref_y, 0.0f), 1.0f);

            const float ix = ((locx + 1.0f) * (float)LSEQ - 1.0f) * 0.5f;
            const float iy = locy * 0.5f;
            const float ix0 = floorf(ix);
            const float fx = ix - ix0;
            const float iy0 = floorf(iy);
            const float fy = iy - iy0;
            const float ywt = (1.0f - fy) * (iy0 == 0.0f ? 1.0f : 0.0f)
                            + fy * ((iy0 + 1.0f) == 0.0f ? 1.0f : 0.0f);

            const int i0 = (int)ix0;
            const int i1 = i0 + 1;
            const float w = a * ywt;
            const bool v0 = (i0 >= 0) && (i0 < LSEQ);
            const bool v1 = (i1 >= 0) && (i1 < LSEQ);
            s_w0[h][p] = v0 ? w * (1.0f - fx) : 0.0f;
            s_w1[h][p] = v1 ? w * fx : 0.0f;
            s_i0[h][p] = min(max(i0, 0), LSEQ - 1);
            s_i1[h][p] = min(max(i1, 0), LSEQ - 1);
        }
    }
    __syncthreads();

    const int h  = t >> 4;
    const int c4 = t & 15;
    const uint2* vb = reinterpret_cast<const uint2*>(
        v + (size_t)b * LSEQ * DMODEL + h * CHEAD) + c4;

    float ax = 0.0f, ay = 0.0f, az = 0.0f, aw = 0.0f;
#pragma unroll
    for (int p = 0; p < NPNT; p++) {
        const float w0 = s_w0[h][p];
        const float w1 = s_w1[h][p];
        const uint2 u0 = vb[(size_t)s_i0[h][p] * (DMODEL / 4)];
        const uint2 u1 = vb[(size_t)s_i1[h][p] * (DMODEL / 4)];
        const float2 f00 = __half22float2(*reinterpret_cast<const __half2*>(&u0.x));
        const float2 f01 = __half22float2(*reinterpret_cast<const __half2*>(&u0.y));
        const float2 f10 = __half22float2(*reinterpret_cast<const __half2*>(&u1.x));
        const float2 f11 = __half22float2(*reinterpret_cast<const __half2*>(&u1.y));
        ax = fmaf(w0, f00.x, ax); ay = fmaf(w0, f00.y, ay);
        az = fmaf(w0, f01.x, az); aw = fmaf(w0, f01.y, aw);
        ax = fmaf(w1, f10.x, ax); ay = fmaf(w1, f10.y, ay);
        az = fmaf(w1, f11.x, az); aw = fmaf(w1, f11.y, aw);
    }
    __half2 o0 = __floats2half2_rn(ax, ay);
    __half2 o1 = __floats2half2_rn(az, aw);
    uint2 o;
    o.x = *reinterpret_cast<uint32_t*>(&o0);
    o.y = *reinterpret_cast<uint32_t*>(&o1);
    *reinterpret_cast<uint2*>(&mid[(size_t)blk * DMODEL + h * CHEAD + c4 * 4]) = o;
}

// ===========================================================================
// Host launch — fork/join; off/aw via fused split-fp16 tensor GEMM
// ===========================================================================
extern "C" void kernel_launch(void* const* d_in, const int* in_sizes, int n_in,
                              void* d_out, int out_size)
{
    const float* query = (const float*)d_in[0];
    const float* value = (const float*)d_in[2];
    const float* W_v   = (const float*)d_in[3];
    const float* b_v   = (const float*)d_in[4];
    const float* W_off = (const float*)d_in[5];
    const float* b_off = (const float*)d_in[6];
    const float* W_aw  = (const float*)d_in[7];
    const float* b_aw  = (const float*)d_in[8];
    const float* W_out = (const float*)d_in[9];
    const float* b_out = (const float*)d_in[10];
    float* out = (float*)d_out;

    __half *pv, *pva, *pmid, *pwvt, *pwot, *pqhi, *pqlo, *pwqh, *pwql;
    float *poffaw, *pbq;
    cudaGetSymbolAddress((void**)&pv,     g_v);
    cudaGetSymbolAddress((void**)&pva,    g_va);
    cudaGetSymbolAddress((void**)&pmid,   g_mid);
    cudaGetSymbolAddress((void**)&poffaw, g_offaw);
    cudaGetSymbolAddress((void**)&pwvt,   g_wvt);
    cudaGetSymbolAddress((void**)&pwot,   g_wot);
    cudaGetSymbolAddress((void**)&pqhi,   g_qhi);
    cudaGetSymbolAddress((void**)&pqlo,   g_qlo);
    cudaGetSymbolAddress((void**)&pwqh,   g_wqt_hi);
    cudaGetSymbolAddress((void**)&pwql,   g_wqt_lo);
    cudaGetSymbolAddress((void**)&pbq,    g_bq);

    cudaFuncSetAttribute((const void*)gemm_async_h_kernel<__half>,
                         cudaFuncAttributeMaxDynamicSharedMemorySize, HG_SMEM);
    cudaFuncSetAttribute((const void*)gemm_async_h_kernel<float>,
                         cudaFuncAttributeMaxDynamicSharedMemorySize, HG_SMEM);
    cudaFuncSetAttribute((const void*)gemm_offaw_fused_kernel,
                         cudaFuncAttributeMaxDynamicSharedMemorySize, FG_SMEM);

    // Fork.
    cudaEventRecord(g_ev0, 0);
    cudaStreamWaitEvent(g_s1, g_ev0, 0);
    cudaStreamWaitEvent(g_s2, g_ev0, 0);

    // --- s1: off/aw chain via fused split-fp16 tensor GEMM + W_out transpose ---
    build_wq_split_kernel<<<(128 * DMODEL + 255) / 256, 256, 0, g_s1>>>(
        W_off, W_aw, b_off, b_aw, pwqh, pwql, pbq);
    split_h_kernel<<<(MROWS * DMODEL / 4 + 255) / 256, 256, 0, g_s1>>>(
        (const float4*)query, (uint2*)pqhi, (uint2*)pqlo, MROWS * DMODEL / 4);
    {
        dim3 grid(1, MROWS / 128);
        gemm_offaw_fused_kernel<<<grid, 256, FG_SMEM, g_s1>>>(
            pqhi, pqlo, pwqh, pwql, pbq, poffaw, MROWS, DMODEL);
    }
    {
        dim3 tb(32, 8);
        dim3 tg(DMODEL / 32, DMODEL / 32);
        transpose_h_kernel<<<tg, tb, 0, g_s1>>>(W_out, pwot, DMODEL, DMODEL);
    }
    cudaEventRecord(g_ev1, g_s1);

    // --- s2: convert value to fp16 ---
    convert_h_kernel<<<(MROWS * DMODEL / 8 + 255) / 256, 256, 0, g_s2>>>(
        (const float4*)value, (uint2*)pva, MROWS * DMODEL / 8);
    cudaEventRecord(g_ev2, g_s2);

    // --- s0 (origin): W_v transpose, then v-GEMM once convert is done ---
    {
        dim3 tb(32, 8);
        dim3 tg(DMODEL / 32, DMODEL / 32);
        transpose_h_kernel<<<tg, tb>>>(W_v, pwvt, DMODEL, DMODEL);
    }
    cudaStreamWaitEvent(0, g_ev2, 0);
    {
        dim3 grid(DMODEL / 128, MROWS / 128);
        gemm_async_h_kernel<__half><<<grid, 256, HG_SMEM>>>(
            pva, pwvt, b_v, pv, MROWS, DMODEL, DMODEL);
    }

    // Join: deform needs the off/aw chain too.
    cudaStreamWaitEvent(0, g_ev1, 0);
    deform_kernel<<<MROWS, 128>>>(pv, poffaw, pmid);

    // --- out = mid @ W_out + b_out (fp16 mma, fp32 out) ---
    {
        dim3 grid(DMODEL / 128, MROWS / 128);
        gemm_async_h_kernel<float><<<grid, 256, HG_SMEM>>>(
            pmid, pwot, b_out, out, MROWS, DMODEL, DMODEL);
    }
}

// round 12
// speedup vs baseline: 4.7741x; 1.0065x over previous
#include <cuda_runtime.h>
#include <cuda_fp16.h>
#include <math.h>
#include <stdint.h>

// Problem constants
#define BATCH 8
#define LSEQ  2048
#define DMODEL 512
#define NHEAD 8
#define NPNT  4
#define CHEAD 64
#define MROWS (BATCH * LSEQ)   // 16384

// Scratch (device globals; no allocation allowed)
__device__ __align__(16) __half g_v[MROWS * DMODEL];      // value projection (fp16)
__device__ __align__(16) __half g_mid[MROWS * DMODEL];    // deform output (fp16)
__device__ __align__(16) float  g_offaw[MROWS * 128];     // off(64)|aw(32)|pad, fp32
__device__ __align__(16) __half g_wvt[DMODEL * DMODEL];   // W_v^T   fp16 [N][K]
__device__ __align__(16) __half g_wot[DMODEL * DMODEL];   // W_out^T fp16 [N][K]
__device__ __align__(16) __half g_qhi[MROWS * DMODEL];    // query hi fp16
__device__ __align__(16) __half g_qlo[MROWS * DMODEL];    // query lo fp16 (residual)
__device__ __align__(16) __half g_wqt_hi[128 * DMODEL];   // Wq^T hi fp16 [128][512]
__device__ __align__(16) __half g_wqt_lo[128 * DMODEL];   // Wq^T lo fp16
__device__ __align__(16) float  g_bq[128];

// Streams/events for fork-join overlap (created once at module load).
static cudaStream_t g_s1;
static cudaEvent_t g_ev0, g_ev1;
namespace {
struct StreamInit {
    StreamInit() {
        cudaStreamCreateWithFlags(&g_s1, cudaStreamNonBlocking);
        cudaEventCreateWithFlags(&g_ev0, cudaEventDisableTiming);
        cudaEventCreateWithFlags(&g_ev1, cudaEventDisableTiming);
    }
};
StreamInit g_stream_init;
}

__device__ __forceinline__ uint32_t smem_u32(const void* p) {
    uint32_t a;
    asm("{ .reg .u64 t; cvta.to.shared.u64 t, %1; cvt.u32.u64 %0, t; }" : "=r"(a) : "l"(p));
    return a;
}

__device__ __forceinline__ void mma_f16(float c[4],
                                        const uint32_t a[4],
                                        uint32_t b0, uint32_t b1) {
    asm volatile(
        "mma.sync.aligned.m16n8k16.row.col.f32.f16.f16.f32 "
        "{%0,%1,%2,%3}, {%4,%5,%6,%7}, {%8,%9}, {%0,%1,%2,%3};"
        : "+f"(c[0]), "+f"(c[1]), "+f"(c[2]), "+f"(c[3])
        : "r"(a[0]), "r"(a[1]), "r"(a[2]), "r"(a[3]), "r"(b0), "r"(b1));
}

__device__ __forceinline__ void ldsm_x4(uint32_t r[4], uint32_t addr) {
    asm volatile(
        "ldmatrix.sync.aligned.m8n8.x4.shared.b16 {%0,%1,%2,%3}, [%4];"
        : "=r"(r[0]), "=r"(r[1]), "=r"(r[2]), "=r"(r[3]) : "r"(addr));
}

#define CP_ASYNC16(dst, src) \
    asm volatile("cp.async.cg.shared.global [%0], [%1], 16;" :: "r"(dst), "l"(src) : "memory")
#define CP_COMMIT() asm volatile("cp.async.commit_group;" ::: "memory")
#define CP_WAIT1()  asm volatile("cp.async.wait_group 1;" ::: "memory")
#define CP_WAIT2()  asm volatile("cp.async.wait_group 2;" ::: "memory")

// Common tile geometry
#define HG_KC 32
#define HG_ROWB 80
#define HG_TILE (128 * HG_ROWB)
#define HG_STAGE (2 * HG_TILE)
#define HG_STAGES 4
#define HG_SMEM (HG_STAGES * HG_STAGE)  // 81920 B

// ===========================================================================
// Async fp16 GEMM (fp16 A): C[M,N] = A @ Bt^T + bias. (out-GEMM, fp32 out)
// ===========================================================================
template <typename OutT>
__global__ __launch_bounds__(256, 2)
void gemm_async_h_kernel(const __half* __restrict__ A, const __half* __restrict__ Bt,
                         const float* __restrict__ bias, OutT* __restrict__ C,
                         int M, int N, int K)
{
    extern __shared__ char smem[];
    const uint32_t sbase = smem_u32(smem);

    const int tid  = threadIdx.x;
    const int wid  = tid >> 5;
    const int lane = tid & 31;
    const int g    = lane >> 2;
    const int tig  = lane & 3;
    const int wm   = wid & 3;
    const int wn   = wid >> 2;

    const int m0 = blockIdx.y * 128;
    const int n0 = blockIdx.x * 128;

    const uint32_t aOff = (uint32_t)((wm * 32 + (lane & 15)) * HG_ROWB + (lane >> 4) * 16);
    const uint32_t bOff = (uint32_t)(HG_TILE +
        (wn * 64 + (lane & 7) + (lane >> 4) * 8) * HG_ROWB + ((lane >> 3) & 1) * 16);

    float acc[2][8][4];
#pragma unroll
    for (int mt = 0; mt < 2; mt++)
#pragma unroll
        for (int nt = 0; nt < 8; nt++)
#pragma unroll
            for (int j = 0; j < 4; j++) acc[mt][nt][j] = 0.0f;

    const int nch = K / HG_KC;

#define HCOPY_STAGE(s, chunk)                                                  \
    do {                                                                       \
        const int _k0 = (chunk) * HG_KC;                                       \
        const uint32_t _dA = sbase + (s) * HG_STAGE;                           \
        const uint32_t _dB = _dA + HG_TILE;                                    \
        _Pragma("unroll")                                                      \
        for (int e = 0; e < 2; e++) {                                          \
            const int cc = tid + e * 256;                                      \
            const int r = cc >> 2;                                             \
            const int q = cc & 3;                                              \
            CP_ASYNC16(_dA + r * HG_ROWB + q * 16,                             \
                       &A[(size_t)(m0 + r) * K + _k0 + q * 8]);                \
            CP_ASYNC16(_dB + r * HG_ROWB + q * 16,                             \
                       &Bt[(size_t)(n0 + r) * K + _k0 + q * 8]);               \
        }                                                                      \
    } while (0)

    HCOPY_STAGE(0, 0); CP_COMMIT();
    HCOPY_STAGE(1, 1); CP_COMMIT();
    HCOPY_STAGE(2, 2); CP_COMMIT();

    for (int c = 0; c < nch; ++c) {
        CP_WAIT2();
        __syncthreads();

        if (c + 3 < nch) {
            HCOPY_STAGE((c + 3) % HG_STAGES, c + 3);
        }
        CP_COMMIT();

        const uint32_t stageBase = sbase + (c % HG_STAGES) * HG_STAGE;
        const uint32_t aBase = stageBase + aOff;
        const uint32_t bBase = stageBase + bOff;

#pragma unroll
        for (int ks = 0; ks < 2; ks++) {
            uint32_t a0[4], a1[4];
            ldsm_x4(a0, aBase + ks * 32);
            ldsm_x4(a1, aBase + 16 * HG_ROWB + ks * 32);
#pragma unroll
            for (int j = 0; j < 4; j++) {
                uint32_t b[4];
                ldsm_x4(b, bBase + j * 16 * HG_ROWB + ks * 32);
                mma_f16(acc[0][2 * j],     a0, b[0], b[1]);
                mma_f16(acc[1][2 * j],     a1, b[0], b[1]);
                mma_f16(acc[0][2 * j + 1], a0, b[2], b[3]);
                mma_f16(acc[1][2 * j + 1], a1, b[2], b[3]);
            }
        }
        __syncthreads();
    }
#undef HCOPY_STAGE

#pragma unroll
    for (int mt = 0; mt < 2; mt++) {
        const int row0 = m0 + wm * 32 + mt * 16 + g;
#pragma unroll
        for (int nt = 0; nt < 8; nt++) {
            const int col = n0 + wn * 64 + nt * 8 + tig * 2;
            const float bx = bias[col];
            const float by = bias[col + 1];
            const float l0 = acc[mt][nt][0] + bx;
            const float l1 = acc[mt][nt][1] + by;
            const float h0 = acc[mt][nt][2] + bx;
            const float h1 = acc[mt][nt][3] + by;
            if constexpr (sizeof(OutT) == 2) {
                __half2* p0 = reinterpret_cast<__half2*>(&C[(size_t)row0 * N + col]);
                __half2* p1 = reinterpret_cast<__half2*>(&C[(size_t)(row0 + 8) * N + col]);
                *p0 = __floats2half2_rn(l0, l1);
                *p1 = __floats2half2_rn(h0, h1);
            } else {
                float2 lo, hi;
                lo.x = l0; lo.y = l1; hi.x = h0; hi.y = h1;
                *reinterpret_cast<float2*>(&C[(size_t)row0 * N + col]) = lo;
                *reinterpret_cast<float2*>(&C[(size_t)(row0 + 8) * N + col]) = hi;
            }
        }
    }
}

// ===========================================================================
// v-GEMM with fused fp32->fp16 A conversion:
// C[M,N](fp16) = half(A_f32)[M,K] @ Bt[N,K]^T + bias
// A staged LDG(float4) -> cvt -> STS fp16 one iter ahead; B via cp.async.
// smem layout identical to gemm_async_h_kernel (same ldmatrix offsets).
// ===========================================================================
__global__ __launch_bounds__(256, 2)
void gemm_v_f32a_kernel(const float* __restrict__ A, const __half* __restrict__ Bt,
                        const float* __restrict__ bias, __half* __restrict__ C,
                        int M, int N, int K)
{
    extern __shared__ char smem[];
    const uint32_t sbase = smem_u32(smem);

    const int tid  = threadIdx.x;
    const int wid  = tid >> 5;
    const int lane = tid & 31;
    const int g    = lane >> 2;
    const int tig  = lane & 3;
    const int wm   = wid & 3;
    const int wn   = wid >> 2;

    const int m0 = blockIdx.y * 128;
    const int n0 = blockIdx.x * 128;

    const uint32_t aOff = (uint32_t)((wm * 32 + (lane & 15)) * HG_ROWB + (lane >> 4) * 16);
    const uint32_t bOff = (uint32_t)(HG_TILE +
        (wn * 64 + (lane & 7) + (lane >> 4) * 8) * HG_ROWB + ((lane >> 3) & 1) * 16);

    // A staging coords: i = tid + e*256 (e<2); r = i>>2 (0..127), q2 = i&3 (16B fp16 chunk)
    float4 areg[2][2];

    float acc[2][8][4];
#pragma unroll
    for (int mt = 0; mt < 2; mt++)
#pragma unroll
        for (int nt = 0; nt < 8; nt++)
#pragma unroll
            for (int j = 0; j < 4; j++) acc[mt][nt][j] = 0.0f;

    const int nch = K / HG_KC;

#define VG_LDG_A(k0)                                                           \
    do {                                                                       \
        _Pragma("unroll")                                                      \
        for (int e = 0; e < 2; e++) {                                          \
            const int i = tid + e * 256;                                       \
            const int r = i >> 2;                                              \
            const int q2 = i & 3;                                              \
            const float* pA = &A[(size_t)(m0 + r) * K + (k0) + q2 * 8];        \
            areg[e][0] = *reinterpret_cast<const float4*>(pA);                 \
            areg[e][1] = *reinterpret_cast<const float4*>(pA + 4);             \
        }                                                                      \
    } while (0)

#define VG_STS_A(s)                                                            \
    do {                                                                       \
        _Pragma("unroll")                                                      \
        for (int e = 0; e < 2; e++) {                                          \
            const int i = tid + e * 256;                                       \
            const int r = i >> 2;                                              \
            const int q2 = i & 3;                                              \
            __half2 h0 = __floats2half2_rn(areg[e][0].x, areg[e][0].y);        \
            __half2 h1 = __floats2half2_rn(areg[e][0].z, areg[e][0].w);        \
            __half2 h2 = __floats2half2_rn(areg[e][1].x, areg[e][1].y);        \
            __half2 h3 = __floats2half2_rn(areg[e][1].z, areg[e][1].w);        \
            uint4 o;                                                           \
            o.x = *reinterpret_cast<uint32_t*>(&h0);                           \
            o.y = *reinterpret_cast<uint32_t*>(&h1);                           \
            o.z = *reinterpret_cast<uint32_t*>(&h2);                           \
            o.w = *reinterpret_cast<uint32_t*>(&h3);                           \
            *reinterpret_cast<uint4*>(                                         \
                smem + (s) * HG_STAGE + r * HG_ROWB + q2 * 16) = o;            \
        }                                                                      \
    } while (0)

#define VG_COPY_B(s, chunk)                                                    \
    do {                                                                       \
        const int _k0 = (chunk) * HG_KC;                                       \
        const uint32_t _dB = sbase + (s) * HG_STAGE + HG_TILE;                 \
        _Pragma("unroll")                                                      \
        for (int e = 0; e < 2; e++) {                                          \
            const int cc = tid + e * 256;                                      \
            const int r = cc >> 2;                                             \
            const int q = cc & 3;                                              \
            CP_ASYNC16(_dB + r * HG_ROWB + q * 16,                             \
                       &Bt[(size_t)(n0 + r) * K + _k0 + q * 8]);               \
        }                                                                      \
    } while (0)

    // prologue: A slots 0..2 via registers, B via cp.async
    VG_LDG_A(0);          VG_STS_A(0);
    VG_LDG_A(HG_KC);      VG_STS_A(1);
    VG_LDG_A(2 * HG_KC);  VG_STS_A(2);
    VG_COPY_B(0, 0); CP_COMMIT();
    VG_COPY_B(1, 1); CP_COMMIT();
    VG_COPY_B(2, 2); CP_COMMIT();

    for (int c = 0; c < nch; ++c) {
        CP_WAIT2();
        __syncthreads();

        const bool pre = (c + 3) < nch;
        if (pre) {
            VG_LDG_A((c + 3) * HG_KC);          // LDG early; latency hidden by MMAs
            VG_COPY_B((c + 3) % HG_STAGES, c + 3);
        }
        CP_COMMIT();

        const uint32_t stageBase = sbase + (c % HG_STAGES) * HG_STAGE;
        const uint32_t aBase = stageBase + aOff;
        const uint32_t bBase = stageBase + bOff;

#pragma unroll
        for (int ks = 0; ks < 2; ks++) {
            uint32_t a0[4], a1[4];
            ldsm_x4(a0, aBase + ks * 32);
            ldsm_x4(a1, aBase + 16 * HG_ROWB + ks * 32);
#pragma unroll
            for (int j = 0; j < 4; j++) {
                uint32_t b[4];
                ldsm_x4(b, bBase + j * 16 * HG_ROWB + ks * 32);
                mma_f16(acc[0][2 * j],     a0, b[0], b[1]);
                mma_f16(acc[1][2 * j],     a1, b[0], b[1]);
                mma_f16(acc[0][2 * j + 1], a0, b[2], b[3]);
                mma_f16(acc[1][2 * j + 1], a1, b[2], b[3]);
            }
        }

        if (pre) VG_STS_A((c + 3) % HG_STAGES);
        __syncthreads();
    }
#undef VG_LDG_A
#undef VG_STS_A
#undef VG_COPY_B

#pragma unroll
    for (int mt = 0; mt < 2; mt++) {
        const int row0 = m0 + wm * 32 + mt * 16 + g;
#pragma unroll
        for (int nt = 0; nt < 8; nt++) {
            const int col = n0 + wn * 64 + nt * 8 + tig * 2;
            const float bx = bias[col];
            const float by = bias[col + 1];
            __half2* p0 = reinterpret_cast<__half2*>(&C[(size_t)row0 * N + col]);
            __half2* p1 = reinterpret_cast<__half2*>(&C[(size_t)(row0 + 8) * N + col]);
            *p0 = __floats2half2_rn(acc[mt][nt][0] + bx, acc[mt][nt][1] + by);
            *p1 = __floats2half2_rn(acc[mt][nt][2] + bx, acc[mt][nt][3] + by);
        }
    }
}

// ===========================================================================
// Fused split-fp16 off/aw GEMM (off critical path — unchanged):
// C[M,128] = (Ah+Al) @ (Bh+Bl)^T + bias  (drops al@bl term)
// ===========================================================================
#define FG_TILE HG_TILE
#define FG_STAGE (4 * FG_TILE)
#define FG_STAGES 3
#define FG_SMEM (FG_STAGES * FG_STAGE)   // 122880 B

__global__ __launch_bounds__(256, 1)
void gemm_offaw_fused_kernel(const __half* __restrict__ Ah, const __half* __restrict__ Al,
                             const __half* __restrict__ Bh, const __half* __restrict__ Bl,
                             const float* __restrict__ bias, float* __restrict__ C,
                             int M, int K)
{
    extern __shared__ char smem[];
    const uint32_t sbase = smem_u32(smem);
    const int N = 128;

    const int tid  = threadIdx.x;
    const int wid  = tid >> 5;
    const int lane = tid & 31;
    const int g    = lane >> 2;
    const int tig  = lane & 3;
    const int wm   = wid & 3;
    const int wn   = wid >> 2;

    const int m0 = blockIdx.y * 128;

    float acc[2][8][4];
#pragma unroll
    for (int mt = 0; mt < 2; mt++)
#pragma unroll
        for (int nt = 0; nt < 8; nt++)
#pragma unroll
            for (int j = 0; j < 4; j++) acc[mt][nt][j] = 0.0f;

    const int nch = K / HG_KC;

#define FCOPY_STAGE(s, chunk)                                                  \
    do {                                                                       \
        const int _k0 = (chunk) * HG_KC;                                       \
        const uint32_t _d0 = sbase + (s) * FG_STAGE;                           \
        _Pragma("unroll")                                                      \
        for (int e = 0; e < 2; e++) {                                          \
            const int cc = tid + e * 256;                                      \
            const int r = cc >> 2;                                             \
            const int q = cc & 3;                                              \
            const uint32_t od = r * HG_ROWB + q * 16;                          \
            const size_t oa = (size_t)(m0 + r) * K + _k0 + q * 8;              \
            const size_t ob = (size_t)r * K + _k0 + q * 8;                     \
            CP_ASYNC16(_d0 + od,                 &Ah[oa]);                     \
            CP_ASYNC16(_d0 + FG_TILE + od,       &Al[oa]);                     \
            CP_ASYNC16(_d0 + 2 * FG_TILE + od,   &Bh[ob]);                     \
            CP_ASYNC16(_d0 + 3 * FG_TILE + od,   &Bl[ob]);                     \
        }                                                                      \
    } while (0)

    FCOPY_STAGE(0, 0); CP_COMMIT();
    FCOPY_STAGE(1, 1); CP_COMMIT();

    for (int c = 0; c < nch; ++c) {
        CP_WAIT1();
        __syncthreads();

        if (c + 2 < nch) {
            FCOPY_STAGE((c + 2) % FG_STAGES, c + 2);
        }
        CP_COMMIT();

        const int s = c % FG_STAGES;
        const uint32_t* SAh = reinterpret_cast<const uint32_t*>(smem + s * FG_STAGE);
        const uint32_t* SAl = SAh + FG_TILE / 4;
        const uint32_t* SBh = SAh + 2 * (FG_TILE / 4);
        const uint32_t* SBl = SAh + 3 * (FG_TILE / 4);

#pragma unroll
        for (int ks = 0; ks < 2; ks++) {
            const int kw = ks * 8 + tig;

            uint32_t ah[2][4], al[2][4];
#pragma unroll
            for (int mt = 0; mt < 2; mt++) {
                const int r = wm * 32 + mt * 16 + g;
                ah[mt][0] = SAh[r * 20 + kw];
                ah[mt][1] = SAh[(r + 8) * 20 + kw];
                ah[mt][2] = SAh[r * 20 + kw + 4];
                ah[mt][3] = SAh[(r + 8) * 20 + kw + 4];
                al[mt][0] = SAl[r * 20 + kw];
                al[mt][1] = SAl[(r + 8) * 20 + kw];
                al[mt][2] = SAl[r * 20 + kw + 4];
                al[mt][3] = SAl[(r + 8) * 20 + kw + 4];
            }
#pragma unroll
            for (int nt = 0; nt < 8; nt++) {
                const int n = wn * 64 + nt * 8 + g;
                const uint32_t bh0 = SBh[n * 20 + kw];
                const uint32_t bh1 = SBh[n * 20 + kw + 4];
                const uint32_t bl0 = SBl[n * 20 + kw];
                const uint32_t bl1 = SBl[n * 20 + kw + 4];
#pragma unroll
                for (int mt = 0; mt < 2; mt++) {
                    mma_f16(acc[mt][nt], ah[mt], bh0, bh1);
                    mma_f16(acc[mt][nt], ah[mt], bl0, bl1);
                    mma_f16(acc[mt][nt], al[mt], bh0, bh1);
                }
            }
        }
        __syncthreads();
    }
#undef FCOPY_STAGE

#pragma unroll
    for (int mt = 0; mt < 2; mt++) {
        const int row0 = m0 + wm * 32 + mt * 16 + g;
#pragma unroll
        for (int nt = 0; nt < 8; nt++) {
            const int col = wn * 64 + nt * 8 + tig * 2;
            const float bx = bias[col];
            const float by = bias[col + 1];
            float2 lo, hi;
            lo.x = acc[mt][nt][0] + bx;  lo.y = acc[mt][nt][1] + by;
            hi.x = acc[mt][nt][2] + bx;  hi.y = acc[mt][nt][3] + by;
            *reinterpret_cast<float2*>(&C[(size_t)row0 * N + col]) = lo;
            *reinterpret_cast<float2*>(&C[(size_t)(row0 + 8) * N + col]) = hi;
        }
    }
}

// ===========================================================================
// Prep kernels
// ===========================================================================
__global__ void transpose_h_kernel(const float* __restrict__ in,
                                   __half* __restrict__ out, int R, int C)
{
    __shared__ float tile[32][33];
    const int bx = blockIdx.x * 32;
    const int by = blockIdx.y * 32;
#pragma unroll
    for (int j = 0; j < 32; j += 8)
        tile[threadIdx.y + j][threadIdx.x] =
            in[(size_t)(by + threadIdx.y + j) * C + bx + threadIdx.x];
    __syncthreads();
#pragma unroll
    for (int j = 0; j < 32; j += 8)
        out[(size_t)(bx + threadIdx.y + j) * R + by + threadIdx.x] =
            __float2half_rn(tile[threadIdx.x][threadIdx.y + j]);
}

__global__ void split_h_kernel(const float4* __restrict__ in,
                               uint2* __restrict__ hi, uint2* __restrict__ lo,
                               int n4)
{
    const int i = blockIdx.x * 256 + threadIdx.x;
    if (i < n4) {
        const float4 a = in[i];
        const __half hx = __float2half_rn(a.x), hy = __float2half_rn(a.y);
        const __half hz = __float2half_rn(a.z), hw = __float2half_rn(a.w);
        const __half lx = __float2half_rn(a.x - __half2float(hx));
        const __half ly = __float2half_rn(a.y - __half2float(hy));
        const __half lz = __float2half_rn(a.z - __half2float(hz));
        const __half lw = __float2half_rn(a.w - __half2float(hw));
        __half2 h0 = __halves2half2(hx, hy), h1 = __halves2half2(hz, hw);
        __half2 l0 = __halves2half2(lx, ly), l1 = __halves2half2(lz, lw);
        uint2 oh, ol;
        oh.x = *reinterpret_cast<uint32_t*>(&h0);
        oh.y = *reinterpret_cast<uint32_t*>(&h1);
        ol.x = *reinterpret_cast<uint32_t*>(&l0);
        ol.y = *reinterpret_cast<uint32_t*>(&l1);
        hi[i] = oh;
        lo[i] = ol;
    }
}

__global__ void build_wq_split_kernel(const float* __restrict__ W_off,
                                      const float* __restrict__ W_aw,
                                      const float* __restrict__ b_off,
                                      const float* __restrict__ b_aw,
                                      __half* __restrict__ wqt_hi,
                                      __half* __restrict__ wqt_lo,
                                      float* __restrict__ bq)
{
    const int i = blockIdx.x * 256 + threadIdx.x;
    if (i < 128 * DMODEL) {
        const int n = i / DMODEL;
        const int k = i - n * DMODEL;
        float w = 0.0f;
        if (n < 64)      w = W_off[k * 64 + n];
        else if (n < 96) w = W_aw[k * 32 + (n - 64)];
        const __half h = __float2half_rn(w);
        const __half l = __float2half_rn(w - __half2float(h));
        wqt_hi[i] = h;
        wqt_lo[i] = l;
    }
    if (i < 128) {
        float bv = 0.0f;
        if (i < 64)      bv = b_off[i];
        else if (i < 96) bv = b_aw[i - 64];
        bq[i] = bv;
    }
}

// ===========================================================================
// Deformable sampling: 4 rows per block, 256 threads; uint4 (8-half) taps.
// v and mid fp16, math fp32 (per-channel fmaf order unchanged vs round 11).
// ===========================================================================
__global__ __launch_bounds__(256) void deform_kernel(
    const __half* __restrict__ v,
    const float* __restrict__ offaw,
    __half* __restrict__ mid)
{
    __shared__ float s_w0[4][NHEAD][NPNT];
    __shared__ float s_w1[4][NHEAD][NPNT];
    __shared__ int   s_i0[4][NHEAD][NPNT];
    __shared__ int   s_i1[4][NHEAD][NPNT];

    const int blk0 = blockIdx.x * 4;
    const int t = threadIdx.x;

    if (t < 32) {
        const int rr = t >> 3;
        const int h = t & 7;
        const int blk = blk0 + rr;
        const int l = blk & (LSEQ - 1);
        const float ref_y = (float)l / (float)(LSEQ - 1);
        const float* row = &offaw[(size_t)blk * 128];

        float lg[NPNT];
        float mx = -1e30f;
#pragma unroll
        for (int p = 0; p < NPNT; p++) {
            lg[p] = row[64 + h * NPNT + p];
            mx = fmaxf(mx, lg[p]);
        }
        float sum = 0.0f;
#pragma unroll
        for (int p = 0; p < NPNT; p++) { lg[p] = __expf(lg[p] - mx); sum += lg[p]; }
        const float inv = 1.0f / sum;

#pragma unroll
        for (int p = 0; p < NPNT; p++) {
            const float a = lg[p] * inv;
            const float ox = row[(h * NPNT + p) * 2 + 0];
            const float oy = row[(h * NPNT + p) * 2 + 1];
            const float locx = fminf(fmaxf(ox, 0.0f), 1.0f);
            const float locy = fminf(fmaxf(oy + ref_y, 0.0f), 1.0f);

            const float ix = ((locx + 1.0f) * (float)LSEQ - 1.0f) * 0.5f;
            const float iy = locy * 0.5f;
            const float ix0 = floorf(ix);
            const float fx = ix - ix0;
            const float iy0 = floorf(iy);
            const float fy = iy - iy0;
            const float ywt = (1.0f - fy) * (iy0 == 0.0f ? 1.0f : 0.0f)
                            + fy * ((iy0 + 1.0f) == 0.0f ? 1.0f : 0.0f);

            const int i0 = (int)ix0;
            const int i1 = i0 + 1;
            const float w = a * ywt;
            const bool v0 = (i0 >= 0) && (i0 < LSEQ);
            const bool v1 = (i1 >= 0) && (i1 < LSEQ);
            s_w0[rr][h][p] = v0 ? w * (1.0f - fx) : 0.0f;
            s_w1[rr][h][p] = v1 ? w * fx : 0.0f;
            s_i0[rr][h][p] = min(max(i0, 0), LSEQ - 1);
            s_i1[rr][h][p] = min(max(i1, 0), LSEQ - 1);
        }
    }
    __syncthreads();

    const int rr = t >> 6;           // 0..3 (row within block)
    const int u  = t & 63;
    const int h  = u >> 3;           // 0..7
    const int c8 = u & 7;            // uint4 (8-half) group within head
    const int blk = blk0 + rr;
    const int b = blk >> 11;         // blk / LSEQ

    const uint4* vb = reinterpret_cast<const uint4*>(
        v + (size_t)b * LSEQ * DMODEL + h * CHEAD) + c8;

    float a0 = 0.f, a1 = 0.f, a2 = 0.f, a3 = 0.f;
    float a4 = 0.f, a5 = 0.f, a6 = 0.f, a7 = 0.f;
#pragma unroll
    for (int p = 0; p < NPNT; p++) {
        const float w0 = s_w0[rr][h][p];
        const float w1 = s_w1[rr][h][p];
        const uint4 x0 = vb[(size_t)s_i0[rr][h][p] * (DMODEL / 8)];
        const uint4 x1 = vb[(size_t)s_i1[rr][h][p] * (DMODEL / 8)];
        const float2 f0a = __half22float2(*reinterpret_cast<const __half2*>(&x0.x));
        const float2 f0b = __half22float2(*reinterpret_cast<const __half2*>(&x0.y));
        const float2 f0c = __half22float2(*reinterpret_cast<const __half2*>(&x0.z));
        const float2 f0d = __half22float2(*reinterpret_cast<const __half2*>(&x0.w));
        const float2 f1a = __half22float2(*reinterpret_cast<const __half2*>(&x1.x));
        const float2 f1b = __half22float2(*reinterpret_cast<const __half2*>(&x1.y));
        const float2 f1c = __half22float2(*reinterpret_cast<const __half2*>(&x1.z));
        const float2 f1d = __half22float2(*reinterpret_cast<const __half2*>(&x1.w));
        a0 = fmaf(w0, f0a.x, a0); a1 = fmaf(w0, f0a.y, a1);
        a2 = fmaf(w0, f0b.x, a2); a3 = fmaf(w0, f0b.y, a3);
        a4 = fmaf(w0, f0c.x, a4); a5 = fmaf(w0, f0c.y, a5);
        a6 = fmaf(w0, f0d.x, a6); a7 = fmaf(w0, f0d.y, a7);
        a0 = fmaf(w1, f1a.x, a0); a1 = fmaf(w1, f1a.y, a1);
        a2 = fmaf(w1, f1b.x, a2); a3 = fmaf(w1, f1b.y, a3);
        a4 = fmaf(w1, f1c.x, a4); a5 = fmaf(w1, f1c.y, a5);
        a6 = fmaf(w1, f1d.x, a6); a7 = fmaf(w1, f1d.y, a7);
    }
    __half2 o0 = __floats2half2_rn(a0, a1);
    __half2 o1 = __floats2half2_rn(a2, a3);
    __half2 o2 = __floats2half2_rn(a4, a5);
    __half2 o3 = __floats2half2_rn(a6, a7);
    uint4 o;
    o.x = *reinterpret_cast<uint32_t*>(&o0);
    o.y = *reinterpret_cast<uint32_t*>(&o1);
    o.z = *reinterpret_cast<uint32_t*>(&o2);
    o.w = *reinterpret_cast<uint32_t*>(&o3);
    *reinterpret_cast<uint4*>(&mid[(size_t)blk * DMODEL + h * CHEAD + c8 * 8]) = o;
}

// ===========================================================================
// Host launch — fork/join
// ===========================================================================
extern "C" void kernel_launch(void* const* d_in, const int* in_sizes, int n_in,
                              void* d_out, int out_size)
{
    const float* query = (const float*)d_in[0];
    const float* value = (const float*)d_in[2];
    const float* W_v   = (const float*)d_in[3];
    const float* b_v   = (const float*)d_in[4];
    const float* W_off = (const float*)d_in[5];
    const float* b_off = (const float*)d_in[6];
    const float* W_aw  = (const float*)d_in[7];
    const float* b_aw  = (const float*)d_in[8];
    const float* W_out = (const float*)d_in[9];
    const float* b_out = (const float*)d_in[10];
    float* out = (float*)d_out;

    __half *pv, *pmid, *pwvt, *pwot, *pqhi, *pqlo, *pwqh, *pwql;
    float *poffaw, *pbq;
    cudaGetSymbolAddress((void**)&pv,     g_v);
    cudaGetSymbolAddress((void**)&pmid,   g_mid);
    cudaGetSymbolAddress((void**)&poffaw, g_offaw);
    cudaGetSymbolAddress((void**)&pwvt,   g_wvt);
    cudaGetSymbolAddress((void**)&pwot,   g_wot);
    cudaGetSymbolAddress((void**)&pqhi,   g_qhi);
    cudaGetSymbolAddress((void**)&pqlo,   g_qlo);
    cudaGetSymbolAddress((void**)&pwqh,   g_wqt_hi);
    cudaGetSymbolAddress((void**)&pwql,   g_wqt_lo);
    cudaGetSymbolAddress((void**)&pbq,    g_bq);

    cudaFuncSetAttribute((const void*)gemm_async_h_kernel<float>,
                         cudaFuncAttributeMaxDynamicSharedMemorySize, HG_SMEM);
    cudaFuncSetAttribute((const void*)gemm_v_f32a_kernel,
                         cudaFuncAttributeMaxDynamicSharedMemorySize, HG_SMEM);
    cudaFuncSetAttribute((const void*)gemm_offaw_fused_kernel,
                         cudaFuncAttributeMaxDynamicSharedMemorySize, FG_SMEM);

    // Fork.
    cudaEventRecord(g_ev0, 0);
    cudaStreamWaitEvent(g_s1, g_ev0, 0);

    // --- s1: off/aw chain via fused split-fp16 tensor GEMM + W_out transpose ---
    build_wq_split_kernel<<<(128 * DMODEL + 255) / 256, 256, 0, g_s1>>>(
        W_off, W_aw, b_off, b_aw, pwqh, pwql, pbq);
    split_h_kernel<<<(MROWS * DMODEL / 4 + 255) / 256, 256, 0, g_s1>>>(
        (const float4*)query, (uint2*)pqhi, (uint2*)pqlo, MROWS * DMODEL / 4);
    {
        dim3 grid(1, MROWS / 128);
        gemm_offaw_fused_kernel<<<grid, 256, FG_SMEM, g_s1>>>(
            pqhi, pqlo, pwqh, pwql, pbq, poffaw, MROWS, DMODEL);
    }
    {
        dim3 tb(32, 8);
        dim3 tg(DMODEL / 32, DMODEL / 32);
        transpose_h_kernel<<<tg, tb, 0, g_s1>>>(W_out, pwot, DMODEL, DMODEL);
    }
    cudaEventRecord(g_ev1, g_s1);

    // --- s0 (origin): W_v transpose, then v-GEMM with fused fp32-A convert ---
    {
        dim3 tb(32, 8);
        dim3 tg(DMODEL / 32, DMODEL / 32);
        transpose_h_kernel<<<tg, tb>>>(W_v, pwvt, DMODEL, DMODEL);
    }
    {
        dim3 grid(DMODEL / 128, MROWS / 128);
        gemm_v_f32a_kernel<<<grid, 256, HG_SMEM>>>(
            value, pwvt, b_v, pv, MROWS, DMODEL, DMODEL);
    }

    // Join: deform needs the off/aw chain too.
    cudaStreamWaitEvent(0, g_ev1, 0);
    deform_kernel<<<MROWS / 4, 256>>>(pv, poffaw, pmid);

    // --- out = mid @ W_out + b_out (fp16 mma, fp32 out) ---
    {
        dim3 grid(DMODEL / 128, MROWS / 128);
        gemm_async_h_kernel<float><<<grid, 256, HG_SMEM>>>(
            pmid, pwot, b_out, out, MROWS, DMODEL, DMODEL);
    }
}

// round 13
// speedup vs baseline: 5.1964x; 1.0884x over previous
#include <cuda_runtime.h>
#include <cuda_fp16.h>
#include <math.h>
#include <stdint.h>

// Problem constants
#define BATCH 8
#define LSEQ  2048
#define DMODEL 512
#define NHEAD 8
#define NPNT  4
#define CHEAD 64
#define MROWS (BATCH * LSEQ)   // 16384

// Scratch (device globals; no allocation allowed)
__device__ __align__(16) __half g_v[MROWS * DMODEL];      // value projection (fp16)
__device__ __align__(16) __half g_mid[MROWS * DMODEL];    // deform output (fp16)
__device__ __align__(16) float  g_offaw[MROWS * 128];     // off(64)|aw(32)|pad, fp32
__device__ __align__(16) __half g_wvt[DMODEL * DMODEL];   // W_v^T   fp16 [N][K]
__device__ __align__(16) __half g_wot[DMODEL * DMODEL];   // W_out^T fp16 [N][K]
__device__ __align__(16) __half g_wqt_hi[128 * DMODEL];   // Wq^T hi fp16 [128][512]
__device__ __align__(16) __half g_wqt_lo[128 * DMODEL];   // Wq^T lo fp16
__device__ __align__(16) float  g_bq[128];

// Streams/events for fork-join overlap (created once at module load).
static cudaStream_t g_s1;
static cudaEvent_t g_ev0, g_ev1, g_ev2;
namespace {
struct StreamInit {
    StreamInit() {
        cudaStreamCreateWithFlags(&g_s1, cudaStreamNonBlocking);
        cudaEventCreateWithFlags(&g_ev0, cudaEventDisableTiming);
        cudaEventCreateWithFlags(&g_ev1, cudaEventDisableTiming);
        cudaEventCreateWithFlags(&g_ev2, cudaEventDisableTiming);
    }
};
StreamInit g_stream_init;
}

__device__ __forceinline__ uint32_t smem_u32(const void* p) {
    uint32_t a;
    asm("{ .reg .u64 t; cvta.to.shared.u64 t, %1; cvt.u32.u64 %0, t; }" : "=r"(a) : "l"(p));
    return a;
}

__device__ __forceinline__ void mma_f16(float c[4],
                                        const uint32_t a[4],
                                        uint32_t b0, uint32_t b1) {
    asm volatile(
        "mma.sync.aligned.m16n8k16.row.col.f32.f16.f16.f32 "
        "{%0,%1,%2,%3}, {%4,%5,%6,%7}, {%8,%9}, {%0,%1,%2,%3};"
        : "+f"(c[0]), "+f"(c[1]), "+f"(c[2]), "+f"(c[3])
        : "r"(a[0]), "r"(a[1]), "r"(a[2]), "r"(a[3]), "r"(b0), "r"(b1));
}

__device__ __forceinline__ void ldsm_x4(uint32_t r[4], uint32_t addr) {
    asm volatile(
        "ldmatrix.sync.aligned.m8n8.x4.shared.b16 {%0,%1,%2,%3}, [%4];"
        : "=r"(r[0]), "=r"(r[1]), "=r"(r[2]), "=r"(r[3]) : "r"(addr));
}

#define CP_ASYNC16(dst, src) \
    asm volatile("cp.async.cg.shared.global [%0], [%1], 16;" :: "r"(dst), "l"(src) : "memory")
#define CP_COMMIT() asm volatile("cp.async.commit_group;" ::: "memory")
#define CP_WAIT1()  asm volatile("cp.async.wait_group 1;" ::: "memory")
#define CP_WAIT2()  asm volatile("cp.async.wait_group 2;" ::: "memory")

// Common tile geometry
#define HG_KC 32
#define HG_ROWB 80
#define HG_TILE (128 * HG_ROWB)
#define HG_STAGE (2 * HG_TILE)
#define HG_STAGES 4
#define HG_SMEM (HG_STAGES * HG_STAGE)  // 81920 B

// ===========================================================================
// Async fp16 GEMM (fp16 A): C[M,N] = A @ Bt^T + bias. (out-GEMM, fp32 out)
// ===========================================================================
template <typename OutT>
__global__ __launch_bounds__(256, 2)
void gemm_async_h_kernel(const __half* __restrict__ A, const __half* __restrict__ Bt,
                         const float* __restrict__ bias, OutT* __restrict__ C,
                         int M, int N, int K)
{
    extern __shared__ char smem[];
    const uint32_t sbase = smem_u32(smem);

    const int tid  = threadIdx.x;
    const int wid  = tid >> 5;
    const int lane = tid & 31;
    const int g    = lane >> 2;
    const int tig  = lane & 3;
    const int wm   = wid & 3;
    const int wn   = wid >> 2;

    const int m0 = blockIdx.y * 128;
    const int n0 = blockIdx.x * 128;

    const uint32_t aOff = (uint32_t)((wm * 32 + (lane & 15)) * HG_ROWB + (lane >> 4) * 16);
    const uint32_t bOff = (uint32_t)(HG_TILE +
        (wn * 64 + (lane & 7) + (lane >> 4) * 8) * HG_ROWB + ((lane >> 3) & 1) * 16);

    float acc[2][8][4];
#pragma unroll
    for (int mt = 0; mt < 2; mt++)
#pragma unroll
        for (int nt = 0; nt < 8; nt++)
#pragma unroll
            for (int j = 0; j < 4; j++) acc[mt][nt][j] = 0.0f;

    const int nch = K / HG_KC;

#define HCOPY_STAGE(s, chunk)                                                  \
    do {                                                                       \
        const int _k0 = (chunk) * HG_KC;                                       \
        const uint32_t _dA = sbase + (s) * HG_STAGE;                           \
        const uint32_t _dB = _dA + HG_TILE;                                    \
        _Pragma("unroll")                                                      \
        for (int e = 0; e < 2; e++) {                                          \
            const int cc = tid + e * 256;                                      \
            const int r = cc >> 2;                                             \
            const int q = cc & 3;                                              \
            CP_ASYNC16(_dA + r * HG_ROWB + q * 16,                             \
                       &A[(size_t)(m0 + r) * K + _k0 + q * 8]);                \
            CP_ASYNC16(_dB + r * HG_ROWB + q * 16,                             \
                       &Bt[(size_t)(n0 + r) * K + _k0 + q * 8]);               \
        }                                                                      \
    } while (0)

    HCOPY_STAGE(0, 0); CP_COMMIT();
    HCOPY_STAGE(1, 1); CP_COMMIT();
    HCOPY_STAGE(2, 2); CP_COMMIT();

    for (int c = 0; c < nch; ++c) {
        CP_WAIT2();
        __syncthreads();

        if (c + 3 < nch) {
            HCOPY_STAGE((c + 3) % HG_STAGES, c + 3);
        }
        CP_COMMIT();

        const uint32_t stageBase = sbase + (c % HG_STAGES) * HG_STAGE;
        const uint32_t aBase = stageBase + aOff;
        const uint32_t bBase = stageBase + bOff;

#pragma unroll
        for (int ks = 0; ks < 2; ks++) {
            uint32_t a0[4], a1[4];
            ldsm_x4(a0, aBase + ks * 32);
            ldsm_x4(a1, aBase + 16 * HG_ROWB + ks * 32);
#pragma unroll
            for (int j = 0; j < 4; j++) {
                uint32_t b[4];
                ldsm_x4(b, bBase + j * 16 * HG_ROWB + ks * 32);
                mma_f16(acc[0][2 * j],     a0, b[0], b[1]);
                mma_f16(acc[1][2 * j],     a1, b[0], b[1]);
                mma_f16(acc[0][2 * j + 1], a0, b[2], b[3]);
                mma_f16(acc[1][2 * j + 1], a1, b[2], b[3]);
            }
        }
        __syncthreads();
    }
#undef HCOPY_STAGE

#pragma unroll
    for (int mt = 0; mt < 2; mt++) {
        const int row0 = m0 + wm * 32 + mt * 16 + g;
#pragma unroll
        for (int nt = 0; nt < 8; nt++) {
            const int col = n0 + wn * 64 + nt * 8 + tig * 2;
            const float bx = bias[col];
            const float by = bias[col + 1];
            const float l0 = acc[mt][nt][0] + bx;
            const float l1 = acc[mt][nt][1] + by;
            const float h0 = acc[mt][nt][2] + bx;
            const float h1 = acc[mt][nt][3] + by;
            if constexpr (sizeof(OutT) == 2) {
                __half2* p0 = reinterpret_cast<__half2*>(&C[(size_t)row0 * N + col]);
                __half2* p1 = reinterpret_cast<__half2*>(&C[(size_t)(row0 + 8) * N + col]);
                *p0 = __floats2half2_rn(l0, l1);
                *p1 = __floats2half2_rn(h0, h1);
            } else {
                float2 lo, hi;
                lo.x = l0; lo.y = l1; hi.x = h0; hi.y = h1;
                *reinterpret_cast<float2*>(&C[(size_t)row0 * N + col]) = lo;
                *reinterpret_cast<float2*>(&C[(size_t)(row0 + 8) * N + col]) = hi;
            }
        }
    }
}

// ===========================================================================
// v-GEMM with fused fp32->fp16 A conversion (unchanged from round 12).
// ===========================================================================
__global__ __launch_bounds__(256, 2)
void gemm_v_f32a_kernel(const float* __restrict__ A, const __half* __restrict__ Bt,
                        const float* __restrict__ bias, __half* __restrict__ C,
                        int M, int N, int K)
{
    extern __shared__ char smem[];
    const uint32_t sbase = smem_u32(smem);

    const int tid  = threadIdx.x;
    const int wid  = tid >> 5;
    const int lane = tid & 31;
    const int g    = lane >> 2;
    const int tig  = lane & 3;
    const int wm   = wid & 3;
    const int wn   = wid >> 2;

    const int m0 = blockIdx.y * 128;
    const int n0 = blockIdx.x * 128;

    const uint32_t aOff = (uint32_t)((wm * 32 + (lane & 15)) * HG_ROWB + (lane >> 4) * 16);
    const uint32_t bOff = (uint32_t)(HG_TILE +
        (wn * 64 + (lane & 7) + (lane >> 4) * 8) * HG_ROWB + ((lane >> 3) & 1) * 16);

    float4 areg[2][2];

    float acc[2][8][4];
#pragma unroll
    for (int mt = 0; mt < 2; mt++)
#pragma unroll
        for (int nt = 0; nt < 8; nt++)
#pragma unroll
            for (int j = 0; j < 4; j++) acc[mt][nt][j] = 0.0f;

    const int nch = K / HG_KC;

#define VG_LDG_A(k0)                                                           \
    do {                                                                       \
        _Pragma("unroll")                                                      \
        for (int e = 0; e < 2; e++) {                                          \
            const int i = tid + e * 256;                                       \
            const int r = i >> 2;                                              \
            const int q2 = i & 3;                                              \
            const float* pA = &A[(size_t)(m0 + r) * K + (k0) + q2 * 8];        \
            areg[e][0] = *reinterpret_cast<const float4*>(pA);                 \
            areg[e][1] = *reinterpret_cast<const float4*>(pA + 4);             \
        }                                                                      \
    } while (0)

#define VG_STS_A(s)                                                            \
    do {                                                                       \
        _Pragma("unroll")                                                      \
        for (int e = 0; e < 2; e++) {                                          \
            const int i = tid + e * 256;                                       \
            const int r = i >> 2;                                              \
            const int q2 = i & 3;                                              \
            __half2 h0 = __floats2half2_rn(areg[e][0].x, areg[e][0].y);        \
            __half2 h1 = __floats2half2_rn(areg[e][0].z, areg[e][0].w);        \
            __half2 h2 = __floats2half2_rn(areg[e][1].x, areg[e][1].y);        \
            __half2 h3 = __floats2half2_rn(areg[e][1].z, areg[e][1].w);        \
            uint4 o;                                                           \
            o.x = *reinterpret_cast<uint32_t*>(&h0);                           \
            o.y = *reinterpret_cast<uint32_t*>(&h1);                           \
            o.z = *reinterpret_cast<uint32_t*>(&h2);                           \
            o.w = *reinterpret_cast<uint32_t*>(&h3);                           \
            *reinterpret_cast<uint4*>(                                         \
                smem + (s) * HG_STAGE + r * HG_ROWB + q2 * 16) = o;            \
        }                                                                      \
    } while (0)

#define VG_COPY_B(s, chunk)                                                    \
    do {                                                                       \
        const int _k0 = (chunk) * HG_KC;                                       \
        const uint32_t _dB = sbase + (s) * HG_STAGE + HG_TILE;                 \
        _Pragma("unroll")                                                      \
        for (int e = 0; e < 2; e++) {                                          \
            const int cc = tid + e * 256;                                      \
            const int r = cc >> 2;                                             \
            const int q = cc & 3;                                              \
            CP_ASYNC16(_dB + r * HG_ROWB + q * 16,                             \
                       &Bt[(size_t)(n0 + r) * K + _k0 + q * 8]);               \
        }                                                                      \
    } while (0)

    VG_LDG_A(0);          VG_STS_A(0);
    VG_LDG_A(HG_KC);      VG_STS_A(1);
    VG_LDG_A(2 * HG_KC);  VG_STS_A(2);
    VG_COPY_B(0, 0); CP_COMMIT();
    VG_COPY_B(1, 1); CP_COMMIT();
    VG_COPY_B(2, 2); CP_COMMIT();

    for (int c = 0; c < nch; ++c) {
        CP_WAIT2();
        __syncthreads();

        const bool pre = (c + 3) < nch;
        if (pre) {
            VG_LDG_A((c + 3) * HG_KC);
            VG_COPY_B((c + 3) % HG_STAGES, c + 3);
        }
        CP_COMMIT();

        const uint32_t stageBase = sbase + (c % HG_STAGES) * HG_STAGE;
        const uint32_t aBase = stageBase + aOff;
        const uint32_t bBase = stageBase + bOff;

#pragma unroll
        for (int ks = 0; ks < 2; ks++) {
            uint32_t a0[4], a1[4];
            ldsm_x4(a0, aBase + ks * 32);
            ldsm_x4(a1, aBase + 16 * HG_ROWB + ks * 32);
#pragma unroll
            for (int j = 0; j < 4; j++) {
                uint32_t b[4];
                ldsm_x4(b, bBase + j * 16 * HG_ROWB + ks * 32);
                mma_f16(acc[0][2 * j],     a0, b[0], b[1]);
                mma_f16(acc[1][2 * j],     a1, b[0], b[1]);
                mma_f16(acc[0][2 * j + 1], a0, b[2], b[3]);
                mma_f16(acc[1][2 * j + 1], a1, b[2], b[3]);
            }
        }

        if (pre) VG_STS_A((c + 3) % HG_STAGES);
        __syncthreads();
    }
#undef VG_LDG_A
#undef VG_STS_A
#undef VG_COPY_B

#pragma unroll
    for (int mt = 0; mt < 2; mt++) {
        const int row0 = m0 + wm * 32 + mt * 16 + g;
#pragma unroll
        for (int nt = 0; nt < 8; nt++) {
            const int col = n0 + wn * 64 + nt * 8 + tig * 2;
            const float bx = bias[col];
            const float by = bias[col + 1];
            __half2* p0 = reinterpret_cast<__half2*>(&C[(size_t)row0 * N + col]);
            __half2* p1 = reinterpret_cast<__half2*>(&C[(size_t)(row0 + 8) * N + col]);
            *p0 = __floats2half2_rn(acc[mt][nt][0] + bx, acc[mt][nt][1] + by);
            *p1 = __floats2half2_rn(acc[mt][nt][2] + bx, acc[mt][nt][3] + by);
        }
    }
}

// ===========================================================================
// Fused split-fp16 off/aw GEMM with IN-KERNEL query split + ldmatrix:
// C[M,128] = (hi(Q)+lo(Q)) @ (Bh+Bl)^T + bias  (drops lo@lo)
// A: LDG fp32 -> hi/lo fp16 tiles in smem. B: cp.async.
// Stage = Ah|Al|Bh|Bl (4 x 10240B); 3 stages = 120KB smem, 1 CTA/SM.
// Per-acc MMA order per ks: hh, hl, lh (matches prior rounds bit-exactly).
// ===========================================================================
#define FG_TILE HG_TILE
#define FG_STAGE (4 * FG_TILE)
#define FG_STAGES 3
#define FG_SMEM (FG_STAGES * FG_STAGE)   // 122880 B

__global__ __launch_bounds__(256, 1)
void gemm_offaw_fused_kernel(const float* __restrict__ Q,
                             const __half* __restrict__ Bh, const __half* __restrict__ Bl,
                             const float* __restrict__ bias, float* __restrict__ C,
                             int M, int K)
{
    extern __shared__ char smem[];
    const uint32_t sbase = smem_u32(smem);
    const int N = 128;

    const int tid  = threadIdx.x;
    const int wid  = tid >> 5;
    const int lane = tid & 31;
    const int g    = lane >> 2;
    const int tig  = lane & 3;
    const int wm   = wid & 3;
    const int wn   = wid >> 2;

    const int m0 = blockIdx.y * 128;

    // ldmatrix offsets (relative to stage base)
    const uint32_t aOff = (uint32_t)((wm * 32 + (lane & 15)) * HG_ROWB + (lane >> 4) * 16);
    const uint32_t bOff = (uint32_t)(
        (wn * 64 + (lane & 7) + (lane >> 4) * 8) * HG_ROWB + ((lane >> 3) & 1) * 16);

    float4 areg[2][2];

    float acc[2][8][4];
#pragma unroll
    for (int mt = 0; mt < 2; mt++)
#pragma unroll
        for (int nt = 0; nt < 8; nt++)
#pragma unroll
            for (int j = 0; j < 4; j++) acc[mt][nt][j] = 0.0f;

    const int nch = K / HG_KC;

#define FO_LDG_A(k0)                                                           \
    do {                                                                       \
        _Pragma("unroll")                                                      \
        for (int e = 0; e < 2; e++) {                                          \
            const int i = tid + e * 256;                                       \
            const int r = i >> 2;                                              \
            const int q2 = i & 3;                                              \
            const float* pQ = &Q[(size_t)(m0 + r) * K + (k0) + q2 * 8];        \
            areg[e][0] = *reinterpret_cast<const float4*>(pQ);                 \
            areg[e][1] = *reinterpret_cast<const float4*>(pQ + 4);             \
        }                                                                      \
    } while (0)

#define FO_STS_A(s)                                                            \
    do {                                                                       \
        _Pragma("unroll")                                                      \
        for (int e = 0; e < 2; e++) {                                          \
            const int i = tid + e * 256;                                       \
            const int r = i >> 2;                                              \
            const int q2 = i & 3;                                              \
            const uint32_t od = (s) * FG_STAGE + r * HG_ROWB + q2 * 16;        \
            float hf[8], lf[8];                                                \
            const float* av = reinterpret_cast<const float*>(areg[e]);         \
            _Pragma("unroll")                                                  \
            for (int x = 0; x < 8; x++) {                                      \
                const __half hh = __float2half_rn(av[x]);                      \
                hf[x] = __half2float(hh);                                      \
                lf[x] = av[x] - hf[x];                                         \
            }                                                                  \
            __half2 H[4], L[4];                                                \
            _Pragma("unroll")                                                  \
            for (int x = 0; x < 4; x++) {                                      \
                H[x] = __floats2half2_rn(hf[2 * x], hf[2 * x + 1]);            \
                L[x] = __floats2half2_rn(lf[2 * x], lf[2 * x + 1]);            \
            }                                                                  \
            uint4 oh, ol;                                                      \
            oh.x = *reinterpret_cast<uint32_t*>(&H[0]);                        \
            oh.y = *reinterpret_cast<uint32_t*>(&H[1]);                        \
            oh.z = *reinterpret_cast<uint32_t*>(&H[2]);                        \
            oh.w = *reinterpret_cast<uint32_t*>(&H[3]);                        \
            ol.x = *reinterpret_cast<uint32_t*>(&L[0]);                        \
            ol.y = *reinterpret_cast<uint32_t*>(&L[1]);                        \
            ol.z = *reinterpret_cast<uint32_t*>(&L[2]);                        \
            ol.w = *reinterpret_cast<uint32_t*>(&L[3]);                        \
            *reinterpret_cast<uint4*>(smem + od) = oh;                         \
            *reinterpret_cast<uint4*>(smem + FG_TILE + od) = ol;               \
        }                                                                      \
    } while (0)

#define FO_COPY_B(s, chunk)                                                    \
    do {                                                                       \
        const int _k0 = (chunk) * HG_KC;                                       \
        const uint32_t _d0 = sbase + (s) * FG_STAGE;                           \
        _Pragma("unroll")                                                      \
        for (int e = 0; e < 2; e++) {                                          \
            const int cc = tid + e * 256;                                      \
            const int r = cc >> 2;                                             \
            const int q = cc & 3;                                              \
            const uint32_t od = r * HG_ROWB + q * 16;                          \
            const size_t ob = (size_t)r * K + _k0 + q * 8;                     \
            CP_ASYNC16(_d0 + 2 * FG_TILE + od, &Bh[ob]);                       \
            CP_ASYNC16(_d0 + 3 * FG_TILE + od, &Bl[ob]);                       \
        }                                                                      \
    } while (0)

    // prologue: A via registers (2 stages), B via cp.async (2 stages)
    FO_LDG_A(0);      FO_STS_A(0);
    FO_LDG_A(HG_KC);  FO_STS_A(1);
    FO_COPY_B(0, 0); CP_COMMIT();
    FO_COPY_B(1, 1); CP_COMMIT();

    for (int c = 0; c < nch; ++c) {
        CP_WAIT1();
        __syncthreads();

        const bool pre = (c + 2) < nch;
        if (pre) {
            FO_LDG_A((c + 2) * HG_KC);
            FO_COPY_B((c + 2) % FG_STAGES, c + 2);
        }
        CP_COMMIT();

        const uint32_t stageBase = sbase + (c % FG_STAGES) * FG_STAGE;
        const uint32_t ahBase = stageBase + aOff;
        const uint32_t alBase = ahBase + FG_TILE;
        const uint32_t bhBase = stageBase + 2 * FG_TILE + bOff;
        const uint32_t blBase = bhBase + FG_TILE;

#pragma unroll
        for (int ks = 0; ks < 2; ks++) {
            uint32_t ah0[4], ah1[4], al0[4], al1[4];
            ldsm_x4(ah0, ahBase + ks * 32);
            ldsm_x4(ah1, ahBase + 16 * HG_ROWB + ks * 32);
            ldsm_x4(al0, alBase + ks * 32);
            ldsm_x4(al1, alBase + 16 * HG_ROWB + ks * 32);
#pragma unroll
            for (int j = 0; j < 4; j++) {
                uint32_t bh[4], bl[4];
                ldsm_x4(bh, bhBase + j * 16 * HG_ROWB + ks * 32);
                ldsm_x4(bl, blBase + j * 16 * HG_ROWB + ks * 32);
                // per-acc order: hh, hl, lh (bit-identical to prior rounds)
                mma_f16(acc[0][2 * j],     ah0, bh[0], bh[1]);
                mma_f16(acc[0][2 * j],     ah0, bl[0], bl[1]);
                mma_f16(acc[0][2 * j],     al0, bh[0], bh[1]);
                mma_f16(acc[1][2 * j],     ah1, bh[0], bh[1]);
                mma_f16(acc[1][2 * j],     ah1, bl[0], bl[1]);
                mma_f16(acc[1][2 * j],     al1, bh[0], bh[1]);
                mma_f16(acc[0][2 * j + 1], ah0, bh[2], bh[3]);
                mma_f16(acc[0][2 * j + 1], ah0, bl[2], bl[3]);
                mma_f16(acc[0][2 * j + 1], al0, bh[2], bh[3]);
                mma_f16(acc[1][2 * j + 1], ah1, bh[2], bh[3]);
                mma_f16(acc[1][2 * j + 1], ah1, bl[2], bl[3]);
                mma_f16(acc[1][2 * j + 1], al1, bh[2], bh[3]);
            }
        }

        if (pre) FO_STS_A((c + 2) % FG_STAGES);
        __syncthreads();
    }
#undef FO_LDG_A
#undef FO_STS_A
#undef FO_COPY_B

#pragma unroll
    for (int mt = 0; mt < 2; mt++) {
        const int row0 = m0 + wm * 32 + mt * 16 + g;
#pragma unroll
        for (int nt = 0; nt < 8; nt++) {
            const int col = wn * 64 + nt * 8 + tig * 2;
            const float bx = bias[col];
            const float by = bias[col + 1];
            float2 lo, hi;
            lo.x = acc[mt][nt][0] + bx;  lo.y = acc[mt][nt][1] + by;
            hi.x = acc[mt][nt][2] + bx;  hi.y = acc[mt][nt][3] + by;
            *reinterpret_cast<float2*>(&C[(size_t)row0 * N + col]) = lo;
            *reinterpret_cast<float2*>(&C[(size_t)(row0 + 8) * N + col]) = hi;
        }
    }
}

// ===========================================================================
// Prep kernels
// ===========================================================================
__global__ void transpose_h_kernel(const float* __restrict__ in,
                                   __half* __restrict__ out, int R, int C)
{
    __shared__ float tile[32][33];
    const int bx = blockIdx.x * 32;
    const int by = blockIdx.y * 32;
#pragma unroll
    for (int j = 0; j < 32; j += 8)
        tile[threadIdx.y + j][threadIdx.x] =
            in[(size_t)(by + threadIdx.y + j) * C + bx + threadIdx.x];
    __syncthreads();
#pragma unroll
    for (int j = 0; j < 32; j += 8)
        out[(size_t)(bx + threadIdx.y + j) * R + by + threadIdx.x] =
            __float2half_rn(tile[threadIdx.x][threadIdx.y + j]);
}

__global__ void build_wq_split_kernel(const float* __restrict__ W_off,
                                      const float* __restrict__ W_aw,
                                      const float* __restrict__ b_off,
                                      const float* __restrict__ b_aw,
                                      __half* __restrict__ wqt_hi,
                                      __half* __restrict__ wqt_lo,
                                      float* __restrict__ bq)
{
    const int i = blockIdx.x * 256 + threadIdx.x;
    if (i < 128 * DMODEL) {
        const int n = i / DMODEL;
        const int k = i - n * DMODEL;
        float w = 0.0f;
        if (n < 64)      w = W_off[k * 64 + n];
        else if (n < 96) w = W_aw[k * 32 + (n - 64)];
        const __half h = __float2half_rn(w);
        const __half l = __float2half_rn(w - __half2float(h));
        wqt_hi[i] = h;
        wqt_lo[i] = l;
    }
    if (i < 128) {
        float bv = 0.0f;
        if (i < 64)      bv = b_off[i];
        else if (i < 96) bv = b_aw[i - 64];
        bq[i] = bv;
    }
}

// ===========================================================================
// Deformable sampling: 4 rows per block, 256 threads; uint4 (8-half) taps.
// ===========================================================================
__global__ __launch_bounds__(256) void deform_kernel(
    const __half* __restrict__ v,
    const float* __restrict__ offaw,
    __half* __restrict__ mid)
{
    __shared__ float s_w0[4][NHEAD][NPNT];
    __shared__ float s_w1[4][NHEAD][NPNT];
    __shared__ int   s_i0[4][NHEAD][NPNT];
    __shared__ int   s_i1[4][NHEAD][NPNT];

    const int blk0 = blockIdx.x * 4;
    const int t = threadIdx.x;

    if (t < 32) {
        const int rr = t >> 3;
        const int h = t & 7;
        const int blk = blk0 + rr;
        const int l = blk & (LSEQ - 1);
        const float ref_y = (float)l / (float)(LSEQ - 1);
        const float* row = &offaw[(size_t)blk * 128];

        float lg[NPNT];
        float mx = -1e30f;
#pragma unroll
        for (int p = 0; p < NPNT; p++) {
            lg[p] = row[64 + h * NPNT + p];
            mx = fmaxf(mx, lg[p]);
        }
        float sum = 0.0f;
#pragma unroll
        for (int p = 0; p < NPNT; p++) { lg[p] = __expf(lg[p] - mx); sum += lg[p]; }
        const float inv = 1.0f / sum;

#pragma unroll
        for (int p = 0; p < NPNT; p++) {
            const float a = lg[p] * inv;
            const float ox = row[(h * NPNT + p) * 2 + 0];
            const float oy = row[(h * NPNT + p) * 2 + 1];
            const float locx = fminf(fmaxf(ox, 0.0f), 1.0f);
            const float locy = fminf(fmaxf(oy + ref_y, 0.0f), 1.0f);

            const float ix = ((locx + 1.0f) * (float)LSEQ - 1.0f) * 0.5f;
            const float iy = locy * 0.5f;
            const float ix0 = floorf(ix);
            const float fx = ix - ix0;
            const float iy0 = floorf(iy);
            const float fy = iy - iy0;
            const float ywt = (1.0f - fy) * (iy0 == 0.0f ? 1.0f : 0.0f)
                            + fy * ((iy0 + 1.0f) == 0.0f ? 1.0f : 0.0f);

            const int i0 = (int)ix0;
            const int i1 = i0 + 1;
            const float w = a * ywt;
            const bool v0 = (i0 >= 0) && (i0 < LSEQ);
            const bool v1 = (i1 >= 0) && (i1 < LSEQ);
            s_w0[rr][h][p] = v0 ? w * (1.0f - fx) : 0.0f;
            s_w1[rr][h][p] = v1 ? w * fx : 0.0f;
            s_i0[rr][h][p] = min(max(i0, 0), LSEQ - 1);
            s_i1[rr][h][p] = min(max(i1, 0), LSEQ - 1);
        }
    }
    __syncthreads();

    const int rr = t >> 6;
    const int u  = t & 63;
    const int h  = u >> 3;
    const int c8 = u & 7;
    const int blk = blk0 + rr;
    const int b = blk >> 11;

    const uint4* vb = reinterpret_cast<const uint4*>(
        v + (size_t)b * LSEQ * DMODEL + h * CHEAD) + c8;

    float a0 = 0.f, a1 = 0.f, a2 = 0.f, a3 = 0.f;
    float a4 = 0.f, a5 = 0.f, a6 = 0.f, a7 = 0.f;
#pragma unroll
    for (int p = 0; p < NPNT; p++) {
        const float w0 = s_w0[rr][h][p];
        const float w1 = s_w1[rr][h][p];
        const uint4 x0 = vb[(size_t)s_i0[rr][h][p] * (DMODEL / 8)];
        const uint4 x1 = vb[(size_t)s_i1[rr][h][p] * (DMODEL / 8)];
        const float2 f0a = __half22float2(*reinterpret_cast<const __half2*>(&x0.x));
        const float2 f0b = __half22float2(*reinterpret_cast<const __half2*>(&x0.y));
        const float2 f0c = __half22float2(*reinterpret_cast<const __half2*>(&x0.z));
        const float2 f0d = __half22float2(*reinterpret_cast<const __half2*>(&x0.w));
        const float2 f1a = __half22float2(*reinterpret_cast<const __half2*>(&x1.x));
        const float2 f1b = __half22float2(*reinterpret_cast<const __half2*>(&x1.y));
        const float2 f1c = __half22float2(*reinterpret_cast<const __half2*>(&x1.z));
        const float2 f1d = __half22float2(*reinterpret_cast<const __half2*>(&x1.w));
        a0 = fmaf(w0, f0a.x, a0); a1 = fmaf(w0, f0a.y, a1);
        a2 = fmaf(w0, f0b.x, a2); a3 = fmaf(w0, f0b.y, a3);
        a4 = fmaf(w0, f0c.x, a4); a5 = fmaf(w0, f0c.y, a5);
        a6 = fmaf(w0, f0d.x, a6); a7 = fmaf(w0, f0d.y, a7);
        a0 = fmaf(w1, f1a.x, a0); a1 = fmaf(w1, f1a.y, a1);
        a2 = fmaf(w1, f1b.x, a2); a3 = fmaf(w1, f1b.y, a3);
        a4 = fmaf(w1, f1c.x, a4); a5 = fmaf(w1, f1c.y, a5);
        a6 = fmaf(w1, f1d.x, a6); a7 = fmaf(w1, f1d.y, a7);
    }
    __half2 o0 = __floats2half2_rn(a0, a1);
    __half2 o1 = __floats2half2_rn(a2, a3);
    __half2 o2 = __floats2half2_rn(a4, a5);
    __half2 o3 = __floats2half2_rn(a6, a7);
    uint4 o;
    o.x = *reinterpret_cast<uint32_t*>(&o0);
    o.y = *reinterpret_cast<uint32_t*>(&o1);
    o.z = *reinterpret_cast<uint32_t*>(&o2);
    o.w = *reinterpret_cast<uint32_t*>(&o3);
    *reinterpret_cast<uint4*>(&mid[(size_t)blk * DMODEL + h * CHEAD + c8 * 8]) = o;
}

// ===========================================================================
// Host launch — fork/join; tW_out hidden under deform
// ===========================================================================
extern "C" void kernel_launch(void* const* d_in, const int* in_sizes, int n_in,
                              void* d_out, int out_size)
{
    const float* query = (const float*)d_in[0];
    const float* value = (const float*)d_in[2];
    const float* W_v   = (const float*)d_in[3];
    const float* b_v   = (const float*)d_in[4];
    const float* W_off = (const float*)d_in[5];
    const float* b_off = (const float*)d_in[6];
    const float* W_aw  = (const float*)d_in[7];
    const float* b_aw  = (const float*)d_in[8];
    const float* W_out = (const float*)d_in[9];
    const float* b_out = (const float*)d_in[10];
    float* out = (float*)d_out;

    __half *pv, *pmid, *pwvt, *pwot, *pwqh, *pwql;
    float *poffaw, *pbq;
    cudaGetSymbolAddress((void**)&pv,     g_v);
    cudaGetSymbolAddress((void**)&pmid,   g_mid);
    cudaGetSymbolAddress((void**)&poffaw, g_offaw);
    cudaGetSymbolAddress((void**)&pwvt,   g_wvt);
    cudaGetSymbolAddress((void**)&pwot,   g_wot);
    cudaGetSymbolAddress((void**)&pwqh,   g_wqt_hi);
    cudaGetSymbolAddress((void**)&pwql,   g_wqt_lo);
    cudaGetSymbolAddress((void**)&pbq,    g_bq);

    cudaFuncSetAttribute((const void*)gemm_async_h_kernel<float>,
                         cudaFuncAttributeMaxDynamicSharedMemorySize, HG_SMEM);
    cudaFuncSetAttribute((const void*)gemm_v_f32a_kernel,
                         cudaFuncAttributeMaxDynamicSharedMemorySize, HG_SMEM);
    cudaFuncSetAttribute((const void*)gemm_offaw_fused_kernel,
                         cudaFuncAttributeMaxDynamicSharedMemorySize, FG_SMEM);

    // Fork.
    cudaEventRecord(g_ev0, 0);
    cudaStreamWaitEvent(g_s1, g_ev0, 0);

    // --- s1: off/aw chain (in-kernel query split), then W_out transpose ---
    build_wq_split_kernel<<<(128 * DMODEL + 255) / 256, 256, 0, g_s1>>>(
        W_off, W_aw, b_off, b_aw, pwqh, pwql, pbq);
    {
        dim3 grid(1, MROWS / 128);
        gemm_offaw_fused_kernel<<<grid, 256, FG_SMEM, g_s1>>>(
            query, pwqh, pwql, pbq, poffaw, MROWS, DMODEL);
    }
    cudaEventRecord(g_ev1, g_s1);     // deform dependency
    {
        dim3 tb(32, 8);
        dim3 tg(DMODEL / 32, DMODEL / 32);
        transpose_h_kernel<<<tg, tb, 0, g_s1>>>(W_out, pwot, DMODEL, DMODEL);
    }
    cudaEventRecord(g_ev2, g_s1);     // out-GEMM dependency

    // --- s0 (origin): W_v transpose, then v-GEMM with fused fp32-A convert ---
    {
        dim3 tb(32, 8);
        dim3 tg(DMODEL / 32, DMODEL / 32);
        transpose_h_kernel<<<tg, tb>>>(W_v, pwvt, DMODEL, DMODEL);
    }
    {
        dim3 grid(DMODEL / 128, MROWS / 128);
        gemm_v_f32a_kernel<<<grid, 256, HG_SMEM>>>(
            value, pwvt, b_v, pv, MROWS, DMODEL, DMODEL);
    }

    // Join: deform needs off/aw.
    cudaStreamWaitEvent(0, g_ev1, 0);
    deform_kernel<<<MROWS / 4, 256>>>(pv, poffaw, pmid);

    // --- out = mid @ W_out + b_out (needs tW_out) ---
    cudaStreamWaitEvent(0, g_ev2, 0);
    {
        dim3 grid(DMODEL / 128, MROWS / 128);
        gemm_async_h_kernel<float><<<grid, 256, HG_SMEM>>>(
            pmid, pwot, b_out, out, MROWS, DMODEL, DMODEL);
    }
}

// round 14
// speedup vs baseline: 5.6035x; 1.0783x over previous
#include <cuda_runtime.h>
#include <cuda_fp16.h>
#include <math.h>
#include <stdint.h>

// Problem constants
#define BATCH 8
#define LSEQ  2048
#define DMODEL 512
#define NHEAD 8
#define NPNT  4
#define CHEAD 64
#define MROWS (BATCH * LSEQ)   // 16384
#define MHALF (MROWS / 2)      // 8192

// Scratch (device globals; no allocation allowed)
__device__ __align__(16) __half g_v[MROWS * DMODEL];      // value projection (fp16)
__device__ __align__(16) __half g_mid[MROWS * DMODEL];    // deform output (fp16)
__device__ __align__(16) float  g_offaw[MROWS * 128];     // off(64)|aw(32)|pad, fp32
__device__ __align__(16) __half g_wvt[DMODEL * DMODEL];   // W_v^T   fp16 [N][K]
__device__ __align__(16) __half g_wot[DMODEL * DMODEL];   // W_out^T fp16 [N][K]
__device__ __align__(16) __half g_wqt_hi[128 * DMODEL];   // Wq^T hi fp16 [128][512]
__device__ __align__(16) __half g_wqt_lo[128 * DMODEL];   // Wq^T lo fp16
__device__ __align__(16) float  g_bq[128];

// Streams/events (created once at module load).
static cudaStream_t g_s1;
static cudaEvent_t g_ev0, g_ev1, g_ev2;
namespace {
struct StreamInit {
    StreamInit() {
        cudaStreamCreateWithFlags(&g_s1, cudaStreamNonBlocking);
        cudaEventCreateWithFlags(&g_ev0, cudaEventDisableTiming);
        cudaEventCreateWithFlags(&g_ev1, cudaEventDisableTiming);
        cudaEventCreateWithFlags(&g_ev2, cudaEventDisableTiming);
    }
};
StreamInit g_stream_init;
}

__device__ __forceinline__ uint32_t smem_u32(const void* p) {
    uint32_t a;
    asm("{ .reg .u64 t; cvta.to.shared.u64 t, %1; cvt.u32.u64 %0, t; }" : "=r"(a) : "l"(p));
    return a;
}

__device__ __forceinline__ void mma_f16(float c[4],
                                        const uint32_t a[4],
                                        uint32_t b0, uint32_t b1) {
    asm volatile(
        "mma.sync.aligned.m16n8k16.row.col.f32.f16.f16.f32 "
        "{%0,%1,%2,%3}, {%4,%5,%6,%7}, {%8,%9}, {%0,%1,%2,%3};"
        : "+f"(c[0]), "+f"(c[1]), "+f"(c[2]), "+f"(c[3])
        : "r"(a[0]), "r"(a[1]), "r"(a[2]), "r"(a[3]), "r"(b0), "r"(b1));
}

__device__ __forceinline__ void ldsm_x4(uint32_t r[4], uint32_t addr) {
    asm volatile(
        "ldmatrix.sync.aligned.m8n8.x4.shared.b16 {%0,%1,%2,%3}, [%4];"
        : "=r"(r[0]), "=r"(r[1]), "=r"(r[2]), "=r"(r[3]) : "r"(addr));
}

#define CP_ASYNC16(dst, src) \
    asm volatile("cp.async.cg.shared.global [%0], [%1], 16;" :: "r"(dst), "l"(src) : "memory")
#define CP_COMMIT() asm volatile("cp.async.commit_group;" ::: "memory")
#define CP_WAIT1()  asm volatile("cp.async.wait_group 1;" ::: "memory")
#define CP_WAIT2()  asm volatile("cp.async.wait_group 2;" ::: "memory")

// Common tile geometry
#define HG_KC 32
#define HG_ROWB 80
#define HG_TILE (128 * HG_ROWB)
#define HG_STAGE (2 * HG_TILE)
#define HG_STAGES 4
#define HG_SMEM (HG_STAGES * HG_STAGE)  // 81920 B

// ===========================================================================
// Async fp16 GEMM (fp16 A): C[M,N] = A @ Bt^T + bias. (out-GEMM, fp32 out)
// mbase: row offset of this launch's M-slice.
// ===========================================================================
template <typename OutT>
__global__ __launch_bounds__(256, 2)
void gemm_async_h_kernel(const __half* __restrict__ A, const __half* __restrict__ Bt,
                         const float* __restrict__ bias, OutT* __restrict__ C,
                         int mbase, int N, int K)
{
    extern __shared__ char smem[];
    const uint32_t sbase = smem_u32(smem);

    const int tid  = threadIdx.x;
    const int wid  = tid >> 5;
    const int lane = tid & 31;
    const int g    = lane >> 2;
    const int tig  = lane & 3;
    const int wm   = wid & 3;
    const int wn   = wid >> 2;

    const int m0 = mbase + blockIdx.y * 128;
    const int n0 = blockIdx.x * 128;

    const uint32_t aOff = (uint32_t)((wm * 32 + (lane & 15)) * HG_ROWB + (lane >> 4) * 16);
    const uint32_t bOff = (uint32_t)(HG_TILE +
        (wn * 64 + (lane & 7) + (lane >> 4) * 8) * HG_ROWB + ((lane >> 3) & 1) * 16);

    float acc[2][8][4];
#pragma unroll
    for (int mt = 0; mt < 2; mt++)
#pragma unroll
        for (int nt = 0; nt < 8; nt++)
#pragma unroll
            for (int j = 0; j < 4; j++) acc[mt][nt][j] = 0.0f;

    const int nch = K / HG_KC;

#define HCOPY_STAGE(s, chunk)                                                  \
    do {                                                                       \
        const int _k0 = (chunk) * HG_KC;                                       \
        const uint32_t _dA = sbase + (s) * HG_STAGE;                           \
        const uint32_t _dB = _dA + HG_TILE;                                    \
        _Pragma("unroll")                                                      \
        for (int e = 0; e < 2; e++) {                                          \
            const int cc = tid + e * 256;                                      \
            const int r = cc >> 2;                                             \
            const int q = cc & 3;                                              \
            CP_ASYNC16(_dA + r * HG_ROWB + q * 16,                             \
                       &A[(size_t)(m0 + r) * K + _k0 + q * 8]);                \
            CP_ASYNC16(_dB + r * HG_ROWB + q * 16,                             \
                       &Bt[(size_t)(n0 + r) * K + _k0 + q * 8]);               \
        }                                                                      \
    } while (0)

    HCOPY_STAGE(0, 0); CP_COMMIT();
    HCOPY_STAGE(1, 1); CP_COMMIT();
    HCOPY_STAGE(2, 2); CP_COMMIT();

    for (int c = 0; c < nch; ++c) {
        CP_WAIT2();
        __syncthreads();

        if (c + 3 < nch) {
            HCOPY_STAGE((c + 3) % HG_STAGES, c + 3);
        }
        CP_COMMIT();

        const uint32_t stageBase = sbase + (c % HG_STAGES) * HG_STAGE;
        const uint32_t aBase = stageBase + aOff;
        const uint32_t bBase = stageBase + bOff;

#pragma unroll
        for (int ks = 0; ks < 2; ks++) {
            uint32_t a0[4], a1[4];
            ldsm_x4(a0, aBase + ks * 32);
            ldsm_x4(a1, aBase + 16 * HG_ROWB + ks * 32);
#pragma unroll
            for (int j = 0; j < 4; j++) {
                uint32_t b[4];
                ldsm_x4(b, bBase + j * 16 * HG_ROWB + ks * 32);
                mma_f16(acc[0][2 * j],     a0, b[0], b[1]);
                mma_f16(acc[1][2 * j],     a1, b[0], b[1]);
                mma_f16(acc[0][2 * j + 1], a0, b[2], b[3]);
                mma_f16(acc[1][2 * j + 1], a1, b[2], b[3]);
            }
        }
        __syncthreads();
    }
#undef HCOPY_STAGE

#pragma unroll
    for (int mt = 0; mt < 2; mt++) {
        const int row0 = m0 + wm * 32 + mt * 16 + g;
#pragma unroll
        for (int nt = 0; nt < 8; nt++) {
            const int col = n0 + wn * 64 + nt * 8 + tig * 2;
            const float bx = bias[col];
            const float by = bias[col + 1];
            const float l0 = acc[mt][nt][0] + bx;
            const float l1 = acc[mt][nt][1] + by;
            const float h0 = acc[mt][nt][2] + bx;
            const float h1 = acc[mt][nt][3] + by;
            if constexpr (sizeof(OutT) == 2) {
                __half2* p0 = reinterpret_cast<__half2*>(&C[(size_t)row0 * N + col]);
                __half2* p1 = reinterpret_cast<__half2*>(&C[(size_t)(row0 + 8) * N + col]);
                *p0 = __floats2half2_rn(l0, l1);
                *p1 = __floats2half2_rn(h0, h1);
            } else {
                float2 lo, hi;
                lo.x = l0; lo.y = l1; hi.x = h0; hi.y = h1;
                *reinterpret_cast<float2*>(&C[(size_t)row0 * N + col]) = lo;
                *reinterpret_cast<float2*>(&C[(size_t)(row0 + 8) * N + col]) = hi;
            }
        }
    }
}

// ===========================================================================
// v-GEMM with fused fp32->fp16 A conversion. mbase: M-slice offset.
// ===========================================================================
__global__ __launch_bounds__(256, 2)
void gemm_v_f32a_kernel(const float* __restrict__ A, const __half* __restrict__ Bt,
                        const float* __restrict__ bias, __half* __restrict__ C,
                        int mbase, int N, int K)
{
    extern __shared__ char smem[];
    const uint32_t sbase = smem_u32(smem);

    const int tid  = threadIdx.x;
    const int wid  = tid >> 5;
    const int lane = tid & 31;
    const int g    = lane >> 2;
    const int tig  = lane & 3;
    const int wm   = wid & 3;
    const int wn   = wid >> 2;

    const int m0 = mbase + blockIdx.y * 128;
    const int n0 = blockIdx.x * 128;

    const uint32_t aOff = (uint32_t)((wm * 32 + (lane & 15)) * HG_ROWB + (lane >> 4) * 16);
    const uint32_t bOff = (uint32_t)(HG_TILE +
        (wn * 64 + (lane & 7) + (lane >> 4) * 8) * HG_ROWB + ((lane >> 3) & 1) * 16);

    float4 areg[2][2];

    float acc[2][8][4];
#pragma unroll
    for (int mt = 0; mt < 2; mt++)
#pragma unroll
        for (int nt = 0; nt < 8; nt++)
#pragma unroll
            for (int j = 0; j < 4; j++) acc[mt][nt][j] = 0.0f;

    const int nch = K / HG_KC;

#define VG_LDG_A(k0)                                                           \
    do {                                                                       \
        _Pragma("unroll")                                                      \
        for (int e = 0; e < 2; e++) {                                          \
            const int i = tid + e * 256;                                       \
            const int r = i >> 2;                                              \
            const int q2 = i & 3;                                              \
            const float* pA = &A[(size_t)(m0 + r) * K + (k0) + q2 * 8];        \
            areg[e][0] = *reinterpret_cast<const float4*>(pA);                 \
            areg[e][1] = *reinterpret_cast<const float4*>(pA + 4);             \
        }                                                                      \
    } while (0)

#define VG_STS_A(s)                                                            \
    do {                                                                       \
        _Pragma("unroll")                                                      \
        for (int e = 0; e < 2; e++) {                                          \
            const int i = tid + e * 256;                                       \
            const int r = i >> 2;                                              \
            const int q2 = i & 3;                                              \
            __half2 h0 = __floats2half2_rn(areg[e][0].x, areg[e][0].y);        \
            __half2 h1 = __floats2half2_rn(areg[e][0].z, areg[e][0].w);        \
            __half2 h2 = __floats2half2_rn(areg[e][1].x, areg[e][1].y);        \
            __half2 h3 = __floats2half2_rn(areg[e][1].z, areg[e][1].w);        \
            uint4 o;                                                           \
            o.x = *reinterpret_cast<uint32_t*>(&h0);                           \
            o.y = *reinterpret_cast<uint32_t*>(&h1);                           \
            o.z = *reinterpret_cast<uint32_t*>(&h2);                           \
            o.w = *reinterpret_cast<uint32_t*>(&h3);                           \
            *reinterpret_cast<uint4*>(                                         \
                smem + (s) * HG_STAGE + r * HG_ROWB + q2 * 16) = o;            \
        }                                                                      \
    } while (0)

#define VG_COPY_B(s, chunk)                                                    \
    do {                                                                       \
        const int _k0 = (chunk) * HG_KC;                                       \
        const uint32_t _dB = sbase + (s) * HG_STAGE + HG_TILE;                 \
        _Pragma("unroll")                                                      \
        for (int e = 0; e < 2; e++) {                                          \
            const int cc = tid + e * 256;                                      \
            const int r = cc >> 2;                                             \
            const int q = cc & 3;                                              \
            CP_ASYNC16(_dB + r * HG_ROWB + q * 16,                             \
                       &Bt[(size_t)(n0 + r) * K + _k0 + q * 8]);               \
        }                                                                      \
    } while (0)

    VG_LDG_A(0);          VG_STS_A(0);
    VG_LDG_A(HG_KC);      VG_STS_A(1);
    VG_LDG_A(2 * HG_KC);  VG_STS_A(2);
    VG_COPY_B(0, 0); CP_COMMIT();
    VG_COPY_B(1, 1); CP_COMMIT();
    VG_COPY_B(2, 2); CP_COMMIT();

    for (int c = 0; c < nch; ++c) {
        CP_WAIT2();
        __syncthreads();

        const bool pre = (c + 3) < nch;
        if (pre) {
            VG_LDG_A((c + 3) * HG_KC);
            VG_COPY_B((c + 3) % HG_STAGES, c + 3);
        }
        CP_COMMIT();

        const uint32_t stageBase = sbase + (c % HG_STAGES) * HG_STAGE;
        const uint32_t aBase = stageBase + aOff;
        const uint32_t bBase = stageBase + bOff;

#pragma unroll
        for (int ks = 0; ks < 2; ks++) {
            uint32_t a0[4], a1[4];
            ldsm_x4(a0, aBase + ks * 32);
            ldsm_x4(a1, aBase + 16 * HG_ROWB + ks * 32);
#pragma unroll
            for (int j = 0; j < 4; j++) {
                uint32_t b[4];
                ldsm_x4(b, bBase + j * 16 * HG_ROWB + ks * 32);
                mma_f16(acc[0][2 * j],     a0, b[0], b[1]);
                mma_f16(acc[1][2 * j],     a1, b[0], b[1]);
                mma_f16(acc[0][2 * j + 1], a0, b[2], b[3]);
                mma_f16(acc[1][2 * j + 1], a1, b[2], b[3]);
            }
        }

        if (pre) VG_STS_A((c + 3) % HG_STAGES);
        __syncthreads();
    }
#undef VG_LDG_A
#undef VG_STS_A
#undef VG_COPY_B

#pragma unroll
    for (int mt = 0; mt < 2; mt++) {
        const int row0 = m0 + wm * 32 + mt * 16 + g;
#pragma unroll
        for (int nt = 0; nt < 8; nt++) {
            const int col = n0 + wn * 64 + nt * 8 + tig * 2;
            const float bx = bias[col];
            const float by = bias[col + 1];
            __half2* p0 = reinterpret_cast<__half2*>(&C[(size_t)row0 * N + col]);
            __half2* p1 = reinterpret_cast<__half2*>(&C[(size_t)(row0 + 8) * N + col]);
            *p0 = __floats2half2_rn(acc[mt][nt][0] + bx, acc[mt][nt][1] + by);
            *p1 = __floats2half2_rn(acc[mt][nt][2] + bx, acc[mt][nt][3] + by);
        }
    }
}

// ===========================================================================
// Fused split-fp16 off/aw GEMM (in-kernel query split + ldmatrix) — unchanged.
// ===========================================================================
#define FG_TILE HG_TILE
#define FG_STAGE (4 * FG_TILE)
#define FG_STAGES 3
#define FG_SMEM (FG_STAGES * FG_STAGE)   // 122880 B

__global__ __launch_bounds__(256, 1)
void gemm_offaw_fused_kernel(const float* __restrict__ Q,
                             const __half* __restrict__ Bh, const __half* __restrict__ Bl,
                             const float* __restrict__ bias, float* __restrict__ C,
                             int M, int K)
{
    extern __shared__ char smem[];
    const uint32_t sbase = smem_u32(smem);
    const int N = 128;

    const int tid  = threadIdx.x;
    const int wid  = tid >> 5;
    const int lane = tid & 31;
    const int g    = lane >> 2;
    const int tig  = lane & 3;
    const int wm   = wid & 3;
    const int wn   = wid >> 2;

    const int m0 = blockIdx.y * 128;

    const uint32_t aOff = (uint32_t)((wm * 32 + (lane & 15)) * HG_ROWB + (lane >> 4) * 16);
    const uint32_t bOff = (uint32_t)(
        (wn * 64 + (lane & 7) + (lane >> 4) * 8) * HG_ROWB + ((lane >> 3) & 1) * 16);

    float4 areg[2][2];

    float acc[2][8][4];
#pragma unroll
    for (int mt = 0; mt < 2; mt++)
#pragma unroll
        for (int nt = 0; nt < 8; nt++)
#pragma unroll
            for (int j = 0; j < 4; j++) acc[mt][nt][j] = 0.0f;

    const int nch = K / HG_KC;

#define FO_LDG_A(k0)                                                           \
    do {                                                                       \
        _Pragma("unroll")                                                      \
        for (int e = 0; e < 2; e++) {                                          \
            const int i = tid + e * 256;                                       \
            const int r = i >> 2;                                              \
            const int q2 = i & 3;                                              \
            const float* pQ = &Q[(size_t)(m0 + r) * K + (k0) + q2 * 8];        \
            areg[e][0] = *reinterpret_cast<const float4*>(pQ);                 \
            areg[e][1] = *reinterpret_cast<const float4*>(pQ + 4);             \
        }                                                                      \
    } while (0)

#define FO_STS_A(s)                                                            \
    do {                                                                       \
        _Pragma("unroll")                                                      \
        for (int e = 0; e < 2; e++) {                                          \
            const int i = tid + e * 256;                                       \
            const int r = i >> 2;                                              \
            const int q2 = i & 3;                                              \
            const uint32_t od = (s) * FG_STAGE + r * HG_ROWB + q2 * 16;        \
            float hf[8], lf[8];                                                \
            const float* av = reinterpret_cast<const float*>(areg[e]);         \
            _Pragma("unroll")                                                  \
            for (int x = 0; x < 8; x++) {                                      \
                const __half hh = __float2half_rn(av[x]);                      \
                hf[x] = __half2float(hh);                                      \
                lf[x] = av[x] - hf[x];                                         \
            }                                                                  \
            __half2 H[4], L[4];                                                \
            _Pragma("unroll")                                                  \
            for (int x = 0; x < 4; x++) {                                      \
                H[x] = __floats2half2_rn(hf[2 * x], hf[2 * x + 1]);            \
                L[x] = __floats2half2_rn(lf[2 * x], lf[2 * x + 1]);            \
            }                                                                  \
            uint4 oh, ol;                                                      \
            oh.x = *reinterpret_cast<uint32_t*>(&H[0]);                        \
            oh.y = *reinterpret_cast<uint32_t*>(&H[1]);                        \
            oh.z = *reinterpret_cast<uint32_t*>(&H[2]);                        \
            oh.w = *reinterpret_cast<uint32_t*>(&H[3]);                        \
            ol.x = *reinterpret_cast<uint32_t*>(&L[0]);                        \
            ol.y = *reinterpret_cast<uint32_t*>(&L[1]);                        \
            ol.z = *reinterpret_cast<uint32_t*>(&L[2]);                        \
            ol.w = *reinterpret_cast<uint32_t*>(&L[3]);                        \
            *reinterpret_cast<uint4*>(smem + od) = oh;                         \
            *reinterpret_cast<uint4*>(smem + FG_TILE + od) = ol;               \
        }                                                                      \
    } while (0)

#define FO_COPY_B(s, chunk)                                                    \
    do {                                                                       \
        const int _k0 = (chunk) * HG_KC;                                       \
        const uint32_t _d0 = sbase + (s) * FG_STAGE;                           \
        _Pragma("unroll")                                                      \
        for (int e = 0; e < 2; e++) {                                          \
            const int cc = tid + e * 256;                                      \
            const int r = cc >> 2;                                             \
            const int q = cc & 3;                                              \
            const uint32_t od = r * HG_ROWB + q * 16;                          \
            const size_t ob = (size_t)r * K + _k0 + q * 8;                     \
            CP_ASYNC16(_d0 + 2 * FG_TILE + od, &Bh[ob]);                       \
            CP_ASYNC16(_d0 + 3 * FG_TILE + od, &Bl[ob]);                       \
        }                                                                      \
    } while (0)

    FO_LDG_A(0);      FO_STS_A(0);
    FO_LDG_A(HG_KC);  FO_STS_A(1);
    FO_COPY_B(0, 0); CP_COMMIT();
    FO_COPY_B(1, 1); CP_COMMIT();

    for (int c = 0; c < nch; ++c) {
        CP_WAIT1();
        __syncthreads();

        const bool pre = (c + 2) < nch;
        if (pre) {
            FO_LDG_A((c + 2) * HG_KC);
            FO_COPY_B((c + 2) % FG_STAGES, c + 2);
        }
        CP_COMMIT();

        const uint32_t stageBase = sbase + (c % FG_STAGES) * FG_STAGE;
        const uint32_t ahBase = stageBase + aOff;
        const uint32_t alBase = ahBase + FG_TILE;
        const uint32_t bhBase = stageBase + 2 * FG_TILE + bOff;
        const uint32_t blBase = bhBase + FG_TILE;

#pragma unroll
        for (int ks = 0; ks < 2; ks++) {
            uint32_t ah0[4], ah1[4], al0[4], al1[4];
            ldsm_x4(ah0, ahBase + ks * 32);
            ldsm_x4(ah1, ahBase + 16 * HG_ROWB + ks * 32);
            ldsm_x4(al0, alBase + ks * 32);
            ldsm_x4(al1, alBase + 16 * HG_ROWB + ks * 32);
#pragma unroll
            for (int j = 0; j < 4; j++) {
                uint32_t bh[4], bl[4];
                ldsm_x4(bh, bhBase + j * 16 * HG_ROWB + ks * 32);
                ldsm_x4(bl, blBase + j * 16 * HG_ROWB + ks * 32);
                mma_f16(acc[0][2 * j],     ah0, bh[0], bh[1]);
                mma_f16(acc[0][2 * j],     ah0, bl[0], bl[1]);
                mma_f16(acc[0][2 * j],     al0, bh[0], bh[1]);
                mma_f16(acc[1][2 * j],     ah1, bh[0], bh[1]);
                mma_f16(acc[1][2 * j],     ah1, bl[0], bl[1]);
                mma_f16(acc[1][2 * j],     al1, bh[0], bh[1]);
                mma_f16(acc[0][2 * j + 1], ah0, bh[2], bh[3]);
                mma_f16(acc[0][2 * j + 1], ah0, bl[2], bl[3]);
                mma_f16(acc[0][2 * j + 1], al0, bh[2], bh[3]);
                mma_f16(acc[1][2 * j + 1], ah1, bh[2], bh[3]);
                mma_f16(acc[1][2 * j + 1], ah1, bl[2], bl[3]);
                mma_f16(acc[1][2 * j + 1], al1, bh[2], bh[3]);
            }
        }

        if (pre) FO_STS_A((c + 2) % FG_STAGES);
        __syncthreads();
    }
#undef FO_LDG_A
#undef FO_STS_A
#undef FO_COPY_B

#pragma unroll
    for (int mt = 0; mt < 2; mt++) {
        const int row0 = m0 + wm * 32 + mt * 16 + g;
#pragma unroll
        for (int nt = 0; nt < 8; nt++) {
            const int col = wn * 64 + nt * 8 + tig * 2;
            const float bx = bias[col];
            const float by = bias[col + 1];
            float2 lo, hi;
            lo.x = acc[mt][nt][0] + bx;  lo.y = acc[mt][nt][1] + by;
            hi.x = acc[mt][nt][2] + bx;  hi.y = acc[mt][nt][3] + by;
            *reinterpret_cast<float2*>(&C[(size_t)row0 * N + col]) = lo;
            *reinterpret_cast<float2*>(&C[(size_t)(row0 + 8) * N + col]) = hi;
        }
    }
}

// ===========================================================================
// Unified prep kernel: blockIdx.y selects task.
//   y=0: W_v^T -> fp16    y=1: W_out^T -> fp16    y=2: build split Wq + bias
// block (32,8); grid (256, 3).
// ===========================================================================
__global__ void prep_kernel(const float* __restrict__ W_v,
                            const float* __restrict__ W_out,
                            const float* __restrict__ W_off,
                            const float* __restrict__ W_aw,
                            const float* __restrict__ b_off,
                            const float* __restrict__ b_aw,
                            __half* __restrict__ wvt, __half* __restrict__ wot,
                            __half* __restrict__ wqt_hi, __half* __restrict__ wqt_lo,
                            float* __restrict__ bq)
{
    const int task = blockIdx.y;
    if (task < 2) {
        __shared__ float tile[32][33];
        const float* in = (task == 0) ? W_v : W_out;
        __half* out = (task == 0) ? wvt : wot;
        const int bx = (blockIdx.x & 15) * 32;
        const int by = (blockIdx.x >> 4) * 32;
#pragma unroll
        for (int j = 0; j < 32; j += 8)
            tile[threadIdx.y + j][threadIdx.x] =
                in[(size_t)(by + threadIdx.y + j) * DMODEL + bx + threadIdx.x];
        __syncthreads();
#pragma unroll
        for (int j = 0; j < 32; j += 8)
            out[(size_t)(bx + threadIdx.y + j) * DMODEL + by + threadIdx.x] =
                __float2half_rn(tile[threadIdx.x][threadIdx.y + j]);
    } else {
        const int tid = threadIdx.y * 32 + threadIdx.x;
        const int i = blockIdx.x * 256 + tid;
        if (i < 128 * DMODEL) {
            const int n = i / DMODEL;
            const int k = i - n * DMODEL;
            float w = 0.0f;
            if (n < 64)      w = W_off[k * 64 + n];
            else if (n < 96) w = W_aw[k * 32 + (n - 64)];
            const __half h = __float2half_rn(w);
            const __half l = __float2half_rn(w - __half2float(h));
            wqt_hi[i] = h;
            wqt_lo[i] = l;
        }
        if (i < 128) {
            float bv = 0.0f;
            if (i < 64)      bv = b_off[i];
            else if (i < 96) bv = b_aw[i - 64];
            bq[i] = bv;
        }
    }
}

// ===========================================================================
// Deformable sampling: 4 rows per block, 256 threads; uint4 taps.
// blkbase: row offset (in rows) of this launch's M-slice.
// ===========================================================================
__global__ __launch_bounds__(256) void deform_kernel(
    const __half* __restrict__ v,
    const float* __restrict__ offaw,
    __half* __restrict__ mid,
    int blkbase)
{
    __shared__ float s_w0[4][NHEAD][NPNT];
    __shared__ float s_w1[4][NHEAD][NPNT];
    __shared__ int   s_i0[4][NHEAD][NPNT];
    __shared__ int   s_i1[4][NHEAD][NPNT];

    const int blk0 = blkbase + blockIdx.x * 4;
    const int t = threadIdx.x;

    if (t < 32) {
        const int rr = t >> 3;
        const int h = t & 7;
        const int blk = blk0 + rr;
        const int l = blk & (LSEQ - 1);
        const float ref_y = (float)l / (float)(LSEQ - 1);
        const float* row = &offaw[(size_t)blk * 128];

        float lg[NPNT];
        float mx = -1e30f;
#pragma unroll
        for (int p = 0; p < NPNT; p++) {
            lg[p] = row[64 + h * NPNT + p];
            mx = fmaxf(mx, lg[p]);
        }
        float sum = 0.0f;
#pragma unroll
        for (int p = 0; p < NPNT; p++) { lg[p] = __expf(lg[p] - mx); sum += lg[p]; }
        const float inv = 1.0f / sum;

#pragma unroll
        for (int p = 0; p < NPNT; p++) {
            const float a = lg[p] * inv;
            const float ox = row[(h * NPNT + p) * 2 + 0];
            const float oy = row[(h * NPNT + p) * 2 + 1];
            const float locx = fminf(fmaxf(ox, 0.0f), 1.0f);
            const float locy = fminf(fmaxf(oy + ref_y, 0.0f), 1.0f);

            const float ix = ((locx + 1.0f) * (float)LSEQ - 1.0f) * 0.5f;
            const float iy = locy * 0.5f;
            const float ix0 = floorf(ix);
            const float fx = ix - ix0;
            const float iy0 = floorf(iy);
            const float fy = iy - iy0;
            const float ywt = (1.0f - fy) * (iy0 == 0.0f ? 1.0f : 0.0f)
                            + fy * ((iy0 + 1.0f) == 0.0f ? 1.0f : 0.0f);

            const int i0 = (int)ix0;
            const int i1 = i0 + 1;
            const float w = a * ywt;
            const bool v0 = (i0 >= 0) && (i0 < LSEQ);
            const bool v1 = (i1 >= 0) && (i1 < LSEQ);
            s_w0[rr][h][p] = v0 ? w * (1.0f - fx) : 0.0f;
            s_w1[rr][h][p] = v1 ? w * fx : 0.0f;
            s_i0[rr][h][p] = min(max(i0, 0), LSEQ - 1);
            s_i1[rr][h][p] = min(max(i1, 0), LSEQ - 1);
        }
    }
    __syncthreads();

    const int rr = t >> 6;
    const int u  = t & 63;
    const int h  = u >> 3;
    const int c8 = u & 7;
    const int blk = blk0 + rr;
    const int b = blk >> 11;

    const uint4* vb = reinterpret_cast<const uint4*>(
        v + (size_t)b * LSEQ * DMODEL + h * CHEAD) + c8;

    float a0 = 0.f, a1 = 0.f, a2 = 0.f, a3 = 0.f;
    float a4 = 0.f, a5 = 0.f, a6 = 0.f, a7 = 0.f;
#pragma unroll
    for (int p = 0; p < NPNT; p++) {
        const float w0 = s_w0[rr][h][p];
        const float w1 = s_w1[rr][h][p];
        const uint4 x0 = vb[(size_t)s_i0[rr][h][p] * (DMODEL / 8)];
        const uint4 x1 = vb[(size_t)s_i1[rr][h][p] * (DMODEL / 8)];
        const float2 f0a = __half22float2(*reinterpret_cast<const __half2*>(&x0.x));
        const float2 f0b = __half22float2(*reinterpret_cast<const __half2*>(&x0.y));
        const float2 f0c = __half22float2(*reinterpret_cast<const __half2*>(&x0.z));
        const float2 f0d = __half22float2(*reinterpret_cast<const __half2*>(&x0.w));
        const float2 f1a = __half22float2(*reinterpret_cast<const __half2*>(&x1.x));
        const float2 f1b = __half22float2(*reinterpret_cast<const __half2*>(&x1.y));
        const float2 f1c = __half22float2(*reinterpret_cast<const __half2*>(&x1.z));
        const float2 f1d = __half22float2(*reinterpret_cast<const __half2*>(&x1.w));
        a0 = fmaf(w0, f0a.x, a0); a1 = fmaf(w0, f0a.y, a1);
        a2 = fmaf(w0, f0b.x, a2); a3 = fmaf(w0, f0b.y, a3);
        a4 = fmaf(w0, f0c.x, a4); a5 = fmaf(w0, f0c.y, a5);
        a6 = fmaf(w0, f0d.x, a6); a7 = fmaf(w0, f0d.y, a7);
        a0 = fmaf(w1, f1a.x, a0); a1 = fmaf(w1, f1a.y, a1);
        a2 = fmaf(w1, f1b.x, a2); a3 = fmaf(w1, f1b.y, a3);
        a4 = fmaf(w1, f1c.x, a4); a5 = fmaf(w1, f1c.y, a5);
        a6 = fmaf(w1, f1d.x, a6); a7 = fmaf(w1, f1d.y, a7);
    }
    __half2 o0 = __floats2half2_rn(a0, a1);
    __half2 o1 = __floats2half2_rn(a2, a3);
    __half2 o2 = __floats2half2_rn(a4, a5);
    __half2 o3 = __floats2half2_rn(a6, a7);
    uint4 o;
    o.x = *reinterpret_cast<uint32_t*>(&o0);
    o.y = *reinterpret_cast<uint32_t*>(&o1);
    o.z = *reinterpret_cast<uint32_t*>(&o2);
    o.w = *reinterpret_cast<uint32_t*>(&o3);
    *reinterpret_cast<uint4*>(&mid[(size_t)blk * DMODEL + h * CHEAD + c8 * 8]) = o;
}

// ===========================================================================
// Host launch — M-split pipeline across two streams.
//   s0: prep -> vG(h0) -> [wait offaw] deform(h0) -> out(h0) -> [wait s1 tail]
//   s1: [wait prep] offaw(full) -> vG(h1) -> deform(h1) -> out(h1)
// ===========================================================================
extern "C" void kernel_launch(void* const* d_in, const int* in_sizes, int n_in,
                              void* d_out, int out_size)
{
    const float* query = (const float*)d_in[0];
    const float* value = (const float*)d_in[2];
    const float* W_v   = (const float*)d_in[3];
    const float* b_v   = (const float*)d_in[4];
    const float* W_off = (const float*)d_in[5];
    const float* b_off = (const float*)d_in[6];
    const float* W_aw  = (const float*)d_in[7];
    const float* b_aw  = (const float*)d_in[8];
    const float* W_out = (const float*)d_in[9];
    const float* b_out = (const float*)d_in[10];
    float* out = (float*)d_out;

    __half *pv, *pmid, *pwvt, *pwot, *pwqh, *pwql;
    float *poffaw, *pbq;
    cudaGetSymbolAddress((void**)&pv,     g_v);
    cudaGetSymbolAddress((void**)&pmid,   g_mid);
    cudaGetSymbolAddress((void**)&poffaw, g_offaw);
    cudaGetSymbolAddress((void**)&pwvt,   g_wvt);
    cudaGetSymbolAddress((void**)&pwot,   g_wot);
    cudaGetSymbolAddress((void**)&pwqh,   g_wqt_hi);
    cudaGetSymbolAddress((void**)&pwql,   g_wqt_lo);
    cudaGetSymbolAddress((void**)&pbq,    g_bq);

    cudaFuncSetAttribute((const void*)gemm_async_h_kernel<float>,
                         cudaFuncAttributeMaxDynamicSharedMemorySize, HG_SMEM);
    cudaFuncSetAttribute((const void*)gemm_v_f32a_kernel,
                         cudaFuncAttributeMaxDynamicSharedMemorySize, HG_SMEM);
    cudaFuncSetAttribute((const void*)gemm_offaw_fused_kernel,
                         cudaFuncAttributeMaxDynamicSharedMemorySize, FG_SMEM);

    const dim3 gemmGrid(DMODEL / 128, MHALF / 128);   // (4, 64) per half

    // --- s0: unified prep ---
    {
        dim3 tb(32, 8);
        dim3 tg(256, 3);
        prep_kernel<<<tg, tb>>>(W_v, W_out, W_off, W_aw, b_off, b_aw,
                                pwvt, pwot, pwqh, pwql, pbq);
    }
    cudaEventRecord(g_ev0, 0);
    cudaStreamWaitEvent(g_s1, g_ev0, 0);

    // --- s1: offaw (full M), then half-1 chain ---
    {
        dim3 grid(1, MROWS / 128);
        gemm_offaw_fused_kernel<<<grid, 256, FG_SMEM, g_s1>>>(
            query, pwqh, pwql, pbq, poffaw, MROWS, DMODEL);
    }
    cudaEventRecord(g_ev1, g_s1);   // offaw done (needed by s0's deform h0)
    gemm_v_f32a_kernel<<<gemmGrid, 256, HG_SMEM, g_s1>>>(
        value, pwvt, b_v, pv, MHALF, DMODEL, DMODEL);
    deform_kernel<<<MHALF / 4, 256, 0, g_s1>>>(pv, poffaw, pmid, MHALF);
    gemm_async_h_kernel<float><<<gemmGrid, 256, HG_SMEM, g_s1>>>(
        pmid, pwot, b_out, out, MHALF, DMODEL, DMODEL);
    cudaEventRecord(g_ev2, g_s1);   // s1 tail

    // --- s0: half-0 chain ---
    gemm_v_f32a_kernel<<<gemmGrid, 256, HG_SMEM>>>(
        value, pwvt, b_v, pv, 0, DMODEL, DMODEL);
    cudaStreamWaitEvent(0, g_ev1, 0);
    deform_kernel<<<MHALF / 4, 256>>>(pv, poffaw, pmid, 0);
    gemm_async_h_kernel<float><<<gemmGrid, 256, HG_SMEM>>>(
        pmid, pwot, b_out, out, 0, DMODEL, DMODEL);

    // Join s1 back into the origin stream (required for capture).
    cudaStreamWaitEvent(0, g_ev2, 0);
}